// round 1
// baseline (speedup 1.0000x reference)
#include <cuda_runtime.h>
#include <math.h>

#define F_IN   180
#define T_STEPS 120
#define H      128
#define G4     512      // 4*H
#define MAX_B  2048

// ---------------- scratch (static device globals; no runtime allocation) ----------------
__device__ float g_xt   [(size_t)MAX_B * T_STEPS * F_IN];   // (B*T, 180)
__device__ float g_hpre [(size_t)MAX_B * T_STEPS * H];      // (B*T, 128)
__device__ float g_xproj[(size_t)MAX_B * T_STEPS * G4];     // (B*T, 512)  reused by both layers
__device__ float g_hs   [(size_t)MAX_B * T_STEPS * H];      // layer-0 hidden states

// ---------------- kernel 1: per-sample transpose (B,180,120) -> (B*T,180) ----------------
__global__ void transpose_kernel(const float* __restrict__ x, float* __restrict__ xt)
{
    __shared__ float s[F_IN][41];     // 40-wide t chunk, padded
    int b  = blockIdx.x;
    int t0 = blockIdx.y * 40;
    const float* xb = x + (size_t)b * F_IN * T_STEPS;
    for (int idx = threadIdx.x; idx < F_IN * 40; idx += 256) {
        int f = idx / 40, tt = idx % 40;
        s[f][tt] = xb[f * T_STEPS + t0 + tt];
    }
    __syncthreads();
    float* xtb = xt + (size_t)b * T_STEPS * F_IN;
    for (int idx = threadIdx.x; idx < 40 * F_IN; idx += 256) {
        int tt = idx / F_IN, f = idx % F_IN;
        xtb[(size_t)(t0 + tt) * F_IN + f] = s[f][tt];
    }
}

// ---------------- kernel 2: tiled GEMM  C = epi( A(M,K) @ W(N,K)^T ) ----------------
// mode 0: FC + BatchNorm(eval) + LeakyReLU   (q0=fc_b q1=bn_g q2=bn_b q3=bn_mean q4=bn_var)
// mode 1: + (q0[n] + q1[n])                  (gate biases)
#define BM 128
#define BN 128
#define KC 16
#define LDT 132   // padded tile row stride

__global__ void __launch_bounds__(256, 2)
gemm_kernel(const float* __restrict__ A, const float* __restrict__ W,
            float* __restrict__ C, int M, int N, int K, int mode,
            const float* __restrict__ q0, const float* __restrict__ q1,
            const float* __restrict__ q2, const float* __restrict__ q3,
            const float* __restrict__ q4)
{
    __shared__ float As[KC * LDT];
    __shared__ float Bs[KC * LDT];

    const int tid = threadIdx.x;
    const int tx  = tid & 15;          // n-dir (8 cols each)
    const int ty  = tid >> 4;          // m-dir (8 rows each)
    const int m0  = blockIdx.x * BM;
    const int n0  = blockIdx.y * BN;

    float acc[8][8];
#pragma unroll
    for (int i = 0; i < 8; i++)
#pragma unroll
        for (int j = 0; j < 8; j++) acc[i][j] = 0.f;

    for (int kc = 0; kc < K; kc += KC) {
#pragma unroll
        for (int it = 0; it < 2; ++it) {
            int idx = tid + it * 256;
            int r = idx >> 2, kq = idx & 3;
            int k = kc + kq * 4;
            float4 va, vb;
            if (k + 3 < K) {
                va = *(const float4*)(A + (size_t)(m0 + r) * K + k);
                vb = *(const float4*)(W + (size_t)(n0 + r) * K + k);
            } else {
                float ta[4] = {0,0,0,0}, tb[4] = {0,0,0,0};
#pragma unroll
                for (int j = 0; j < 4; j++) if (k + j < K) {
                    ta[j] = A[(size_t)(m0 + r) * K + k + j];
                    tb[j] = W[(size_t)(n0 + r) * K + k + j];
                }
                va = make_float4(ta[0], ta[1], ta[2], ta[3]);
                vb = make_float4(tb[0], tb[1], tb[2], tb[3]);
            }
            As[(kq*4+0)*LDT + r] = va.x;  As[(kq*4+1)*LDT + r] = va.y;
            As[(kq*4+2)*LDT + r] = va.z;  As[(kq*4+3)*LDT + r] = va.w;
            Bs[(kq*4+0)*LDT + r] = vb.x;  Bs[(kq*4+1)*LDT + r] = vb.y;
            Bs[(kq*4+2)*LDT + r] = vb.z;  Bs[(kq*4+3)*LDT + r] = vb.w;
        }
        __syncthreads();
#pragma unroll
        for (int kk = 0; kk < KC; ++kk) {
            float4 a0 = *(const float4*)(As + kk*LDT + ty*8);
            float4 a1 = *(const float4*)(As + kk*LDT + ty*8 + 4);
            float4 w0 = *(const float4*)(Bs + kk*LDT + tx*8);
            float4 w1 = *(const float4*)(Bs + kk*LDT + tx*8 + 4);
            float a[8] = {a0.x,a0.y,a0.z,a0.w,a1.x,a1.y,a1.z,a1.w};
            float w[8] = {w0.x,w0.y,w0.z,w0.w,w1.x,w1.y,w1.z,w1.w};
#pragma unroll
            for (int i = 0; i < 8; i++)
#pragma unroll
                for (int j = 0; j < 8; j++) acc[i][j] += a[i] * w[j];
        }
        __syncthreads();
    }

    const int nbase = n0 + tx * 8;
    float alpha[8], beta[8];
    if (mode == 0) {
#pragma unroll
        for (int j = 0; j < 8; j++) {
            int n = nbase + j;
            float sc = q1[n] * rsqrtf(q4[n] + 1e-5f);
            alpha[j] = sc;
            beta[j]  = (q0[n] - q3[n]) * sc + q2[n];
        }
    } else {
#pragma unroll
        for (int j = 0; j < 8; j++) {
            int n = nbase + j;
            alpha[j] = 1.f;
            beta[j]  = q0[n] + q1[n];
        }
    }
#pragma unroll
    for (int i = 0; i < 8; i++) {
        int row = m0 + ty * 8 + i;
        float o[8];
#pragma unroll
        for (int j = 0; j < 8; j++) {
            float v = acc[i][j] * alpha[j] + beta[j];
            if (mode == 0) v = (v >= 0.f) ? v : 0.01f * v;
            o[j] = v;
        }
        *(float4*)(C + (size_t)row * N + nbase)     = make_float4(o[0], o[1], o[2], o[3]);
        *(float4*)(C + (size_t)row * N + nbase + 4) = make_float4(o[4], o[5], o[6], o[7]);
    }
}

// ---------------- kernel 3: persistent LSTM layer ----------------
// One block owns LBT=16 batch rows and iterates all T steps; h,c live in smem.
// Whh is streamed L2->smem in 16-wide K chunks, register double-buffered (1 sync/chunk).
#define LBT  16
#define WST  516                 // stage row stride (512 + pad)
#define WBUF (16 * WST)          // one stage buffer: 8256 floats
#define GST  17                  // gbuf / h_s row stride

__device__ __forceinline__ float fast_sigmoid(float v) {
    return __fdividef(1.f, 1.f + __expf(-v));
}
__device__ __forceinline__ float fast_tanh(float v) {
    return __fdividef(2.f, 1.f + __expf(-2.f * v)) - 1.f;
}

__global__ void __launch_bounds__(256)
lstm_kernel(const float* __restrict__ xproj, const float* __restrict__ whh,
            float* __restrict__ hsout, float* __restrict__ hlast)
{
    extern __shared__ float sm[];
    float* h_s  = sm;                       // [128][GST] transposed: h_s[k*GST + r]
    float* c_s  = sm + 128 * GST;           // [16][128]
    float* ubuf = c_s + LBT * H;            // 2*WBUF floats; gbuf[512][GST] aliases it

    const int tid = threadIdx.x;
    const int b0  = blockIdx.x * LBT;
    const int tx  = tid & 127;              // gate group (4 gates each)
    const int ty  = tid >> 7;               // row group (8 rows each)
    const int g0  = tx * 4;
    const int r0  = ty * 8;
    const int gtype = g0 >> 7;              // 0:i 1:f 2:g 3:o

    for (int i = tid; i < 128 * GST; i += 256) h_s[i] = 0.f;
    for (int i = tid; i < LBT * H;   i += 256) c_s[i] = 0.f;

    // prefetch Whh chunk 0 (registers)
    float4 rg4[8];
#pragma unroll
    for (int it = 0; it < 8; ++it) {
        int idx = tid + it * 256;
        int g = idx >> 2, kb = idx & 3;
        rg4[it] = *(const float4*)(whh + g * H + kb * 4);
    }

#pragma unroll 1
    for (int t = 0; t < T_STEPS; ++t) {
        float acc[8][4];
#pragma unroll
        for (int i = 0; i < 8; i++) {
            float4 v = *(const float4*)(xproj + ((size_t)(b0 + r0 + i) * T_STEPS + t) * G4 + g0);
            acc[i][0] = v.x; acc[i][1] = v.y; acc[i][2] = v.z; acc[i][3] = v.w;
        }

#pragma unroll 1
        for (int kci = 0; kci < 8; ++kci) {
            float* buf = ubuf + (kci & 1) * WBUF;
            // stage current chunk
#pragma unroll
            for (int it = 0; it < 8; ++it) {
                int idx = tid + it * 256;
                int g = idx >> 2, kb = idx & 3;
                buf[(kb*4+0)*WST + g] = rg4[it].x;
                buf[(kb*4+1)*WST + g] = rg4[it].y;
                buf[(kb*4+2)*WST + g] = rg4[it].z;
                buf[(kb*4+3)*WST + g] = rg4[it].w;
            }
            // prefetch next chunk (chunk 0 again at wrap — Whh is step-invariant)
            int knext = (kci < 7) ? (kci + 1) * 16 : 0;
#pragma unroll
            for (int it = 0; it < 8; ++it) {
                int idx = tid + it * 256;
                int g = idx >> 2, kb = idx & 3;
                rg4[it] = *(const float4*)(whh + g * H + knext + kb * 4);
            }
            __syncthreads();
            const int kbase = kci * 16;
#pragma unroll
            for (int kk = 0; kk < 16; ++kk) {
                float hv[8];
#pragma unroll
                for (int i = 0; i < 8; i++) hv[i] = h_s[(kbase + kk) * GST + r0 + i];
                float4 w = *(const float4*)(buf + kk * WST + g0);
#pragma unroll
                for (int i = 0; i < 8; i++) {
                    acc[i][0] += hv[i] * w.x;
                    acc[i][1] += hv[i] * w.y;
                    acc[i][2] += hv[i] * w.z;
                    acc[i][3] += hv[i] * w.w;
                }
            }
        }
        __syncthreads();   // all FMA done -> ubuf reusable as gbuf

        // activations -> gbuf[g][r]
#pragma unroll
        for (int i = 0; i < 8; i++) {
#pragma unroll
            for (int j = 0; j < 4; j++) {
                float v = acc[i][j];
                float a = (gtype == 2) ? fast_tanh(v) : fast_sigmoid(v);
                ubuf[(g0 + j) * GST + (r0 + i)] = a;
            }
        }
        __syncthreads();

        // pointwise update; thread handles (h=tx, rows ty*8..ty*8+7)
        const int hh = tx;
#pragma unroll
        for (int i = 0; i < 8; i++) {
            int r = ty * 8 + i;
            float iv = ubuf[(      hh) * GST + r];
            float fv = ubuf[(128 + hh) * GST + r];
            float gv = ubuf[(256 + hh) * GST + r];
            float ov = ubuf[(384 + hh) * GST + r];
            float c  = c_s[r * H + hh];
            float cn = fv * c + iv * gv;
            float hn = ov * fast_tanh(cn);
            c_s[r * H + hh]   = cn;
            h_s[hh * GST + r] = hn;
            if (hsout) hsout[((size_t)(b0 + r) * T_STEPS + t) * H + hh] = hn;
            if (hlast && t == T_STEPS - 1) hlast[(size_t)(b0 + r) * H + hh] = hn;
        }
        __syncthreads();
    }
}

// ---------------- launcher ----------------
extern "C" void kernel_launch(void* const* d_in, const int* in_sizes, int n_in,
                              void* d_out, int out_size)
{
    const float* x       = (const float*)d_in[0];
    const float* fc_w    = (const float*)d_in[1];
    const float* fc_b    = (const float*)d_in[2];
    const float* bn_g    = (const float*)d_in[3];
    const float* bn_b    = (const float*)d_in[4];
    const float* bn_mean = (const float*)d_in[5];
    const float* bn_var  = (const float*)d_in[6];
    const float* wih0    = (const float*)d_in[7];
    const float* whh0    = (const float*)d_in[8];
    const float* bih0    = (const float*)d_in[9];
    const float* bhh0    = (const float*)d_in[10];
    const float* wih1    = (const float*)d_in[11];
    const float* whh1    = (const float*)d_in[12];
    const float* bih1    = (const float*)d_in[13];
    const float* bhh1    = (const float*)d_in[14];
    float* out = (float*)d_out;

    const int B = in_sizes[0] / (F_IN * T_STEPS);
    const int M = B * T_STEPS;

    float *p_xt, *p_hpre, *p_xproj, *p_hs;
    cudaGetSymbolAddress((void**)&p_xt,    g_xt);
    cudaGetSymbolAddress((void**)&p_hpre,  g_hpre);
    cudaGetSymbolAddress((void**)&p_xproj, g_xproj);
    cudaGetSymbolAddress((void**)&p_hs,    g_hs);

    const size_t lstm_smem = (size_t)(128 * GST + LBT * H + 2 * WBUF) * sizeof(float);
    cudaFuncSetAttribute(lstm_kernel, cudaFuncAttributeMaxDynamicSharedMemorySize, (int)lstm_smem);

    // 1) transpose to (B*T, F_IN)
    transpose_kernel<<<dim3(B, 3), 256>>>(x, p_xt);
    // 2) FC + BN + LeakyReLU
    gemm_kernel<<<dim3(M / 128, 1), 256>>>(p_xt, fc_w, p_hpre, M, H, F_IN, 0,
                                           fc_b, bn_g, bn_b, bn_mean, bn_var);
    // 3) layer-0 input projection (+ both biases)
    gemm_kernel<<<dim3(M / 128, 4), 256>>>(p_hpre, wih0, p_xproj, M, G4, H, 1,
                                           bih0, bhh0, nullptr, nullptr, nullptr);
    // 4) layer-0 LSTM (writes all hidden states)
    lstm_kernel<<<B / LBT, 256, lstm_smem>>>(p_xproj, whh0, p_hs, nullptr);
    // 5) layer-1 input projection
    gemm_kernel<<<dim3(M / 128, 4), 256>>>(p_hs, wih1, p_xproj, M, G4, H, 1,
                                           bih1, bhh1, nullptr, nullptr, nullptr);
    // 6) layer-1 LSTM (writes only t = T-1 to output)
    lstm_kernel<<<B / LBT, 256, lstm_smem>>>(p_xproj, whh1, nullptr, out);
}

// round 2
// speedup vs baseline: 2.0896x; 2.0896x over previous
#include <cuda_runtime.h>
#include <math.h>

#define T_STEPS 120
#define F_IN    180
#define H       128
#define G4      512
#define MAX_B   2048

// ---------------- static scratch ----------------
__device__ float g_hpre [(size_t)MAX_B * T_STEPS * H];     // FC output (B*T,128)
__device__ float g_xproj[(size_t)MAX_B * T_STEPS * G4];    // projections (B*T,512) reused
__device__ float g_hs   [(size_t)MAX_B * T_STEPS * H];     // layer-0 hidden states
__device__ float g_wihp0[G4 * H], g_wihp1[G4 * H];         // gate-interleaved wih
__device__ float g_biasp0[G4],    g_biasp1[G4];            // combined permuted biases
__device__ float g_wf0[G4 * H],   g_wf1[G4 * H];           // Whh packed as mma B-fragments

// ---------------- helpers ----------------
__device__ __forceinline__ unsigned cvt_tf32(float f) {
    unsigned u; asm("cvt.rna.tf32.f32 %0, %1;" : "=r"(u) : "f"(f)); return u;
}
__device__ __forceinline__ void mma8(float* c, unsigned a0, unsigned a1, unsigned a2, unsigned a3,
                                     unsigned b0, unsigned b1) {
    asm volatile("mma.sync.aligned.m16n8k8.row.col.f32.tf32.tf32.f32 "
                 "{%0,%1,%2,%3}, {%4,%5,%6,%7}, {%8,%9}, {%0,%1,%2,%3};"
                 : "+f"(c[0]), "+f"(c[1]), "+f"(c[2]), "+f"(c[3])
                 : "r"(a0), "r"(a1), "r"(a2), "r"(a3), "r"(b0), "r"(b1));
}
__device__ __forceinline__ float sigmoidf_(float x) {
    return __fdividef(1.f, 1.f + __expf(-x));
}
__device__ __forceinline__ float tanhf_(float x) {
    return __fdividef(2.f, 1.f + __expf(-2.f * x)) - 1.f;
}

// ---------------- prep: permute wih rows, combine bias, pack Whh B-fragments ----------------
// Gate interleave: orig row n (gate = n>>7, hh = n&127)  ->  row' = hh*4 + gate.
// wf layout: [nt(0..63)][ks(0..15)][lane(0..31)][v(0..1)] where
//   n' = nt*8 + (lane>>2), k = ks*8 + (lane&3) + 4*v   (tf32-rounded)
__global__ void prep_kernel(const float* __restrict__ wih, const float* __restrict__ bih,
                            const float* __restrict__ bhh, const float* __restrict__ whh,
                            float* __restrict__ wihp, float* __restrict__ biasp,
                            float* __restrict__ wf)
{
    int i = blockIdx.x * 256 + threadIdx.x;   // grid covers 65536
    if (i < G4 * H) {
        int n = i >> 7, k = i & 127;
        int np = ((n & 127) << 2) | (n >> 7);
        wihp[np * H + k] = wih[i];
        if (k == 0) biasp[np] = bih[n] + bhh[n];
        // fragment packing
        int v = i & 1, lane = (i >> 1) & 31, ks = (i >> 6) & 15, nt = i >> 10;
        int npf = nt * 8 + (lane >> 2);
        int kk  = ks * 8 + (lane & 3) + 4 * v;
        int orig = ((npf & 3) << 7) | (npf >> 2);
        wf[i] = __uint_as_float(cvt_tf32(whh[orig * H + kk]));
    }
}

// ---------------- tf32 tensor-core GEMM: C = epi( A(M,K) @ W(N,K)^T ) ----------------
// mode 0: A is x (fused transpose), epi = FC bias + BN + LeakyReLU
// mode 1: A row-major, epi = + q0[n]
#define GST 20   // padded smem row stride (conflict-free for frag loads)

__global__ void __launch_bounds__(256)
gemm_tc(const float* __restrict__ A, const float* __restrict__ W, float* __restrict__ C,
        int M, int N, int K, int mode,
        const float* __restrict__ q0, const float* __restrict__ q1,
        const float* __restrict__ q2, const float* __restrict__ q3,
        const float* __restrict__ q4)
{
    __shared__ float As[2][128 * GST];
    __shared__ float Bs[2][128 * GST];
    __shared__ int   rowbase[128];

    const int tid  = threadIdx.x;
    const int lane = tid & 31, warp = tid >> 5;
    const int g = lane >> 2, t = lane & 3;
    const int wm = warp & 3, wn = warp >> 2;          // warp tile 32x64
    const int m0 = blockIdx.x * 128, n0 = blockIdx.y * 128;

    if (mode == 0 && tid < 128) {
        int m = m0 + tid; int b = m / T_STEPS;
        rowbase[tid] = b * (F_IN * T_STEPS) + (m - b * T_STEPS);
    }
    __syncthreads();

    const int r  = tid >> 1;
    const int hf = tid & 1;
    const int nc = (K + 15) >> 4;

    float av[8], wv[8];
    auto LOAD = [&](int kc) {
        if (mode == 0) {
#pragma unroll
            for (int i = 0; i < 8; i++) {
                int k = kc + hf * 8 + i;
                av[i] = (k < K) ? __ldg(A + rowbase[r] + k * T_STEPS) : 0.f;
                wv[i] = (k < K) ? __ldg(W + r * K + k) : 0.f;
            }
        } else {
            const float4* pa = (const float4*)(A + (size_t)(m0 + r) * K + kc + hf * 8);
            const float4* pw = (const float4*)(W + (size_t)(n0 + r) * K + kc + hf * 8);
            float4 a0v = pa[0], a1v = pa[1], w0v = pw[0], w1v = pw[1];
            av[0]=a0v.x; av[1]=a0v.y; av[2]=a0v.z; av[3]=a0v.w;
            av[4]=a1v.x; av[5]=a1v.y; av[6]=a1v.z; av[7]=a1v.w;
            wv[0]=w0v.x; wv[1]=w0v.y; wv[2]=w0v.z; wv[3]=w0v.w;
            wv[4]=w1v.x; wv[5]=w1v.y; wv[6]=w1v.z; wv[7]=w1v.w;
        }
    };
    auto STORE = [&](int s) {
#pragma unroll
        for (int i = 0; i < 8; i++) As[s][r * GST + hf * 8 + i] = __uint_as_float(cvt_tf32(av[i]));
#pragma unroll
        for (int i = 0; i < 8; i++) Bs[s][r * GST + hf * 8 + i] = __uint_as_float(cvt_tf32(wv[i]));
    };

    float acc[2][8][4];
#pragma unroll
    for (int mi = 0; mi < 2; mi++)
#pragma unroll
        for (int j = 0; j < 8; j++)
#pragma unroll
            for (int q = 0; q < 4; q++) acc[mi][j][q] = 0.f;

    LOAD(0); STORE(0); __syncthreads();

    for (int c = 0; c < nc; c++) {
        if (c + 1 < nc) LOAD((c + 1) * 16);
        const float* as = As[c & 1];
        const float* bs = Bs[c & 1];
#pragma unroll
        for (int kh = 0; kh < 2; kh++) {
            unsigned a[2][4];
#pragma unroll
            for (int mi = 0; mi < 2; mi++) {
                int row = wm * 32 + mi * 16;
                a[mi][0] = __float_as_uint(as[(row + g    ) * GST + kh * 8 + t]);
                a[mi][1] = __float_as_uint(as[(row + g + 8) * GST + kh * 8 + t]);
                a[mi][2] = __float_as_uint(as[(row + g    ) * GST + kh * 8 + t + 4]);
                a[mi][3] = __float_as_uint(as[(row + g + 8) * GST + kh * 8 + t + 4]);
            }
            unsigned bfr[8][2];
#pragma unroll
            for (int j = 0; j < 8; j++) {
                int col = wn * 64 + j * 8 + g;
                bfr[j][0] = __float_as_uint(bs[col * GST + kh * 8 + t]);
                bfr[j][1] = __float_as_uint(bs[col * GST + kh * 8 + t + 4]);
            }
#pragma unroll
            for (int mi = 0; mi < 2; mi++)
#pragma unroll
                for (int j = 0; j < 8; j++)
                    mma8(acc[mi][j], a[mi][0], a[mi][1], a[mi][2], a[mi][3],
                         bfr[j][0], bfr[j][1]);
        }
        if (c + 1 < nc) STORE((c + 1) & 1);
        __syncthreads();
    }

    // epilogue
    const int cm = m0 + wm * 32;
    const int cn = n0 + wn * 64;
#pragma unroll
    for (int j = 0; j < 8; j++) {
        int col = cn + j * 8 + 2 * t;
        float al0, be0, al1, be1;
        if (mode == 0) {
            float s0 = q1[col]     * rsqrtf(q4[col]     + 1e-5f);
            float s1 = q1[col + 1] * rsqrtf(q4[col + 1] + 1e-5f);
            al0 = s0; be0 = (q0[col]     - q3[col]    ) * s0 + q2[col];
            al1 = s1; be1 = (q0[col + 1] - q3[col + 1]) * s1 + q2[col + 1];
        } else {
            al0 = al1 = 1.f; be0 = q0[col]; be1 = q0[col + 1];
        }
#pragma unroll
        for (int mi = 0; mi < 2; mi++) {
            int row = cm + mi * 16 + g;
            float v0 = acc[mi][j][0] * al0 + be0;
            float v1 = acc[mi][j][1] * al1 + be1;
            float v2 = acc[mi][j][2] * al0 + be0;
            float v3 = acc[mi][j][3] * al1 + be1;
            if (mode == 0) {
                v0 = (v0 >= 0.f) ? v0 : 0.01f * v0;
                v1 = (v1 >= 0.f) ? v1 : 0.01f * v1;
                v2 = (v2 >= 0.f) ? v2 : 0.01f * v2;
                v3 = (v3 >= 0.f) ? v3 : 0.01f * v3;
            }
            float2 o0 = make_float2(v0, v1), o1 = make_float2(v2, v3);
            *(float2*)(C + (size_t)row * N + col)       = o0;
            *(float2*)(C + (size_t)(row + 8) * N + col) = o1;
        }
    }
}

// ---------------- persistent tf32 tensor-core LSTM ----------------
// Block = 16 batch rows, 8 warps. Warp w owns 64 permuted gate-columns
// (= 16 hidden units x 4 interleaved gates). c stays in registers; gate
// exchange is an intra-pair shfl. Whh streams from L1/L2 as pre-packed frags.
#define SH 132    // h_s row stride (conflict-free for A-frag loads)

__global__ void __launch_bounds__(256)
lstm_tc(const float* __restrict__ xproj, const float* __restrict__ wf,
        float* __restrict__ hsout, float* __restrict__ hlast)
{
    __shared__ unsigned h_s[16 * SH];   // h[batch-row][hidden] as tf32 bits

    const int tid  = threadIdx.x, lane = tid & 31, w = tid >> 5;
    const int g = lane >> 2, t = lane & 3;
    const int odd = t & 1;
    const int b0 = blockIdx.x * 16;
    const uint2* wfw = (const uint2*)(wf + w * 8192);   // this warp's 64x128 frag slice

    for (int i = tid; i < 16 * SH; i += 256) h_s[i] = 0u;
    __syncthreads();

    float c_reg[8];
#pragma unroll
    for (int j = 0; j < 8; j++) c_reg[j] = 0.f;

    const int row_pw = g + odd * 8;
    const int hh0    = w * 16 + (t >> 1);
    const float* xr0 = xproj + (size_t)(b0 + g    ) * T_STEPS * G4;
    const float* xr1 = xproj + (size_t)(b0 + g + 8) * T_STEPS * G4;
    const int colbase = w * 64 + 2 * t;

    for (int ts = 0; ts < T_STEPS; ts++) {
        // init accumulators with the precomputed input projection (fp32 exact add)
        float acc[8][4];
#pragma unroll
        for (int j = 0; j < 8; j++) {
            float2 p0 = *(const float2*)(xr0 + (size_t)ts * G4 + colbase + j * 8);
            float2 p1 = *(const float2*)(xr1 + (size_t)ts * G4 + colbase + j * 8);
            acc[j][0] = p0.x; acc[j][1] = p0.y; acc[j][2] = p1.x; acc[j][3] = p1.y;
        }
        // recurrent matmul: 16 k-steps x 8 n-tiles of m16n8k8
#pragma unroll 4
        for (int ks = 0; ks < 16; ks++) {
            unsigned a0 = h_s[(g    ) * SH + ks * 8 + t];
            unsigned a1 = h_s[(g + 8) * SH + ks * 8 + t];
            unsigned a2 = h_s[(g    ) * SH + ks * 8 + t + 4];
            unsigned a3 = h_s[(g + 8) * SH + ks * 8 + t + 4];
#pragma unroll
            for (int j = 0; j < 8; j++) {
                uint2 b = __ldg(wfw + (j * 16 + ks) * 32 + lane);
                mma8(acc[j], a0, a1, a2, a3, b.x, b.y);
            }
        }
        __syncthreads();   // all h_s reads done

        // activations + pair-exchange + state update
#pragma unroll
        for (int j = 0; j < 8; j++) {
            float a0 = odd ? tanhf_(acc[j][0]) : sigmoidf_(acc[j][0]);
            float a1 = sigmoidf_(acc[j][1]);
            float a2 = odd ? tanhf_(acc[j][2]) : sigmoidf_(acc[j][2]);
            float a3 = sigmoidf_(acc[j][3]);
            float sv0 = odd ? a0 : a2;
            float sv1 = odd ? a1 : a3;
            float rv0 = __shfl_xor_sync(0xffffffffu, sv0, 1);
            float rv1 = __shfl_xor_sync(0xffffffffu, sv1, 1);
            float iG = odd ? rv0 : a0;
            float fG = odd ? rv1 : a1;
            float gG = odd ? a2  : rv0;
            float oG = odd ? a3  : rv1;
            float cn = fG * c_reg[j] + iG * gG;
            float hn = oG * tanhf_(cn);
            c_reg[j] = cn;
            int hh = hh0 + 2 * j;
            h_s[row_pw * SH + hh] = cvt_tf32(hn);
            if (hsout) hsout[((size_t)(b0 + row_pw) * T_STEPS + ts) * H + hh] = hn;
            if (hlast && ts == T_STEPS - 1) hlast[(size_t)(b0 + row_pw) * H + hh] = hn;
        }
        __syncthreads();   // writes visible before next step's reads
    }
}

// ---------------- launcher ----------------
extern "C" void kernel_launch(void* const* d_in, const int* in_sizes, int n_in,
                              void* d_out, int out_size)
{
    const float* x       = (const float*)d_in[0];
    const float* fc_w    = (const float*)d_in[1];
    const float* fc_b    = (const float*)d_in[2];
    const float* bn_g    = (const float*)d_in[3];
    const float* bn_b    = (const float*)d_in[4];
    const float* bn_mean = (const float*)d_in[5];
    const float* bn_var  = (const float*)d_in[6];
    const float* wih0    = (const float*)d_in[7];
    const float* whh0    = (const float*)d_in[8];
    const float* bih0    = (const float*)d_in[9];
    const float* bhh0    = (const float*)d_in[10];
    const float* wih1    = (const float*)d_in[11];
    const float* whh1    = (const float*)d_in[12];
    const float* bih1    = (const float*)d_in[13];
    const float* bhh1    = (const float*)d_in[14];
    float* out = (float*)d_out;

    const int B = in_sizes[0] / (F_IN * T_STEPS);
    const int M = B * T_STEPS;

    float *p_hpre, *p_xproj, *p_hs, *p_wihp0, *p_wihp1, *p_biasp0, *p_biasp1, *p_wf0, *p_wf1;
    cudaGetSymbolAddress((void**)&p_hpre,   g_hpre);
    cudaGetSymbolAddress((void**)&p_xproj,  g_xproj);
    cudaGetSymbolAddress((void**)&p_hs,     g_hs);
    cudaGetSymbolAddress((void**)&p_wihp0,  g_wihp0);
    cudaGetSymbolAddress((void**)&p_wihp1,  g_wihp1);
    cudaGetSymbolAddress((void**)&p_biasp0, g_biasp0);
    cudaGetSymbolAddress((void**)&p_biasp1, g_biasp1);
    cudaGetSymbolAddress((void**)&p_wf0,    g_wf0);
    cudaGetSymbolAddress((void**)&p_wf1,    g_wf1);

    // weight prep (permute + fragment packing), cheap
    prep_kernel<<<256, 256>>>(wih0, bih0, bhh0, whh0, p_wihp0, p_biasp0, p_wf0);
    prep_kernel<<<256, 256>>>(wih1, bih1, bhh1, whh1, p_wihp1, p_biasp1, p_wf1);

    // FC (fused input transpose) + BN + LeakyReLU
    gemm_tc<<<dim3(M / 128, 1), 256>>>(x, fc_w, p_hpre, M, H, F_IN, 0,
                                       fc_b, bn_g, bn_b, bn_mean, bn_var);
    // layer-0 input projection (gate-interleaved columns)
    gemm_tc<<<dim3(M / 128, 4), 256>>>(p_hpre, p_wihp0, p_xproj, M, G4, H, 1,
                                       p_biasp0, nullptr, nullptr, nullptr, nullptr);
    // layer-0 LSTM
    lstm_tc<<<B / 16, 256>>>(p_xproj, p_wf0, p_hs, nullptr);
    // layer-1 input projection
    gemm_tc<<<dim3(M / 128, 4), 256>>>(p_hs, p_wihp1, p_xproj, M, G4, H, 1,
                                       p_biasp1, nullptr, nullptr, nullptr, nullptr);
    // layer-1 LSTM -> final hidden state
    lstm_tc<<<B / 16, 256>>>(p_xproj, p_wf1, nullptr, out);
}

// round 4
// speedup vs baseline: 2.7673x; 1.3243x over previous
#include <cuda_runtime.h>
#include <math.h>

#define T_STEPS 120
#define F_IN    180
#define H       128
#define G4      512
#define MAX_B   2048

// ---------------- static scratch ----------------
__device__ float g_hpre [(size_t)MAX_B * T_STEPS * H];     // FC output (B*T,128)
__device__ float g_xproj[(size_t)MAX_B * T_STEPS * G4];    // projections (B*T,512) reused
__device__ float g_hs   [(size_t)MAX_B * T_STEPS * H];     // layer-0 hidden states
__device__ float g_biasp0[G4],  g_biasp1[G4];              // combined permuted biases
__device__ float g_wf0[G4 * H], g_wf1[G4 * H];             // Whh packed as mma B-fragments
__device__ float g_wif0[G4 * H], g_wif1[G4 * H];           // wih packed as mma B-fragments

// ---------------- helpers ----------------
__device__ __forceinline__ unsigned cvt_tf32(float f) {
    unsigned u; asm("cvt.rna.tf32.f32 %0, %1;" : "=r"(u) : "f"(f)); return u;
}
__device__ __forceinline__ void mma8(float* c, unsigned a0, unsigned a1, unsigned a2, unsigned a3,
                                     unsigned b0, unsigned b1) {
    asm volatile("mma.sync.aligned.m16n8k8.row.col.f32.tf32.tf32.f32 "
                 "{%0,%1,%2,%3}, {%4,%5,%6,%7}, {%8,%9}, {%0,%1,%2,%3};"
                 : "+f"(c[0]), "+f"(c[1]), "+f"(c[2]), "+f"(c[3])
                 : "r"(a0), "r"(a1), "r"(a2), "r"(a3), "r"(b0), "r"(b1));
}
__device__ __forceinline__ float sigmoidf_(float x) {
    return __fdividef(1.f, 1.f + __expf(-x));
}
__device__ __forceinline__ float tanhf_(float x) {
    return __fdividef(2.f, 1.f + __expf(-2.f * x)) - 1.f;
}

// ---------------- prep: combine bias, pack Whh and wih as B-fragments ----------------
// Gate interleave: orig row n (gate = n>>7, hh = n&127) -> row' = hh*4 + gate.
// frag layout: [nt(0..63)][ks(0..15)][lane(0..31)][v(0..1)]:
//   n' = nt*8 + (lane>>2), k = ks*8 + (lane&3) + 4*v   (tf32-rounded)
__global__ void prep_kernel(const float* __restrict__ wih, const float* __restrict__ bih,
                            const float* __restrict__ bhh, const float* __restrict__ whh,
                            float* __restrict__ biasp, float* __restrict__ wf,
                            float* __restrict__ wif)
{
    int i = blockIdx.x * 256 + threadIdx.x;   // grid covers 65536
    if (i < G4 * H) {
        int n = i >> 7, k = i & 127;
        if (k == 0) {
            int np = ((n & 127) << 2) | (n >> 7);
            biasp[np] = bih[n] + bhh[n];
        }
        int v = i & 1, lane = (i >> 1) & 31, ks = (i >> 6) & 15, nt = i >> 10;
        int npf = nt * 8 + (lane >> 2);
        int kk  = ks * 8 + (lane & 3) + 4 * v;
        int orig = ((npf & 3) << 7) | (npf >> 2);
        wf [i] = __uint_as_float(cvt_tf32(whh[orig * H + kk]));
        wif[i] = __uint_as_float(cvt_tf32(wih[orig * H + kk]));
    }
}

// ---------------- tf32 tensor-core GEMM: C = epi( A(M,K) @ W(N,K)^T ) ----------------
// MODE 0: A is x (fused transpose), W row-major via smem; epi = FC bias+BN+LeakyReLU
// MODE 1: A row-major; B streamed as pre-packed fragments (Wf) via L1; epi = + q0[n]
#define GST 20   // padded smem row stride

template<int MODE>
__global__ void __launch_bounds__(256)
gemm_tc(const float* __restrict__ A, const float* __restrict__ W,
        const float* __restrict__ Wf, float* __restrict__ C,
        int M, int N, int K,
        const float* __restrict__ q0, const float* __restrict__ q1,
        const float* __restrict__ q2, const float* __restrict__ q3,
        const float* __restrict__ q4)
{
    __shared__ float As[2][128 * GST];
    __shared__ float Bs[2][(MODE == 0) ? 128 * GST : 1];
    __shared__ int   rowbase[128];

    const int tid  = threadIdx.x;
    const int lane = tid & 31, warp = tid >> 5;
    const int g = lane >> 2, t = lane & 3;
    const int wm = warp & 3, wn = warp >> 2;          // warp tile 32x64
    const int m0 = blockIdx.x * 128, n0 = blockIdx.y * 128;

    if (MODE == 0 && tid < 128) {
        int m = m0 + tid; int b = m / T_STEPS;
        rowbase[tid] = b * (F_IN * T_STEPS) + (m - b * T_STEPS);
    }
    __syncthreads();

    const int r  = tid >> 1;
    const int hf = tid & 1;
    const int nc = (K + 15) >> 4;

    float av[8], wv[8];
    auto LOAD = [&](int kc) {
        if (MODE == 0) {
#pragma unroll
            for (int i = 0; i < 8; i++) {
                int k = kc + hf * 8 + i;
                av[i] = (k < K) ? __ldg(A + rowbase[r] + k * T_STEPS) : 0.f;
                wv[i] = (k < K) ? __ldg(W + r * K + k) : 0.f;
            }
        } else {
            const float4* pa = (const float4*)(A + (size_t)(m0 + r) * K + kc + hf * 8);
            float4 a0v = pa[0], a1v = pa[1];
            av[0]=a0v.x; av[1]=a0v.y; av[2]=a0v.z; av[3]=a0v.w;
            av[4]=a1v.x; av[5]=a1v.y; av[6]=a1v.z; av[7]=a1v.w;
        }
    };
    auto STORE = [&](int s) {
#pragma unroll
        for (int i = 0; i < 8; i++) As[s][r * GST + hf * 8 + i] = __uint_as_float(cvt_tf32(av[i]));
        if (MODE == 0) {
#pragma unroll
            for (int i = 0; i < 8; i++) Bs[s][r * GST + hf * 8 + i] = __uint_as_float(cvt_tf32(wv[i]));
        }
    };

    float acc[2][8][4];
#pragma unroll
    for (int mi = 0; mi < 2; mi++)
#pragma unroll
        for (int j = 0; j < 8; j++)
#pragma unroll
            for (int q = 0; q < 4; q++) acc[mi][j][q] = 0.f;

    const uint2* wfrag = (const uint2*)Wf;
    const int nt_base = (n0 >> 3) + wn * 8;

    LOAD(0); STORE(0); __syncthreads();

    for (int c = 0; c < nc; c++) {
        if (c + 1 < nc) LOAD((c + 1) * 16);
        const float* as = As[c & 1];
        const float* bs = Bs[c & 1];
#pragma unroll
        for (int kh = 0; kh < 2; kh++) {
            unsigned a[2][4];
#pragma unroll
            for (int mi = 0; mi < 2; mi++) {
                int row = wm * 32 + mi * 16;
                a[mi][0] = __float_as_uint(as[(row + g    ) * GST + kh * 8 + t]);
                a[mi][1] = __float_as_uint(as[(row + g + 8) * GST + kh * 8 + t]);
                a[mi][2] = __float_as_uint(as[(row + g    ) * GST + kh * 8 + t + 4]);
                a[mi][3] = __float_as_uint(as[(row + g + 8) * GST + kh * 8 + t + 4]);
            }
            unsigned bfr[8][2];
#pragma unroll
            for (int j = 0; j < 8; j++) {
                if (MODE == 0) {
                    int col = wn * 64 + j * 8 + g;
                    bfr[j][0] = __float_as_uint(bs[col * GST + kh * 8 + t]);
                    bfr[j][1] = __float_as_uint(bs[col * GST + kh * 8 + t + 4]);
                } else {
                    uint2 b = __ldg(wfrag + ((size_t)(nt_base + j) * 16 + c * 2 + kh) * 32 + lane);
                    bfr[j][0] = b.x; bfr[j][1] = b.y;
                }
            }
#pragma unroll
            for (int mi = 0; mi < 2; mi++)
#pragma unroll
                for (int j = 0; j < 8; j++)
                    mma8(acc[mi][j], a[mi][0], a[mi][1], a[mi][2], a[mi][3],
                         bfr[j][0], bfr[j][1]);
        }
        if (c + 1 < nc) STORE((c + 1) & 1);
        __syncthreads();
    }

    const int cm = m0 + wm * 32;
    const int cn = n0 + wn * 64;
#pragma unroll
    for (int j = 0; j < 8; j++) {
        int col = cn + j * 8 + 2 * t;
        float al0, be0, al1, be1;
        if (MODE == 0) {
            float s0 = q1[col]     * rsqrtf(q4[col]     + 1e-5f);
            float s1 = q1[col + 1] * rsqrtf(q4[col + 1] + 1e-5f);
            al0 = s0; be0 = (q0[col]     - q3[col]    ) * s0 + q2[col];
            al1 = s1; be1 = (q0[col + 1] - q3[col + 1]) * s1 + q2[col + 1];
        } else {
            al0 = al1 = 1.f; be0 = q0[col]; be1 = q0[col + 1];
        }
#pragma unroll
        for (int mi = 0; mi < 2; mi++) {
            int row = cm + mi * 16 + g;
            float v0 = acc[mi][j][0] * al0 + be0;
            float v1 = acc[mi][j][1] * al1 + be1;
            float v2 = acc[mi][j][2] * al0 + be0;
            float v3 = acc[mi][j][3] * al1 + be1;
            if (MODE == 0) {
                v0 = (v0 >= 0.f) ? v0 : 0.01f * v0;
                v1 = (v1 >= 0.f) ? v1 : 0.01f * v1;
                v2 = (v2 >= 0.f) ? v2 : 0.01f * v2;
                v3 = (v3 >= 0.f) ? v3 : 0.01f * v3;
            }
            *(float2*)(C + (size_t)row * N + col)       = make_float2(v0, v1);
            *(float2*)(C + (size_t)(row + 8) * N + col) = make_float2(v2, v3);
        }
    }
}

// ---------------- persistent tf32 tensor-core LSTM (block-resident Whh) ----------------
// Block = 16 batch rows, 8 warps. Warp w owns 64 permuted gate-cols (16 hidden x 4 gates).
// Whh B-frags: ks 0..3 in registers (64 regs/thread), ks 4..15 in smem (192KB/CTA).
// xproj for the next step is prefetched into registers during the mma loop.
#define SH 132    // h_s row stride (conflict-free for A-frag loads)

__global__ void __launch_bounds__(256)
lstm_tc(const float* __restrict__ xproj, const float* __restrict__ wf,
        float* __restrict__ hsout, float* __restrict__ hlast)
{
    extern __shared__ unsigned smx[];
    unsigned* h_s = smx;                         // [16][SH] tf32 bits
    uint2*    swf = (uint2*)(smx + 16 * SH);     // 8 warps x (8j x 12ks x 32) uint2

    const int tid  = threadIdx.x, lane = tid & 31, w = tid >> 5;
    const int g = lane >> 2, t = lane & 3;
    const int odd = t & 1;
    const int b0 = blockIdx.x * 16;
    const uint2* wfw = (const uint2*)wf + (size_t)w * 4096;   // warp's 64x128 slice
    uint2* swfw = swf + (size_t)w * 3072;

    // stage ks 4..15 into smem (one-time)
#pragma unroll
    for (int j = 0; j < 8; j++)
#pragma unroll
        for (int ks = 4; ks < 16; ks++)
            swfw[(j * 12 + ks - 4) * 32 + lane] = __ldg(wfw + (j * 16 + ks) * 32 + lane);

    // ks 0..3 resident in registers
    uint2 rb[8][4];
#pragma unroll
    for (int j = 0; j < 8; j++)
#pragma unroll
        for (int ks = 0; ks < 4; ks++)
            rb[j][ks] = __ldg(wfw + (j * 16 + ks) * 32 + lane);

    for (int i = tid; i < 16 * SH; i += 256) h_s[i] = 0u;
    __syncthreads();

    float c_reg[8];
#pragma unroll
    for (int j = 0; j < 8; j++) c_reg[j] = 0.f;

    const int row_pw = g + odd * 8;
    const int hh0    = w * 16 + (t >> 1);
    const float* xr0 = xproj + (size_t)(b0 + g    ) * T_STEPS * G4;
    const float* xr1 = xproj + (size_t)(b0 + g + 8) * T_STEPS * G4;
    const int colbase = w * 64 + 2 * t;

    // prefetch xproj for ts = 0
    float2 p0[8], p1[8];
#pragma unroll
    for (int j = 0; j < 8; j++) {
        p0[j] = *(const float2*)(xr0 + colbase + j * 8);
        p1[j] = *(const float2*)(xr1 + colbase + j * 8);
    }

    for (int ts = 0; ts < T_STEPS; ts++) {
        float acc[8][4];
#pragma unroll
        for (int j = 0; j < 8; j++) {
            acc[j][0] = p0[j].x; acc[j][1] = p0[j].y;
            acc[j][2] = p1[j].x; acc[j][3] = p1[j].y;
        }
        // prefetch next step (dup of last step is harmless)
        {
            int tn = (ts + 1 < T_STEPS) ? ts + 1 : ts;
#pragma unroll
            for (int j = 0; j < 8; j++) {
                p0[j] = __ldg((const float2*)(xr0 + (size_t)tn * G4 + colbase + j * 8));
                p1[j] = __ldg((const float2*)(xr1 + (size_t)tn * G4 + colbase + j * 8));
            }
        }

        // recurrent matmul: register-resident ks 0..3
#pragma unroll
        for (int ks = 0; ks < 4; ks++) {
            unsigned a0 = h_s[(g    ) * SH + ks * 8 + t];
            unsigned a1 = h_s[(g + 8) * SH + ks * 8 + t];
            unsigned a2 = h_s[(g    ) * SH + ks * 8 + t + 4];
            unsigned a3 = h_s[(g + 8) * SH + ks * 8 + t + 4];
#pragma unroll
            for (int j = 0; j < 8; j++)
                mma8(acc[j], a0, a1, a2, a3, rb[j][ks].x, rb[j][ks].y);
        }
        // smem-resident ks 4..15
#pragma unroll 4
        for (int ks = 4; ks < 16; ks++) {
            unsigned a0 = h_s[(g    ) * SH + ks * 8 + t];
            unsigned a1 = h_s[(g + 8) * SH + ks * 8 + t];
            unsigned a2 = h_s[(g    ) * SH + ks * 8 + t + 4];
            unsigned a3 = h_s[(g + 8) * SH + ks * 8 + t + 4];
#pragma unroll
            for (int j = 0; j < 8; j++) {
                uint2 b = swfw[(j * 12 + ks - 4) * 32 + lane];
                mma8(acc[j], a0, a1, a2, a3, b.x, b.y);
            }
        }
        __syncthreads();   // all h_s reads done

        // activations + pair-exchange + state update
#pragma unroll
        for (int j = 0; j < 8; j++) {
            float a0 = odd ? tanhf_(acc[j][0]) : sigmoidf_(acc[j][0]);
            float a1 = sigmoidf_(acc[j][1]);
            float a2 = odd ? tanhf_(acc[j][2]) : sigmoidf_(acc[j][2]);
            float a3 = sigmoidf_(acc[j][3]);
            float sv0 = odd ? a0 : a2;
            float sv1 = odd ? a1 : a3;
            float rv0 = __shfl_xor_sync(0xffffffffu, sv0, 1);
            float rv1 = __shfl_xor_sync(0xffffffffu, sv1, 1);
            float iG = odd ? rv0 : a0;
            float fG = odd ? rv1 : a1;
            float gG = odd ? a2  : rv0;
            float oG = odd ? a3  : rv1;
            float cn = fG * c_reg[j] + iG * gG;
            float hn = oG * tanhf_(cn);
            c_reg[j] = cn;
            int hh = hh0 + 2 * j;
            h_s[row_pw * SH + hh] = cvt_tf32(hn);
            if (hsout) hsout[((size_t)(b0 + row_pw) * T_STEPS + ts) * H + hh] = hn;
            if (hlast && ts == T_STEPS - 1) hlast[(size_t)(b0 + row_pw) * H + hh] = hn;
        }
        __syncthreads();   // writes visible before next step's reads
    }
}

// ---------------- launcher ----------------
extern "C" void kernel_launch(void* const* d_in, const int* in_sizes, int n_in,
                              void* d_out, int out_size)
{
    const float* x       = (const float*)d_in[0];
    const float* fc_w    = (const float*)d_in[1];
    const float* fc_b    = (const float*)d_in[2];
    const float* bn_g    = (const float*)d_in[3];
    const float* bn_b    = (const float*)d_in[4];
    const float* bn_mean = (const float*)d_in[5];
    const float* bn_var  = (const float*)d_in[6];
    const float* wih0    = (const float*)d_in[7];
    const float* whh0    = (const float*)d_in[8];
    const float* bih0    = (const float*)d_in[9];
    const float* bhh0    = (const float*)d_in[10];
    const float* wih1    = (const float*)d_in[11];
    const float* whh1    = (const float*)d_in[12];
    const float* bih1    = (const float*)d_in[13];
    const float* bhh1    = (const float*)d_in[14];
    float* out = (float*)d_out;

    const int B = in_sizes[0] / (F_IN * T_STEPS);
    const int M = B * T_STEPS;

    float *p_hpre, *p_xproj, *p_hs, *p_biasp0, *p_biasp1, *p_wf0, *p_wf1, *p_wif0, *p_wif1;
    cudaGetSymbolAddress((void**)&p_hpre,   g_hpre);
    cudaGetSymbolAddress((void**)&p_xproj,  g_xproj);
    cudaGetSymbolAddress((void**)&p_hs,     g_hs);
    cudaGetSymbolAddress((void**)&p_biasp0, g_biasp0);
    cudaGetSymbolAddress((void**)&p_biasp1, g_biasp1);
    cudaGetSymbolAddress((void**)&p_wf0,    g_wf0);
    cudaGetSymbolAddress((void**)&p_wf1,    g_wf1);
    cudaGetSymbolAddress((void**)&p_wif0,   g_wif0);
    cudaGetSymbolAddress((void**)&p_wif1,   g_wif1);

    const size_t lstm_smem = (size_t)(16 * SH) * 4 + (size_t)8 * 3072 * 8;  // ~205KB
    cudaFuncSetAttribute(lstm_tc, cudaFuncAttributeMaxDynamicSharedMemorySize, (int)lstm_smem);

    prep_kernel<<<256, 256>>>(wih0, bih0, bhh0, whh0, p_biasp0, p_wf0, p_wif0);
    prep_kernel<<<256, 256>>>(wih1, bih1, bhh1, whh1, p_biasp1, p_wf1, p_wif1);

    // FC (fused input transpose) + BN + LeakyReLU
    gemm_tc<0><<<dim3(M / 128, 1), 256>>>(x, fc_w, nullptr, p_hpre, M, H, F_IN,
                                          fc_b, bn_g, bn_b, bn_mean, bn_var);
    // layer-0 input projection (gate-interleaved fragment B)
    gemm_tc<1><<<dim3(M / 128, 4), 256>>>(p_hpre, nullptr, p_wif0, p_xproj, M, G4, H,
                                          p_biasp0, nullptr, nullptr, nullptr, nullptr);
    // layer-0 LSTM
    lstm_tc<<<B / 16, 256, lstm_smem>>>(p_xproj, p_wf0, p_hs, nullptr);
    // layer-1 input projection
    gemm_tc<1><<<dim3(M / 128, 4), 256>>>(p_hs, nullptr, p_wif1, p_xproj, M, G4, H,
                                          p_biasp1, nullptr, nullptr, nullptr, nullptr);
    // layer-1 LSTM -> final hidden state
    lstm_tc<<<B / 16, 256, lstm_smem>>>(p_xproj, p_wf1, nullptr, out);
}

// round 5
// speedup vs baseline: 2.9402x; 1.0625x over previous
#include <cuda_runtime.h>
#include <math.h>

#define T_STEPS 120
#define F_IN    180
#define H       128
#define G4      512
#define MAX_B   2048

// ---------------- static scratch ----------------
__device__ float g_hpre [(size_t)MAX_B * T_STEPS * H];
__device__ float g_xproj[(size_t)MAX_B * T_STEPS * G4];
__device__ float g_hs   [(size_t)MAX_B * T_STEPS * H];
__device__ float g_biasp0[G4],  g_biasp1[G4];
__device__ float g_wf0[G4 * H], g_wf1[G4 * H];
__device__ float g_wif0[G4 * H], g_wif1[G4 * H];

// ---------------- helpers ----------------
__device__ __forceinline__ unsigned cvt_tf32(float f) {
    unsigned u; asm("cvt.rna.tf32.f32 %0, %1;" : "=r"(u) : "f"(f)); return u;
}
__device__ __forceinline__ void mma8(float* c, unsigned a0, unsigned a1, unsigned a2, unsigned a3,
                                     unsigned b0, unsigned b1) {
    asm volatile("mma.sync.aligned.m16n8k8.row.col.f32.tf32.tf32.f32 "
                 "{%0,%1,%2,%3}, {%4,%5,%6,%7}, {%8,%9}, {%0,%1,%2,%3};"
                 : "+f"(c[0]), "+f"(c[1]), "+f"(c[2]), "+f"(c[3])
                 : "r"(a0), "r"(a1), "r"(a2), "r"(a3), "r"(b0), "r"(b1));
}
__device__ __forceinline__ float sigmoidf_(float x) {
    return __fdividef(1.f, 1.f + __expf(-x));
}
__device__ __forceinline__ float tanhf_(float x) {
    return __fdividef(2.f, 1.f + __expf(-2.f * x)) - 1.f;
}
__device__ __forceinline__ void cp16(unsigned dst, const void* src) {
    asm volatile("cp.async.ca.shared.global [%0], [%1], 16;" :: "r"(dst), "l"(src));
}
__device__ __forceinline__ void cp_commit() { asm volatile("cp.async.commit_group;"); }
template<int N> __device__ __forceinline__ void cp_wait() {
    asm volatile("cp.async.wait_group %0;" :: "n"(N));
}

// ---------------- prep: combine bias, pack Whh and wih as B-fragments ----------------
// Gate interleave: orig row n (gate=n>>7, hh=n&127) -> row' = hh*4 + gate.
// frag layout: [nt(0..63)][ks(0..15)][lane(0..31)][v(0..1)]:
//   n' = nt*8 + (lane>>2), k = ks*8 + (lane&3) + 4*v   (tf32-rounded)
__global__ void prep_kernel(const float* __restrict__ wih, const float* __restrict__ bih,
                            const float* __restrict__ bhh, const float* __restrict__ whh,
                            float* __restrict__ biasp, float* __restrict__ wf,
                            float* __restrict__ wif)
{
    int i = blockIdx.x * 256 + threadIdx.x;
    if (i < G4 * H) {
        int n = i >> 7, k = i & 127;
        if (k == 0) {
            int np = ((n & 127) << 2) | (n >> 7);
            biasp[np] = bih[n] + bhh[n];
        }
        int v = i & 1, lane = (i >> 1) & 31, ks = (i >> 6) & 15, nt = i >> 10;
        int npf = nt * 8 + (lane >> 2);
        int kk  = ks * 8 + (lane & 3) + 4 * v;
        int orig = ((npf & 3) << 7) | (npf >> 2);
        wf [i] = __uint_as_float(cvt_tf32(whh[orig * H + kk]));
        wif[i] = __uint_as_float(cvt_tf32(wih[orig * H + kk]));
    }
}

// ---------------- tf32 tensor-core GEMM: C = epi( A(M,K) @ W(N,K)^T ) ----------------
// MODE 0: A is x (fused transpose), W row-major via smem; epi = FC bias+BN+LeakyReLU
// MODE 1: A row-major via cp.async (raw fp32, cvt at frag load); B via pre-packed frags
#define GST 20

template<int MODE>
__global__ void __launch_bounds__(256)
gemm_tc(const float* __restrict__ A, const float* __restrict__ W,
        const float* __restrict__ Wf, float* __restrict__ C,
        int M, int N, int K,
        const float* __restrict__ q0, const float* __restrict__ q1,
        const float* __restrict__ q2, const float* __restrict__ q3,
        const float* __restrict__ q4)
{
    __shared__ float As[2][128 * GST];
    __shared__ float Bs[2][(MODE == 0) ? 128 * GST : 1];
    __shared__ int   rowbase[128];

    const int tid  = threadIdx.x;
    const int lane = tid & 31, warp = tid >> 5;
    const int g = lane >> 2, t = lane & 3;
    const int wm = warp & 3, wn = warp >> 2;
    const int m0 = blockIdx.x * 128, n0 = blockIdx.y * 128;

    if (MODE == 0 && tid < 128) {
        int m = m0 + tid; int b = m / T_STEPS;
        rowbase[tid] = b * (F_IN * T_STEPS) + (m - b * T_STEPS);
    }
    __syncthreads();

    const int r  = tid >> 1;
    const int hf = tid & 1;
    const int nc = (K + 15) >> 4;

    float acc[2][8][4];
#pragma unroll
    for (int mi = 0; mi < 2; mi++)
#pragma unroll
        for (int j = 0; j < 8; j++)
#pragma unroll
            for (int q = 0; q < 4; q++) acc[mi][j][q] = 0.f;

    const uint2* wfrag = (const uint2*)Wf;
    const int nt_base = (n0 >> 3) + wn * 8;

    if (MODE == 0) {
        float av[8], wv[8];
        auto LOAD = [&](int kc) {
#pragma unroll
            for (int i = 0; i < 8; i++) {
                int k = kc + hf * 8 + i;
                av[i] = (k < K) ? __ldg(A + rowbase[r] + k * T_STEPS) : 0.f;
                wv[i] = (k < K) ? __ldg(W + r * K + k) : 0.f;
            }
        };
        auto STORE = [&](int s) {
#pragma unroll
            for (int i = 0; i < 8; i++) As[s][r * GST + hf * 8 + i] = __uint_as_float(cvt_tf32(av[i]));
#pragma unroll
            for (int i = 0; i < 8; i++) Bs[s][r * GST + hf * 8 + i] = __uint_as_float(cvt_tf32(wv[i]));
        };
        LOAD(0); STORE(0); __syncthreads();
        for (int c = 0; c < nc; c++) {
            if (c + 1 < nc) LOAD((c + 1) * 16);
            const float* as = As[c & 1];
            const float* bs = Bs[c & 1];
#pragma unroll
            for (int kh = 0; kh < 2; kh++) {
                unsigned a[2][4];
#pragma unroll
                for (int mi = 0; mi < 2; mi++) {
                    int row = wm * 32 + mi * 16;
                    a[mi][0] = __float_as_uint(as[(row + g    ) * GST + kh * 8 + t]);
                    a[mi][1] = __float_as_uint(as[(row + g + 8) * GST + kh * 8 + t]);
                    a[mi][2] = __float_as_uint(as[(row + g    ) * GST + kh * 8 + t + 4]);
                    a[mi][3] = __float_as_uint(as[(row + g + 8) * GST + kh * 8 + t + 4]);
                }
#pragma unroll
                for (int j = 0; j < 8; j++) {
                    int col = wn * 64 + j * 8 + g;
                    unsigned b0 = __float_as_uint(bs[col * GST + kh * 8 + t]);
                    unsigned b1 = __float_as_uint(bs[col * GST + kh * 8 + t + 4]);
#pragma unroll
                    for (int mi = 0; mi < 2; mi++)
                        mma8(acc[mi][j], a[mi][0], a[mi][1], a[mi][2], a[mi][3], b0, b1);
                }
            }
            if (c + 1 < nc) STORE((c + 1) & 1);
            __syncthreads();
        }
    } else {
        unsigned asb = (unsigned)__cvta_generic_to_shared(&As[0][0]);
        auto ISSUE = [&](int c) {
            int s = c & 1;
            const float* src = A + (size_t)(m0 + r) * K + c * 16 + hf * 8;
            unsigned dst = asb + (unsigned)(s * 128 * GST + r * GST + hf * 8) * 4u;
            cp16(dst, src);
            cp16(dst + 16u, src + 4);
            cp_commit();
        };
        ISSUE(0);
        for (int c = 0; c < nc; c++) {
            if (c + 1 < nc) { ISSUE(c + 1); cp_wait<1>(); }
            else            { cp_wait<0>(); }
            __syncthreads();
            const float* as = As[c & 1];
#pragma unroll
            for (int kh = 0; kh < 2; kh++) {
                unsigned a[2][4];
#pragma unroll
                for (int mi = 0; mi < 2; mi++) {
                    int row = wm * 32 + mi * 16;
                    a[mi][0] = cvt_tf32(as[(row + g    ) * GST + kh * 8 + t]);
                    a[mi][1] = cvt_tf32(as[(row + g + 8) * GST + kh * 8 + t]);
                    a[mi][2] = cvt_tf32(as[(row + g    ) * GST + kh * 8 + t + 4]);
                    a[mi][3] = cvt_tf32(as[(row + g + 8) * GST + kh * 8 + t + 4]);
                }
#pragma unroll
                for (int j = 0; j < 8; j++) {
                    uint2 b = __ldg(wfrag + ((size_t)(nt_base + j) * 16 + c * 2 + kh) * 32 + lane);
#pragma unroll
                    for (int mi = 0; mi < 2; mi++)
                        mma8(acc[mi][j], a[mi][0], a[mi][1], a[mi][2], a[mi][3], b.x, b.y);
                }
            }
            __syncthreads();
        }
    }

    const int cm = m0 + wm * 32;
    const int cn = n0 + wn * 64;
#pragma unroll
    for (int j = 0; j < 8; j++) {
        int col = cn + j * 8 + 2 * t;
        float al0, be0, al1, be1;
        if (MODE == 0) {
            float s0 = q1[col]     * rsqrtf(q4[col]     + 1e-5f);
            float s1 = q1[col + 1] * rsqrtf(q4[col + 1] + 1e-5f);
            al0 = s0; be0 = (q0[col]     - q3[col]    ) * s0 + q2[col];
            al1 = s1; be1 = (q0[col + 1] - q3[col + 1]) * s1 + q2[col + 1];
        } else {
            al0 = al1 = 1.f; be0 = q0[col]; be1 = q0[col + 1];
        }
#pragma unroll
        for (int mi = 0; mi < 2; mi++) {
            int row = cm + mi * 16 + g;
            float v0 = acc[mi][j][0] * al0 + be0;
            float v1 = acc[mi][j][1] * al1 + be1;
            float v2 = acc[mi][j][2] * al0 + be0;
            float v3 = acc[mi][j][3] * al1 + be1;
            if (MODE == 0) {
                v0 = (v0 >= 0.f) ? v0 : 0.01f * v0;
                v1 = (v1 >= 0.f) ? v1 : 0.01f * v1;
                v2 = (v2 >= 0.f) ? v2 : 0.01f * v2;
                v3 = (v3 >= 0.f) ? v3 : 0.01f * v3;
            }
            *(float2*)(C + (size_t)row * N + col)       = make_float2(v0, v1);
            *(float2*)(C + (size_t)(row + 8) * N + col) = make_float2(v2, v3);
        }
    }
}

// ---------------- persistent tf32 tensor-core LSTM ----------------
// 512 threads = 16 warps; warp owns 32 permuted gate-cols (8 hidden x 4 gates, j=0..3).
// Whh B-frags: ks0..5 in regs (48 regs), ks6..15 in smem (160KB). h double-buffered
// in smem -> ONE barrier per timestep. c stays in registers.
#define SH     132
#define HS_BUF (16 * SH)

__global__ void __launch_bounds__(512)
lstm_tc(const float* __restrict__ xproj, const float* __restrict__ wf,
        float* __restrict__ hsout, float* __restrict__ hlast)
{
    extern __shared__ unsigned smx[];
    unsigned* h_buf = smx;                           // [2][16*SH]
    uint2*    swf   = (uint2*)(smx + 2 * HS_BUF);    // 16 warps x (4j x 10ks x 32)

    const int tid  = threadIdx.x, lane = tid & 31, w = tid >> 5;   // w 0..15
    const int g = lane >> 2, t = lane & 3;
    const int odd = t & 1;
    const int b0 = blockIdx.x * 16;
    const uint2* wfw = (const uint2*)wf + (size_t)w * 2048;   // warp's 4nt x 16ks x 32
    uint2* swfw = swf + (size_t)w * 1280;

    // stage ks 6..15 into smem (one-time)
#pragma unroll
    for (int j = 0; j < 4; j++)
#pragma unroll
        for (int ks = 6; ks < 16; ks++)
            swfw[(j * 10 + ks - 6) * 32 + lane] = __ldg(wfw + (j * 16 + ks) * 32 + lane);

    // ks 0..5 resident in registers
    uint2 rb[4][6];
#pragma unroll
    for (int j = 0; j < 4; j++)
#pragma unroll
        for (int ks = 0; ks < 6; ks++)
            rb[j][ks] = __ldg(wfw + (j * 16 + ks) * 32 + lane);

    for (int i = tid; i < 2 * HS_BUF; i += 512) h_buf[i] = 0u;
    __syncthreads();

    float c_reg[4] = {0.f, 0.f, 0.f, 0.f};
    const int row_pw = g + odd * 8;
    const int hh0    = w * 8 + (t >> 1);
    const float* xr0 = xproj + (size_t)(b0 + g    ) * T_STEPS * G4;
    const float* xr1 = xproj + (size_t)(b0 + g + 8) * T_STEPS * G4;
    const int colbase = w * 32 + 2 * t;

    // prefetch xproj for ts = 0
    float2 p0[4], p1[4];
#pragma unroll
    for (int j = 0; j < 4; j++) {
        p0[j] = *(const float2*)(xr0 + colbase + j * 8);
        p1[j] = *(const float2*)(xr1 + colbase + j * 8);
    }

    int cur = 0;
    for (int ts = 0; ts < T_STEPS; ts++) {
        const unsigned* hc  = h_buf + cur * HS_BUF;        // read buffer
        unsigned*       hnb = h_buf + (cur ^ 1) * HS_BUF;  // write buffer
        float acc[4][4];
#pragma unroll
        for (int j = 0; j < 4; j++) {
            acc[j][0] = p0[j].x; acc[j][1] = p0[j].y;
            acc[j][2] = p1[j].x; acc[j][3] = p1[j].y;
        }
        // prefetch next step
        {
            int tn = (ts + 1 < T_STEPS) ? ts + 1 : ts;
#pragma unroll
            for (int j = 0; j < 4; j++) {
                p0[j] = __ldg((const float2*)(xr0 + (size_t)tn * G4 + colbase + j * 8));
                p1[j] = __ldg((const float2*)(xr1 + (size_t)tn * G4 + colbase + j * 8));
            }
        }

        // register-resident ks 0..5
#pragma unroll
        for (int ks = 0; ks < 6; ks++) {
            unsigned a0 = hc[(g    ) * SH + ks * 8 + t];
            unsigned a1 = hc[(g + 8) * SH + ks * 8 + t];
            unsigned a2 = hc[(g    ) * SH + ks * 8 + t + 4];
            unsigned a3 = hc[(g + 8) * SH + ks * 8 + t + 4];
#pragma unroll
            for (int j = 0; j < 4; j++)
                mma8(acc[j], a0, a1, a2, a3, rb[j][ks].x, rb[j][ks].y);
        }
        // smem-resident ks 6..15
#pragma unroll 5
        for (int ks = 6; ks < 16; ks++) {
            unsigned a0 = hc[(g    ) * SH + ks * 8 + t];
            unsigned a1 = hc[(g + 8) * SH + ks * 8 + t];
            unsigned a2 = hc[(g    ) * SH + ks * 8 + t + 4];
            unsigned a3 = hc[(g + 8) * SH + ks * 8 + t + 4];
#pragma unroll
            for (int j = 0; j < 4; j++) {
                uint2 b = swfw[(j * 10 + ks - 6) * 32 + lane];
                mma8(acc[j], a0, a1, a2, a3, b.x, b.y);
            }
        }

        // activations + pair-exchange + state update; write to OTHER buffer (no pre-barrier)
#pragma unroll
        for (int j = 0; j < 4; j++) {
            float a0 = odd ? tanhf_(acc[j][0]) : sigmoidf_(acc[j][0]);
            float a1 = sigmoidf_(acc[j][1]);
            float a2 = odd ? tanhf_(acc[j][2]) : sigmoidf_(acc[j][2]);
            float a3 = sigmoidf_(acc[j][3]);
            float sv0 = odd ? a0 : a2;
            float sv1 = odd ? a1 : a3;
            float rv0 = __shfl_xor_sync(0xffffffffu, sv0, 1);
            float rv1 = __shfl_xor_sync(0xffffffffu, sv1, 1);
            float iG = odd ? rv0 : a0;
            float fG = odd ? rv1 : a1;
            float gG = odd ? a2  : rv0;
            float oG = odd ? a3  : rv1;
            float cn = fG * c_reg[j] + iG * gG;
            float hn = oG * tanhf_(cn);
            c_reg[j] = cn;
            int hh = hh0 + 2 * j;
            hnb[row_pw * SH + hh] = cvt_tf32(hn);
            if (hsout) hsout[((size_t)(b0 + row_pw) * T_STEPS + ts) * H + hh] = hn;
            if (hlast && ts == T_STEPS - 1) hlast[(size_t)(b0 + row_pw) * H + hh] = hn;
        }
        __syncthreads();   // single barrier per step
        cur ^= 1;
    }
}

// ---------------- launcher ----------------
extern "C" void kernel_launch(void* const* d_in, const int* in_sizes, int n_in,
                              void* d_out, int out_size)
{
    const float* x       = (const float*)d_in[0];
    const float* fc_w    = (const float*)d_in[1];
    const float* fc_b    = (const float*)d_in[2];
    const float* bn_g    = (const float*)d_in[3];
    const float* bn_b    = (const float*)d_in[4];
    const float* bn_mean = (const float*)d_in[5];
    const float* bn_var  = (const float*)d_in[6];
    const float* wih0    = (const float*)d_in[7];
    const float* whh0    = (const float*)d_in[8];
    const float* bih0    = (const float*)d_in[9];
    const float* bhh0    = (const float*)d_in[10];
    const float* wih1    = (const float*)d_in[11];
    const float* whh1    = (const float*)d_in[12];
    const float* bih1    = (const float*)d_in[13];
    const float* bhh1    = (const float*)d_in[14];
    float* out = (float*)d_out;

    const int B = in_sizes[0] / (F_IN * T_STEPS);
    const int M = B * T_STEPS;

    float *p_hpre, *p_xproj, *p_hs, *p_biasp0, *p_biasp1, *p_wf0, *p_wf1, *p_wif0, *p_wif1;
    cudaGetSymbolAddress((void**)&p_hpre,   g_hpre);
    cudaGetSymbolAddress((void**)&p_xproj,  g_xproj);
    cudaGetSymbolAddress((void**)&p_hs,     g_hs);
    cudaGetSymbolAddress((void**)&p_biasp0, g_biasp0);
    cudaGetSymbolAddress((void**)&p_biasp1, g_biasp1);
    cudaGetSymbolAddress((void**)&p_wf0,    g_wf0);
    cudaGetSymbolAddress((void**)&p_wf1,    g_wf1);
    cudaGetSymbolAddress((void**)&p_wif0,   g_wif0);
    cudaGetSymbolAddress((void**)&p_wif1,   g_wif1);

    const size_t lstm_smem = (size_t)2 * HS_BUF * 4 + (size_t)16 * 1280 * 8;  // ~177KB
    cudaFuncSetAttribute(lstm_tc, cudaFuncAttributeMaxDynamicSharedMemorySize, (int)lstm_smem);

    prep_kernel<<<256, 256>>>(wih0, bih0, bhh0, whh0, p_biasp0, p_wf0, p_wif0);
    prep_kernel<<<256, 256>>>(wih1, bih1, bhh1, whh1, p_biasp1, p_wf1, p_wif1);

    // FC (fused input transpose) + BN + LeakyReLU
    gemm_tc<0><<<dim3(M / 128, 1), 256>>>(x, fc_w, nullptr, p_hpre, M, H, F_IN,
                                          fc_b, bn_g, bn_b, bn_mean, bn_var);
    // layer-0 input projection
    gemm_tc<1><<<dim3(M / 128, 4), 256>>>(p_hpre, nullptr, p_wif0, p_xproj, M, G4, H,
                                          p_biasp0, nullptr, nullptr, nullptr, nullptr);
    // layer-0 LSTM
    lstm_tc<<<B / 16, 512, lstm_smem>>>(p_xproj, p_wf0, p_hs, nullptr);
    // layer-1 input projection
    gemm_tc<1><<<dim3(M / 128, 4), 256>>>(p_hs, nullptr, p_wif1, p_xproj, M, G4, H,
                                          p_biasp1, nullptr, nullptr, nullptr, nullptr);
    // layer-1 LSTM -> final hidden state
    lstm_tc<<<B / 16, 512, lstm_smem>>>(p_xproj, p_wf1, nullptr, out);
}

// round 6
// speedup vs baseline: 3.2539x; 1.1067x over previous
#include <cuda_runtime.h>
#include <math.h>

#define T_STEPS 120
#define F_IN    180
#define H       128
#define G4      512
#define MAX_B   2048

// ---------------- static scratch ----------------
__device__ float g_hpre [(size_t)MAX_B * T_STEPS * H];
__device__ float g_xproj[(size_t)MAX_B * T_STEPS * G4];
__device__ float g_hs   [(size_t)MAX_B * T_STEPS * H];
__device__ float g_biasp0[G4],  g_biasp1[G4];
__device__ float g_wf0[G4 * H], g_wf1[G4 * H];
__device__ float g_wif0[G4 * H], g_wif1[G4 * H];

// ---------------- helpers ----------------
__device__ __forceinline__ unsigned cvt_tf32(float f) {
    unsigned u; asm("cvt.rna.tf32.f32 %0, %1;" : "=r"(u) : "f"(f)); return u;
}
__device__ __forceinline__ void mma8(float* c, unsigned a0, unsigned a1, unsigned a2, unsigned a3,
                                     unsigned b0, unsigned b1) {
    asm volatile("mma.sync.aligned.m16n8k8.row.col.f32.tf32.tf32.f32 "
                 "{%0,%1,%2,%3}, {%4,%5,%6,%7}, {%8,%9}, {%0,%1,%2,%3};"
                 : "+f"(c[0]), "+f"(c[1]), "+f"(c[2]), "+f"(c[3])
                 : "r"(a0), "r"(a1), "r"(a2), "r"(a3), "r"(b0), "r"(b1));
}
__device__ __forceinline__ void ldsm4(unsigned& a0, unsigned& a1, unsigned& a2, unsigned& a3,
                                      unsigned addr) {
    asm volatile("ldmatrix.sync.aligned.m8n8.x4.shared.b16 {%0,%1,%2,%3}, [%4];"
                 : "=r"(a0), "=r"(a1), "=r"(a2), "=r"(a3) : "r"(addr));
}
__device__ __forceinline__ float sigmoidf_(float x) {
    return __fdividef(1.f, 1.f + __expf(-x));
}
__device__ __forceinline__ float tanhf_(float x) {
    return __fdividef(2.f, 1.f + __expf(-2.f * x)) - 1.f;
}

// ---------------- prep: combine bias, pack Whh and wih as B-fragments ----------------
// Gate interleave: orig row n (gate=n>>7, hh=n&127) -> row' = hh*4 + gate.
// frag layout: [nt(0..63)][ks(0..15)][lane(0..31)][v(0..1)]:
//   n' = nt*8 + (lane>>2), k = ks*8 + (lane&3) + 4*v   (tf32-rounded)
__global__ void prep_kernel(const float* __restrict__ wih, const float* __restrict__ bih,
                            const float* __restrict__ bhh, const float* __restrict__ whh,
                            float* __restrict__ biasp, float* __restrict__ wf,
                            float* __restrict__ wif)
{
    int i = blockIdx.x * 256 + threadIdx.x;
    if (i < G4 * H) {
        int n = i >> 7, k = i & 127;
        if (k == 0) {
            int np = ((n & 127) << 2) | (n >> 7);
            biasp[np] = bih[n] + bhh[n];
        }
        int v = i & 1, lane = (i >> 1) & 31, ks = (i >> 6) & 15, nt = i >> 10;
        int npf = nt * 8 + (lane >> 2);
        int kk  = ks * 8 + (lane & 3) + 4 * v;
        int orig = ((npf & 3) << 7) | (npf >> 2);
        wf [i] = __uint_as_float(cvt_tf32(whh[orig * H + kk]));
        wif[i] = __uint_as_float(cvt_tf32(wih[orig * H + kk]));
    }
}

// ---------------- tf32 tensor-core GEMM: C = epi( A(M,K) @ W(N,K)^T ) ----------------
// MODE 0: A is x (fused transpose), W row-major via smem; epi = FC bias+BN+LeakyReLU
// MODE 1: A row-major, register double-buffered staging; B via pre-packed frags (L1)
#define GST 20

template<int MODE>
__global__ void __launch_bounds__(256)
gemm_tc(const float* __restrict__ A, const float* __restrict__ W,
        const float* __restrict__ Wf, float* __restrict__ C,
        int M, int N, int K,
        const float* __restrict__ q0, const float* __restrict__ q1,
        const float* __restrict__ q2, const float* __restrict__ q3,
        const float* __restrict__ q4)
{
    __shared__ float As[2][128 * GST];
    __shared__ float Bs[2][(MODE == 0) ? 128 * GST : 1];
    __shared__ int   rowbase[128];

    const int tid  = threadIdx.x;
    const int lane = tid & 31, warp = tid >> 5;
    const int g = lane >> 2, t = lane & 3;
    const int wm = warp & 3, wn = warp >> 2;
    const int m0 = blockIdx.x * 128, n0 = blockIdx.y * 128;

    if (MODE == 0 && tid < 128) {
        int m = m0 + tid; int b = m / T_STEPS;
        rowbase[tid] = b * (F_IN * T_STEPS) + (m - b * T_STEPS);
    }
    __syncthreads();

    const int r  = tid >> 1;
    const int hf = tid & 1;
    const int nc = (K + 15) >> 4;

    float av[8], wv[8];
    auto LOAD = [&](int kc) {
        if (MODE == 0) {
#pragma unroll
            for (int i = 0; i < 8; i++) {
                int k = kc + hf * 8 + i;
                av[i] = (k < K) ? __ldg(A + rowbase[r] + k * T_STEPS) : 0.f;
                wv[i] = (k < K) ? __ldg(W + r * K + k) : 0.f;
            }
        } else {
            const float4* pa = (const float4*)(A + (size_t)(m0 + r) * K + kc + hf * 8);
            float4 a0v = pa[0], a1v = pa[1];
            av[0]=a0v.x; av[1]=a0v.y; av[2]=a0v.z; av[3]=a0v.w;
            av[4]=a1v.x; av[5]=a1v.y; av[6]=a1v.z; av[7]=a1v.w;
        }
    };
    auto STORE = [&](int s) {
#pragma unroll
        for (int i = 0; i < 8; i++) As[s][r * GST + hf * 8 + i] = __uint_as_float(cvt_tf32(av[i]));
        if (MODE == 0) {
#pragma unroll
            for (int i = 0; i < 8; i++) Bs[s][r * GST + hf * 8 + i] = __uint_as_float(cvt_tf32(wv[i]));
        }
    };

    float acc[2][8][4];
#pragma unroll
    for (int mi = 0; mi < 2; mi++)
#pragma unroll
        for (int j = 0; j < 8; j++)
#pragma unroll
            for (int q = 0; q < 4; q++) acc[mi][j][q] = 0.f;

    const uint2* wfrag = (const uint2*)Wf;
    const int nt_base = (n0 >> 3) + wn * 8;

    LOAD(0); STORE(0); __syncthreads();

    for (int c = 0; c < nc; c++) {
        if (c + 1 < nc) LOAD((c + 1) * 16);
        const float* as = As[c & 1];
        const float* bs = Bs[c & 1];
#pragma unroll
        for (int kh = 0; kh < 2; kh++) {
            unsigned a[2][4];
#pragma unroll
            for (int mi = 0; mi < 2; mi++) {
                int row = wm * 32 + mi * 16;
                a[mi][0] = __float_as_uint(as[(row + g    ) * GST + kh * 8 + t]);
                a[mi][1] = __float_as_uint(as[(row + g + 8) * GST + kh * 8 + t]);
                a[mi][2] = __float_as_uint(as[(row + g    ) * GST + kh * 8 + t + 4]);
                a[mi][3] = __float_as_uint(as[(row + g + 8) * GST + kh * 8 + t + 4]);
            }
            unsigned bfr[8][2];
#pragma unroll
            for (int j = 0; j < 8; j++) {
                if (MODE == 0) {
                    int col = wn * 64 + j * 8 + g;
                    bfr[j][0] = __float_as_uint(bs[col * GST + kh * 8 + t]);
                    bfr[j][1] = __float_as_uint(bs[col * GST + kh * 8 + t + 4]);
                } else {
                    uint2 b = __ldg(wfrag + ((size_t)(nt_base + j) * 16 + c * 2 + kh) * 32 + lane);
                    bfr[j][0] = b.x; bfr[j][1] = b.y;
                }
            }
#pragma unroll
            for (int mi = 0; mi < 2; mi++)
#pragma unroll
                for (int j = 0; j < 8; j++)
                    mma8(acc[mi][j], a[mi][0], a[mi][1], a[mi][2], a[mi][3],
                         bfr[j][0], bfr[j][1]);
        }
        if (c + 1 < nc) STORE((c + 1) & 1);
        __syncthreads();
    }

    const int cm = m0 + wm * 32;
    const int cn = n0 + wn * 64;
#pragma unroll
    for (int j = 0; j < 8; j++) {
        int col = cn + j * 8 + 2 * t;
        float al0, be0, al1, be1;
        if (MODE == 0) {
            float s0 = q1[col]     * rsqrtf(q4[col]     + 1e-5f);
            float s1 = q1[col + 1] * rsqrtf(q4[col + 1] + 1e-5f);
            al0 = s0; be0 = (q0[col]     - q3[col]    ) * s0 + q2[col];
            al1 = s1; be1 = (q0[col + 1] - q3[col + 1]) * s1 + q2[col + 1];
        } else {
            al0 = al1 = 1.f; be0 = q0[col]; be1 = q0[col + 1];
        }
#pragma unroll
        for (int mi = 0; mi < 2; mi++) {
            int row = cm + mi * 16 + g;
            float v0 = acc[mi][j][0] * al0 + be0;
            float v1 = acc[mi][j][1] * al1 + be1;
            float v2 = acc[mi][j][2] * al0 + be0;
            float v3 = acc[mi][j][3] * al1 + be1;
            if (MODE == 0) {
                v0 = (v0 >= 0.f) ? v0 : 0.01f * v0;
                v1 = (v1 >= 0.f) ? v1 : 0.01f * v1;
                v2 = (v2 >= 0.f) ? v2 : 0.01f * v2;
                v3 = (v3 >= 0.f) ? v3 : 0.01f * v3;
            }
            *(float2*)(C + (size_t)row * N + col)       = make_float2(v0, v1);
            *(float2*)(C + (size_t)(row + 8) * N + col) = make_float2(v2, v3);
        }
    }
}

// ---------------- persistent tf32 tensor-core LSTM ----------------
// 512 threads = 16 warps; warp owns 32 permuted gate-cols (8 hidden x 4 gates, j=0..3).
// A-fragments via ldmatrix.x4 (1 instr for 4 regs, conflict-free on stride-132 rows).
// Whh B-frags: ks0..5 in regs, ks6..15 in smem. h double-buffered -> 1 barrier/step.
#define SH     132
#define HS_BUF (16 * SH)

__global__ void __launch_bounds__(512)
lstm_tc(const float* __restrict__ xproj, const float* __restrict__ wf,
        float* __restrict__ hsout, float* __restrict__ hlast)
{
    extern __shared__ unsigned smx[];
    unsigned* h_buf = smx;                           // [2][16*SH]
    uint2*    swf   = (uint2*)(smx + 2 * HS_BUF);    // 16 warps x (4j x 10ks x 32)

    const int tid  = threadIdx.x, lane = tid & 31, w = tid >> 5;   // w 0..15
    const int g = lane >> 2, t = lane & 3;
    const int odd = t & 1;
    const int b0 = blockIdx.x * 16;
    const uint2* wfw = (const uint2*)wf + (size_t)w * 2048;
    uint2* swfw = swf + (size_t)w * 1280;

    // stage ks 6..15 into smem (one-time)
#pragma unroll
    for (int j = 0; j < 4; j++)
#pragma unroll
        for (int ks = 6; ks < 16; ks++)
            swfw[(j * 10 + ks - 6) * 32 + lane] = __ldg(wfw + (j * 16 + ks) * 32 + lane);

    // ks 0..5 resident in registers
    uint2 rb[4][6];
#pragma unroll
    for (int j = 0; j < 4; j++)
#pragma unroll
        for (int ks = 0; ks < 6; ks++)
            rb[j][ks] = __ldg(wfw + (j * 16 + ks) * 32 + lane);

    for (int i = tid; i < 2 * HS_BUF; i += 512) h_buf[i] = 0u;
    __syncthreads();

    float c_reg[4] = {0.f, 0.f, 0.f, 0.f};
    const int row_pw = g + odd * 8;
    const int hh0    = w * 8 + (t >> 1);
    const float* xr0 = xproj + (size_t)(b0 + g    ) * T_STEPS * G4;
    const float* xr1 = xproj + (size_t)(b0 + g + 8) * T_STEPS * G4;
    const int colbase = w * 32 + 2 * t;

    // ldmatrix per-lane base: row = lane%16, col-half = (lane>>4)*4 floats
    const unsigned hb_smem = (unsigned)__cvta_generic_to_shared(h_buf);
    const unsigned lmoff   = hb_smem + (((lane & 15) * SH + (lane >> 4) * 4) << 2);

    // prefetch xproj for ts = 0
    float2 p0[4], p1[4];
#pragma unroll
    for (int j = 0; j < 4; j++) {
        p0[j] = *(const float2*)(xr0 + colbase + j * 8);
        p1[j] = *(const float2*)(xr1 + colbase + j * 8);
    }

    int cur = 0;
    for (int ts = 0; ts < T_STEPS; ts++) {
        unsigned*      hnb = h_buf + (cur ^ 1) * HS_BUF;       // write buffer
        const unsigned abase = lmoff + (unsigned)(cur * HS_BUF * 4);
        float acc[4][4];
#pragma unroll
        for (int j = 0; j < 4; j++) {
            acc[j][0] = p0[j].x; acc[j][1] = p0[j].y;
            acc[j][2] = p1[j].x; acc[j][3] = p1[j].y;
        }
        // prefetch next step
        {
            int tn = (ts + 1 < T_STEPS) ? ts + 1 : ts;
#pragma unroll
            for (int j = 0; j < 4; j++) {
                p0[j] = __ldg((const float2*)(xr0 + (size_t)tn * G4 + colbase + j * 8));
                p1[j] = __ldg((const float2*)(xr1 + (size_t)tn * G4 + colbase + j * 8));
            }
        }

        // register-resident ks 0..5
#pragma unroll
        for (int ks = 0; ks < 6; ks++) {
            unsigned a0, a1, a2, a3;
            ldsm4(a0, a1, a2, a3, abase + ks * 32u);
#pragma unroll
            for (int j = 0; j < 4; j++)
                mma8(acc[j], a0, a1, a2, a3, rb[j][ks].x, rb[j][ks].y);
        }
        // smem-resident ks 6..15
#pragma unroll 5
        for (int ks = 6; ks < 16; ks++) {
            unsigned a0, a1, a2, a3;
            ldsm4(a0, a1, a2, a3, abase + ks * 32u);
#pragma unroll
            for (int j = 0; j < 4; j++) {
                uint2 b = swfw[(j * 10 + ks - 6) * 32 + lane];
                mma8(acc[j], a0, a1, a2, a3, b.x, b.y);
            }
        }

        // activations + pair-exchange + state update; write to OTHER buffer
#pragma unroll
        for (int j = 0; j < 4; j++) {
            float a0 = odd ? tanhf_(acc[j][0]) : sigmoidf_(acc[j][0]);
            float a1 = sigmoidf_(acc[j][1]);
            float a2 = odd ? tanhf_(acc[j][2]) : sigmoidf_(acc[j][2]);
            float a3 = sigmoidf_(acc[j][3]);
            float sv0 = odd ? a0 : a2;
            float sv1 = odd ? a1 : a3;
            float rv0 = __shfl_xor_sync(0xffffffffu, sv0, 1);
            float rv1 = __shfl_xor_sync(0xffffffffu, sv1, 1);
            float iG = odd ? rv0 : a0;
            float fG = odd ? rv1 : a1;
            float gG = odd ? a2  : rv0;
            float oG = odd ? a3  : rv1;
            float cn = fG * c_reg[j] + iG * gG;
            float hn = oG * tanhf_(cn);
            c_reg[j] = cn;
            int hh = hh0 + 2 * j;
            hnb[row_pw * SH + hh] = cvt_tf32(hn);
            if (hsout) hsout[((size_t)(b0 + row_pw) * T_STEPS + ts) * H + hh] = hn;
            if (hlast && ts == T_STEPS - 1) hlast[(size_t)(b0 + row_pw) * H + hh] = hn;
        }
        __syncthreads();   // single barrier per step
        cur ^= 1;
    }
}

// ---------------- launcher ----------------
extern "C" void kernel_launch(void* const* d_in, const int* in_sizes, int n_in,
                              void* d_out, int out_size)
{
    const float* x       = (const float*)d_in[0];
    const float* fc_w    = (const float*)d_in[1];
    const float* fc_b    = (const float*)d_in[2];
    const float* bn_g    = (const float*)d_in[3];
    const float* bn_b    = (const float*)d_in[4];
    const float* bn_mean = (const float*)d_in[5];
    const float* bn_var  = (const float*)d_in[6];
    const float* wih0    = (const float*)d_in[7];
    const float* whh0    = (const float*)d_in[8];
    const float* bih0    = (const float*)d_in[9];
    const float* bhh0    = (const float*)d_in[10];
    const float* wih1    = (const float*)d_in[11];
    const float* whh1    = (const float*)d_in[12];
    const float* bih1    = (const float*)d_in[13];
    const float* bhh1    = (const float*)d_in[14];
    float* out = (float*)d_out;

    const int B = in_sizes[0] / (F_IN * T_STEPS);
    const int M = B * T_STEPS;

    float *p_hpre, *p_xproj, *p_hs, *p_biasp0, *p_biasp1, *p_wf0, *p_wf1, *p_wif0, *p_wif1;
    cudaGetSymbolAddress((void**)&p_hpre,   g_hpre);
    cudaGetSymbolAddress((void**)&p_xproj,  g_xproj);
    cudaGetSymbolAddress((void**)&p_hs,     g_hs);
    cudaGetSymbolAddress((void**)&p_biasp0, g_biasp0);
    cudaGetSymbolAddress((void**)&p_biasp1, g_biasp1);
    cudaGetSymbolAddress((void**)&p_wf0,    g_wf0);
    cudaGetSymbolAddress((void**)&p_wf1,    g_wf1);
    cudaGetSymbolAddress((void**)&p_wif0,   g_wif0);
    cudaGetSymbolAddress((void**)&p_wif1,   g_wif1);

    const size_t lstm_smem = (size_t)2 * HS_BUF * 4 + (size_t)16 * 1280 * 8;  // ~177KB
    cudaFuncSetAttribute(lstm_tc, cudaFuncAttributeMaxDynamicSharedMemorySize, (int)lstm_smem);

    prep_kernel<<<256, 256>>>(wih0, bih0, bhh0, whh0, p_biasp0, p_wf0, p_wif0);
    prep_kernel<<<256, 256>>>(wih1, bih1, bhh1, whh1, p_biasp1, p_wf1, p_wif1);

    // FC (fused input transpose) + BN + LeakyReLU
    gemm_tc<0><<<dim3(M / 128, 1), 256>>>(x, fc_w, nullptr, p_hpre, M, H, F_IN,
                                          fc_b, bn_g, bn_b, bn_mean, bn_var);
    // layer-0 input projection
    gemm_tc<1><<<dim3(M / 128, 4), 256>>>(p_hpre, nullptr, p_wif0, p_xproj, M, G4, H,
                                          p_biasp0, nullptr, nullptr, nullptr, nullptr);
    // layer-0 LSTM
    lstm_tc<<<B / 16, 512, lstm_smem>>>(p_xproj, p_wf0, p_hs, nullptr);
    // layer-1 input projection
    gemm_tc<1><<<dim3(M / 128, 4), 256>>>(p_hs, nullptr, p_wif1, p_xproj, M, G4, H,
                                          p_biasp1, nullptr, nullptr, nullptr, nullptr);
    // layer-1 LSTM -> final hidden state
    lstm_tc<<<B / 16, 512, lstm_smem>>>(p_xproj, p_wf1, nullptr, out);
}

// round 7
// speedup vs baseline: 3.6252x; 1.1141x over previous
#include <cuda_runtime.h>
#include <math.h>

#define T_STEPS 120
#define F_IN    180
#define H       128
#define G4      512
#define MAX_B   2048

// ---------------- static scratch ----------------
__device__ float g_xproj[(size_t)MAX_B * T_STEPS * G4];
__device__ float g_hs   [(size_t)MAX_B * T_STEPS * H];
__device__ float g_biasp0[G4],  g_biasp1[G4];
__device__ float g_wf0[G4 * H], g_wf1[G4 * H];
__device__ float g_wif0[G4 * H], g_wif1[G4 * H];

// ---------------- helpers ----------------
__device__ __forceinline__ unsigned cvt_tf32(float f) {
    unsigned u; asm("cvt.rna.tf32.f32 %0, %1;" : "=r"(u) : "f"(f)); return u;
}
__device__ __forceinline__ void mma8(float* c, unsigned a0, unsigned a1, unsigned a2, unsigned a3,
                                     unsigned b0, unsigned b1) {
    asm volatile("mma.sync.aligned.m16n8k8.row.col.f32.tf32.tf32.f32 "
                 "{%0,%1,%2,%3}, {%4,%5,%6,%7}, {%8,%9}, {%0,%1,%2,%3};"
                 : "+f"(c[0]), "+f"(c[1]), "+f"(c[2]), "+f"(c[3])
                 : "r"(a0), "r"(a1), "r"(a2), "r"(a3), "r"(b0), "r"(b1));
}
__device__ __forceinline__ void ldsm4(unsigned& a0, unsigned& a1, unsigned& a2, unsigned& a3,
                                      unsigned addr) {
    asm volatile("ldmatrix.sync.aligned.m8n8.x4.shared.b16 {%0,%1,%2,%3}, [%4];"
                 : "=r"(a0), "=r"(a1), "=r"(a2), "=r"(a3) : "r"(addr));
}
__device__ __forceinline__ float sigmoidf_(float x) {
    return __fdividef(1.f, 1.f + __expf(-x));
}
__device__ __forceinline__ float tanhf_(float x) {
    return __fdividef(2.f, 1.f + __expf(-2.f * x)) - 1.f;
}

// ---------------- prep: combine bias, pack Whh and wih as B-fragments ----------------
// Gate interleave: orig row n (gate=n>>7, hh=n&127) -> row' = hh*4 + gate.
// frag layout: [nt(0..63)][ks(0..15)][lane(0..31)][v(0..1)]:
//   n' = nt*8 + (lane>>2), k = ks*8 + (lane&3) + 4*v   (tf32-rounded)
__global__ void prep_kernel(const float* __restrict__ wih, const float* __restrict__ bih,
                            const float* __restrict__ bhh, const float* __restrict__ whh,
                            float* __restrict__ biasp, float* __restrict__ wf,
                            float* __restrict__ wif)
{
    int i = blockIdx.x * 256 + threadIdx.x;
    if (i < G4 * H) {
        int n = i >> 7, k = i & 127;
        if (k == 0) {
            int np = ((n & 127) << 2) | (n >> 7);
            biasp[np] = bih[n] + bhh[n];
        }
        int v = i & 1, lane = (i >> 1) & 31, ks = (i >> 6) & 15, nt = i >> 10;
        int npf = nt * 8 + (lane >> 2);
        int kk  = ks * 8 + (lane & 3) + 4 * v;
        int orig = ((npf & 3) << 7) | (npf >> 2);
        wf [i] = __uint_as_float(cvt_tf32(whh[orig * H + kk]));
        wif[i] = __uint_as_float(cvt_tf32(wih[orig * H + kk]));
    }
}

#define GST  20
#define HPST 132

// ---------------- fused FC+BN+LeakyReLU -> layer-0 projection ----------------
// Phase 1: hpre(128x128) = LeakyReLU(BN(x_tile @ fc_w^T + fc_b))  (K=180, fused transpose)
//          epilogue stores tf32 bits into smem hp[128][HPST].
// Phase 2: xproj(128x512) = hp @ wih0_frags^T + biasp   (K=128, A from smem, B from L1)
__global__ void __launch_bounds__(256)
fc_proj_fused(const float* __restrict__ x, const float* __restrict__ W,
              const float* __restrict__ Wf, float* __restrict__ C,
              const float* __restrict__ fcb, const float* __restrict__ bng,
              const float* __restrict__ bnb, const float* __restrict__ bnm,
              const float* __restrict__ bnv, const float* __restrict__ biasp)
{
    extern __shared__ float fsm[];
    float*    As = fsm;                          // [2][128*GST]
    float*    Bs = fsm + 2 * 128 * GST;          // [2][128*GST]
    unsigned* hp = (unsigned*)(fsm + 4 * 128 * GST);   // [128][HPST]
    __shared__ int rowbase[128];

    const int tid  = threadIdx.x;
    const int lane = tid & 31, warp = tid >> 5;
    const int g = lane >> 2, t = lane & 3;
    const int wm = warp & 3, wn = warp >> 2;     // warp tile 32x64, N=128 (wn 0/1)
    const int m0 = blockIdx.x * 128;

    if (tid < 128) {
        int m = m0 + tid; int b = m / T_STEPS;
        rowbase[tid] = b * (F_IN * T_STEPS) + (m - b * T_STEPS);
    }
    __syncthreads();

    const int r  = tid >> 1;
    const int hf = tid & 1;
    const int nc = (F_IN + 15) >> 4;   // 12

    float av[8], wv[8];
    auto LOAD = [&](int kc) {
#pragma unroll
        for (int i = 0; i < 8; i++) {
            int k = kc + hf * 8 + i;
            av[i] = (k < F_IN) ? __ldg(x + rowbase[r] + k * T_STEPS) : 0.f;
            wv[i] = (k < F_IN) ? __ldg(W + r * F_IN + k) : 0.f;
        }
    };
    auto STORE = [&](int s) {
#pragma unroll
        for (int i = 0; i < 8; i++) As[s * 128 * GST + r * GST + hf * 8 + i] = __uint_as_float(cvt_tf32(av[i]));
#pragma unroll
        for (int i = 0; i < 8; i++) Bs[s * 128 * GST + r * GST + hf * 8 + i] = __uint_as_float(cvt_tf32(wv[i]));
    };

    float acc[2][8][4];
#pragma unroll
    for (int mi = 0; mi < 2; mi++)
#pragma unroll
        for (int j = 0; j < 8; j++)
#pragma unroll
            for (int q = 0; q < 4; q++) acc[mi][j][q] = 0.f;

    LOAD(0); STORE(0); __syncthreads();

    for (int c = 0; c < nc; c++) {
        if (c + 1 < nc) LOAD((c + 1) * 16);
        const float* as = As + (c & 1) * 128 * GST;
        const float* bs = Bs + (c & 1) * 128 * GST;
#pragma unroll
        for (int kh = 0; kh < 2; kh++) {
            unsigned a[2][4];
#pragma unroll
            for (int mi = 0; mi < 2; mi++) {
                int row = wm * 32 + mi * 16;
                a[mi][0] = __float_as_uint(as[(row + g    ) * GST + kh * 8 + t]);
                a[mi][1] = __float_as_uint(as[(row + g + 8) * GST + kh * 8 + t]);
                a[mi][2] = __float_as_uint(as[(row + g    ) * GST + kh * 8 + t + 4]);
                a[mi][3] = __float_as_uint(as[(row + g + 8) * GST + kh * 8 + t + 4]);
            }
#pragma unroll
            for (int j = 0; j < 8; j++) {
                int col = wn * 64 + j * 8 + g;
                unsigned b0 = __float_as_uint(bs[col * GST + kh * 8 + t]);
                unsigned b1 = __float_as_uint(bs[col * GST + kh * 8 + t + 4]);
#pragma unroll
                for (int mi = 0; mi < 2; mi++)
                    mma8(acc[mi][j], a[mi][0], a[mi][1], a[mi][2], a[mi][3], b0, b1);
            }
        }
        if (c + 1 < nc) STORE((c + 1) & 1);
        __syncthreads();
    }

    // phase-1 epilogue: BN + LeakyReLU -> tf32 bits into hp
#pragma unroll
    for (int j = 0; j < 8; j++) {
        int col = wn * 64 + j * 8 + 2 * t;
        float s0 = bng[col]     * rsqrtf(bnv[col]     + 1e-5f);
        float s1 = bng[col + 1] * rsqrtf(bnv[col + 1] + 1e-5f);
        float be0 = (fcb[col]     - bnm[col]    ) * s0 + bnb[col];
        float be1 = (fcb[col + 1] - bnm[col + 1]) * s1 + bnb[col + 1];
#pragma unroll
        for (int mi = 0; mi < 2; mi++) {
            int row = wm * 32 + mi * 16 + g;
            float v0 = acc[mi][j][0] * s0 + be0;
            float v1 = acc[mi][j][1] * s1 + be1;
            float v2 = acc[mi][j][2] * s0 + be0;
            float v3 = acc[mi][j][3] * s1 + be1;
            v0 = (v0 >= 0.f) ? v0 : 0.01f * v0;
            v1 = (v1 >= 0.f) ? v1 : 0.01f * v1;
            v2 = (v2 >= 0.f) ? v2 : 0.01f * v2;
            v3 = (v3 >= 0.f) ? v3 : 0.01f * v3;
            *(uint2*)&hp[(row    ) * HPST + col] = make_uint2(cvt_tf32(v0), cvt_tf32(v1));
            *(uint2*)&hp[(row + 8) * HPST + col] = make_uint2(cvt_tf32(v2), cvt_tf32(v3));
        }
    }
    __syncthreads();

    // phase 2: 4 n-chunks of 128 cols, K=128 from smem hp
    const uint2* wfrag = (const uint2*)Wf;
#pragma unroll 1
    for (int nch = 0; nch < 4; nch++) {
        float a2[2][8][4];
#pragma unroll
        for (int mi = 0; mi < 2; mi++)
#pragma unroll
            for (int j = 0; j < 8; j++)
#pragma unroll
                for (int q = 0; q < 4; q++) a2[mi][j][q] = 0.f;

        const int ntb = nch * 16 + wn * 8;
#pragma unroll 4
        for (int kh = 0; kh < 16; kh++) {
            unsigned a[2][4];
#pragma unroll
            for (int mi = 0; mi < 2; mi++) {
                int row = wm * 32 + mi * 16;
                a[mi][0] = hp[(row + g    ) * HPST + kh * 8 + t];
                a[mi][1] = hp[(row + g + 8) * HPST + kh * 8 + t];
                a[mi][2] = hp[(row + g    ) * HPST + kh * 8 + t + 4];
                a[mi][3] = hp[(row + g + 8) * HPST + kh * 8 + t + 4];
            }
#pragma unroll
            for (int j = 0; j < 8; j++) {
                uint2 b = __ldg(wfrag + ((size_t)(ntb + j) * 16 + kh) * 32 + lane);
#pragma unroll
                for (int mi = 0; mi < 2; mi++)
                    mma8(a2[mi][j], a[mi][0], a[mi][1], a[mi][2], a[mi][3], b.x, b.y);
            }
        }
        // epilogue: + biasp -> xproj
#pragma unroll
        for (int j = 0; j < 8; j++) {
            int col = nch * 128 + wn * 64 + j * 8 + 2 * t;
            float be0 = __ldg(biasp + col);
            float be1 = __ldg(biasp + col + 1);
#pragma unroll
            for (int mi = 0; mi < 2; mi++) {
                int row = m0 + wm * 32 + mi * 16 + g;
                *(float2*)(C + (size_t)row * G4 + col) =
                    make_float2(a2[mi][j][0] + be0, a2[mi][j][1] + be1);
                *(float2*)(C + (size_t)(row + 8) * G4 + col) =
                    make_float2(a2[mi][j][2] + be0, a2[mi][j][3] + be1);
            }
        }
    }
}

// ---------------- tf32 GEMM for layer-1 projection (MODE 1 of prior rounds) ----------------
__global__ void __launch_bounds__(256)
gemm_tc1(const float* __restrict__ A, const float* __restrict__ Wf, float* __restrict__ C,
         int M, const float* __restrict__ q0)
{
    __shared__ float As[2][128 * GST];

    const int tid  = threadIdx.x;
    const int lane = tid & 31, warp = tid >> 5;
    const int g = lane >> 2, t = lane & 3;
    const int wm = warp & 3, wn = warp >> 2;
    const int m0 = blockIdx.x * 128, n0 = blockIdx.y * 128;
    const int r  = tid >> 1;
    const int hf = tid & 1;

    float av[8];
    auto LOAD = [&](int kc) {
        const float4* pa = (const float4*)(A + (size_t)(m0 + r) * H + kc + hf * 8);
        float4 a0v = pa[0], a1v = pa[1];
        av[0]=a0v.x; av[1]=a0v.y; av[2]=a0v.z; av[3]=a0v.w;
        av[4]=a1v.x; av[5]=a1v.y; av[6]=a1v.z; av[7]=a1v.w;
    };
    auto STORE = [&](int s) {
#pragma unroll
        for (int i = 0; i < 8; i++) As[s][r * GST + hf * 8 + i] = __uint_as_float(cvt_tf32(av[i]));
    };

    float acc[2][8][4];
#pragma unroll
    for (int mi = 0; mi < 2; mi++)
#pragma unroll
        for (int j = 0; j < 8; j++)
#pragma unroll
            for (int q = 0; q < 4; q++) acc[mi][j][q] = 0.f;

    const uint2* wfrag = (const uint2*)Wf;
    const int nt_base = (n0 >> 3) + wn * 8;

    LOAD(0); STORE(0); __syncthreads();

    for (int c = 0; c < 8; c++) {
        if (c + 1 < 8) LOAD((c + 1) * 16);
        const float* as = As[c & 1];
#pragma unroll
        for (int kh = 0; kh < 2; kh++) {
            unsigned a[2][4];
#pragma unroll
            for (int mi = 0; mi < 2; mi++) {
                int row = wm * 32 + mi * 16;
                a[mi][0] = __float_as_uint(as[(row + g    ) * GST + kh * 8 + t]);
                a[mi][1] = __float_as_uint(as[(row + g + 8) * GST + kh * 8 + t]);
                a[mi][2] = __float_as_uint(as[(row + g    ) * GST + kh * 8 + t + 4]);
                a[mi][3] = __float_as_uint(as[(row + g + 8) * GST + kh * 8 + t + 4]);
            }
#pragma unroll
            for (int j = 0; j < 8; j++) {
                uint2 b = __ldg(wfrag + ((size_t)(nt_base + j) * 16 + c * 2 + kh) * 32 + lane);
#pragma unroll
                for (int mi = 0; mi < 2; mi++)
                    mma8(acc[mi][j], a[mi][0], a[mi][1], a[mi][2], a[mi][3], b.x, b.y);
            }
        }
        if (c + 1 < 8) STORE((c + 1) & 1);
        __syncthreads();
    }

    const int cm = m0 + wm * 32;
    const int cn = n0 + wn * 64;
#pragma unroll
    for (int j = 0; j < 8; j++) {
        int col = cn + j * 8 + 2 * t;
        float be0 = __ldg(q0 + col);
        float be1 = __ldg(q0 + col + 1);
#pragma unroll
        for (int mi = 0; mi < 2; mi++) {
            int row = cm + mi * 16 + g;
            *(float2*)(C + (size_t)row * G4 + col) =
                make_float2(acc[mi][j][0] + be0, acc[mi][j][1] + be1);
            *(float2*)(C + (size_t)(row + 8) * G4 + col) =
                make_float2(acc[mi][j][2] + be0, acc[mi][j][3] + be1);
        }
    }
}

// ---------------- persistent tf32 tensor-core LSTM ----------------
#define SH     132
#define HS_BUF (16 * SH)

__global__ void __launch_bounds__(512)
lstm_tc(const float* __restrict__ xproj, const float* __restrict__ wf,
        float* __restrict__ hsout, float* __restrict__ hlast)
{
    extern __shared__ unsigned smx[];
    unsigned* h_buf = smx;                           // [2][16*SH]
    uint2*    swf   = (uint2*)(smx + 2 * HS_BUF);    // 16 warps x (4j x 10ks x 32)

    const int tid  = threadIdx.x, lane = tid & 31, w = tid >> 5;
    const int g = lane >> 2, t = lane & 3;
    const int odd = t & 1;
    const int b0 = blockIdx.x * 16;
    const uint2* wfw = (const uint2*)wf + (size_t)w * 2048;
    uint2* swfw = swf + (size_t)w * 1280;

#pragma unroll
    for (int j = 0; j < 4; j++)
#pragma unroll
        for (int ks = 6; ks < 16; ks++)
            swfw[(j * 10 + ks - 6) * 32 + lane] = __ldg(wfw + (j * 16 + ks) * 32 + lane);

    uint2 rb[4][6];
#pragma unroll
    for (int j = 0; j < 4; j++)
#pragma unroll
        for (int ks = 0; ks < 6; ks++)
            rb[j][ks] = __ldg(wfw + (j * 16 + ks) * 32 + lane);

    for (int i = tid; i < 2 * HS_BUF; i += 512) h_buf[i] = 0u;
    __syncthreads();

    float c_reg[4] = {0.f, 0.f, 0.f, 0.f};
    const int row_pw = g + odd * 8;
    const int hh0    = w * 8 + (t >> 1);
    const float* xr0 = xproj + (size_t)(b0 + g    ) * T_STEPS * G4;
    const float* xr1 = xproj + (size_t)(b0 + g + 8) * T_STEPS * G4;
    const int colbase = w * 32 + 2 * t;

    const unsigned hb_smem = (unsigned)__cvta_generic_to_shared(h_buf);
    const unsigned lmoff   = hb_smem + (((lane & 15) * SH + (lane >> 4) * 4) << 2);

    float2 p0[4], p1[4];
#pragma unroll
    for (int j = 0; j < 4; j++) {
        p0[j] = *(const float2*)(xr0 + colbase + j * 8);
        p1[j] = *(const float2*)(xr1 + colbase + j * 8);
    }

    int cur = 0;
    for (int ts = 0; ts < T_STEPS; ts++) {
        unsigned*      hnb = h_buf + (cur ^ 1) * HS_BUF;
        const unsigned abase = lmoff + (unsigned)(cur * HS_BUF * 4);
        float acc[4][4];
#pragma unroll
        for (int j = 0; j < 4; j++) {
            acc[j][0] = p0[j].x; acc[j][1] = p0[j].y;
            acc[j][2] = p1[j].x; acc[j][3] = p1[j].y;
        }
        {
            int tn = (ts + 1 < T_STEPS) ? ts + 1 : ts;
#pragma unroll
            for (int j = 0; j < 4; j++) {
                p0[j] = __ldg((const float2*)(xr0 + (size_t)tn * G4 + colbase + j * 8));
                p1[j] = __ldg((const float2*)(xr1 + (size_t)tn * G4 + colbase + j * 8));
            }
        }

#pragma unroll
        for (int ks = 0; ks < 6; ks++) {
            unsigned a0, a1, a2, a3;
            ldsm4(a0, a1, a2, a3, abase + ks * 32u);
#pragma unroll
            for (int j = 0; j < 4; j++)
                mma8(acc[j], a0, a1, a2, a3, rb[j][ks].x, rb[j][ks].y);
        }
#pragma unroll
        for (int ks = 6; ks < 16; ks++) {
            unsigned a0, a1, a2, a3;
            ldsm4(a0, a1, a2, a3, abase + ks * 32u);
#pragma unroll
            for (int j = 0; j < 4; j++) {
                uint2 b = swfw[(j * 10 + ks - 6) * 32 + lane];
                mma8(acc[j], a0, a1, a2, a3, b.x, b.y);
            }
        }

#pragma unroll
        for (int j = 0; j < 4; j++) {
            float a0 = odd ? tanhf_(acc[j][0]) : sigmoidf_(acc[j][0]);
            float a1 = sigmoidf_(acc[j][1]);
            float a2 = odd ? tanhf_(acc[j][2]) : sigmoidf_(acc[j][2]);
            float a3 = sigmoidf_(acc[j][3]);
            float sv0 = odd ? a0 : a2;
            float sv1 = odd ? a1 : a3;
            float rv0 = __shfl_xor_sync(0xffffffffu, sv0, 1);
            float rv1 = __shfl_xor_sync(0xffffffffu, sv1, 1);
            float iG = odd ? rv0 : a0;
            float fG = odd ? rv1 : a1;
            float gG = odd ? a2  : rv0;
            float oG = odd ? a3  : rv1;
            float cn = fG * c_reg[j] + iG * gG;
            float hn = oG * tanhf_(cn);
            c_reg[j] = cn;
            int hh = hh0 + 2 * j;
            hnb[row_pw * SH + hh] = cvt_tf32(hn);
            if (hsout) hsout[((size_t)(b0 + row_pw) * T_STEPS + ts) * H + hh] = hn;
            if (hlast && ts == T_STEPS - 1) hlast[(size_t)(b0 + row_pw) * H + hh] = hn;
        }
        __syncthreads();
        cur ^= 1;
    }
}

// ---------------- launcher ----------------
extern "C" void kernel_launch(void* const* d_in, const int* in_sizes, int n_in,
                              void* d_out, int out_size)
{
    const float* x       = (const float*)d_in[0];
    const float* fc_w    = (const float*)d_in[1];
    const float* fc_b    = (const float*)d_in[2];
    const float* bn_g    = (const float*)d_in[3];
    const float* bn_b    = (const float*)d_in[4];
    const float* bn_mean = (const float*)d_in[5];
    const float* bn_var  = (const float*)d_in[6];
    const float* wih0    = (const float*)d_in[7];
    const float* whh0    = (const float*)d_in[8];
    const float* bih0    = (const float*)d_in[9];
    const float* bhh0    = (const float*)d_in[10];
    const float* wih1    = (const float*)d_in[11];
    const float* whh1    = (const float*)d_in[12];
    const float* bih1    = (const float*)d_in[13];
    const float* bhh1    = (const float*)d_in[14];
    float* out = (float*)d_out;

    const int B = in_sizes[0] / (F_IN * T_STEPS);
    const int M = B * T_STEPS;

    float *p_xproj, *p_hs, *p_biasp0, *p_biasp1, *p_wf0, *p_wf1, *p_wif0, *p_wif1;
    cudaGetSymbolAddress((void**)&p_xproj,  g_xproj);
    cudaGetSymbolAddress((void**)&p_hs,     g_hs);
    cudaGetSymbolAddress((void**)&p_biasp0, g_biasp0);
    cudaGetSymbolAddress((void**)&p_biasp1, g_biasp1);
    cudaGetSymbolAddress((void**)&p_wf0,    g_wf0);
    cudaGetSymbolAddress((void**)&p_wf1,    g_wf1);
    cudaGetSymbolAddress((void**)&p_wif0,   g_wif0);
    cudaGetSymbolAddress((void**)&p_wif1,   g_wif1);

    const size_t lstm_smem = (size_t)2 * HS_BUF * 4 + (size_t)16 * 1280 * 8;          // ~177KB
    const size_t fuse_smem = (size_t)(4 * 128 * GST + 128 * HPST) * 4;                 // ~108KB
    cudaFuncSetAttribute(lstm_tc, cudaFuncAttributeMaxDynamicSharedMemorySize, (int)lstm_smem);
    cudaFuncSetAttribute(fc_proj_fused, cudaFuncAttributeMaxDynamicSharedMemorySize, (int)fuse_smem);

    prep_kernel<<<256, 256>>>(wih0, bih0, bhh0, whh0, p_biasp0, p_wf0, p_wif0);
    prep_kernel<<<256, 256>>>(wih1, bih1, bhh1, whh1, p_biasp1, p_wf1, p_wif1);

    // fused FC+BN+LeakyReLU -> layer-0 projection
    fc_proj_fused<<<M / 128, 256, fuse_smem>>>(x, fc_w, p_wif0, p_xproj,
                                               fc_b, bn_g, bn_b, bn_mean, bn_var, p_biasp0);
    // layer-0 LSTM
    lstm_tc<<<B / 16, 512, lstm_smem>>>(p_xproj, p_wf0, p_hs, nullptr);
    // layer-1 projection
    gemm_tc1<<<dim3(M / 128, 4), 256>>>(p_hs, p_wif1, p_xproj, M, p_biasp1);
    // layer-1 LSTM -> final hidden state
    lstm_tc<<<B / 16, 512, lstm_smem>>>(p_xproj, p_wf1, nullptr, out);
}

// round 8
// speedup vs baseline: 3.7605x; 1.0373x over previous
#include <cuda_runtime.h>
#include <cuda_fp16.h>
#include <math.h>

#define T_STEPS 120
#define F_IN    180
#define H       128
#define G4      512
#define MAX_B   2048

// ---------------- static scratch ----------------
__device__ __half g_xproj[(size_t)MAX_B * T_STEPS * G4];   // fp16 projections (reused)
__device__ float  g_hs   [(size_t)MAX_B * T_STEPS * H];    // layer-0 hidden states (fp32)
__device__ float  g_biasp0[G4],  g_biasp1[G4];
__device__ float  g_wf0[G4 * H], g_wf1[G4 * H];
__device__ float  g_wif0[G4 * H], g_wif1[G4 * H];

// ---------------- helpers ----------------
__device__ __forceinline__ unsigned cvt_tf32(float f) {
    unsigned u; asm("cvt.rna.tf32.f32 %0, %1;" : "=r"(u) : "f"(f)); return u;
}
__device__ __forceinline__ void mma8(float* c, unsigned a0, unsigned a1, unsigned a2, unsigned a3,
                                     unsigned b0, unsigned b1) {
    asm volatile("mma.sync.aligned.m16n8k8.row.col.f32.tf32.tf32.f32 "
                 "{%0,%1,%2,%3}, {%4,%5,%6,%7}, {%8,%9}, {%0,%1,%2,%3};"
                 : "+f"(c[0]), "+f"(c[1]), "+f"(c[2]), "+f"(c[3])
                 : "r"(a0), "r"(a1), "r"(a2), "r"(a3), "r"(b0), "r"(b1));
}
__device__ __forceinline__ void ldsm4(unsigned& a0, unsigned& a1, unsigned& a2, unsigned& a3,
                                      unsigned addr) {
    asm volatile("ldmatrix.sync.aligned.m8n8.x4.shared.b16 {%0,%1,%2,%3}, [%4];"
                 : "=r"(a0), "=r"(a1), "=r"(a2), "=r"(a3) : "r"(addr));
}
__device__ __forceinline__ float sigmoidf_(float x) {
    return __fdividef(1.f, 1.f + __expf(-x));
}
__device__ __forceinline__ float tanhf_(float x) {
    return __fdividef(2.f, 1.f + __expf(-2.f * x)) - 1.f;
}

// ---------------- prep: combine bias, pack Whh and wih as B-fragments ----------------
// Gate interleave: orig row n (gate=n>>7, hh=n&127) -> row' = hh*4 + gate.
// frag layout: [nt(0..63)][ks(0..15)][lane(0..31)][v(0..1)]:
//   n' = nt*8 + (lane>>2), k = ks*8 + (lane&3) + 4*v   (tf32-rounded)
__global__ void prep_kernel(const float* __restrict__ wih, const float* __restrict__ bih,
                            const float* __restrict__ bhh, const float* __restrict__ whh,
                            float* __restrict__ biasp, float* __restrict__ wf,
                            float* __restrict__ wif)
{
    int i = blockIdx.x * 256 + threadIdx.x;
    if (i < G4 * H) {
        int n = i >> 7, k = i & 127;
        if (k == 0) {
            int np = ((n & 127) << 2) | (n >> 7);
            biasp[np] = bih[n] + bhh[n];
        }
        int v = i & 1, lane = (i >> 1) & 31, ks = (i >> 6) & 15, nt = i >> 10;
        int npf = nt * 8 + (lane >> 2);
        int kk  = ks * 8 + (lane & 3) + 4 * v;
        int orig = ((npf & 3) << 7) | (npf >> 2);
        wf [i] = __uint_as_float(cvt_tf32(whh[orig * H + kk]));
        wif[i] = __uint_as_float(cvt_tf32(wih[orig * H + kk]));
    }
}

#define GST  20
#define HPST 132

// ---------------- fused FC+BN+LeakyReLU -> layer-0 projection ----------------
__global__ void __launch_bounds__(256)
fc_proj_fused(const float* __restrict__ x, const float* __restrict__ W,
              const float* __restrict__ Wf, __half* __restrict__ C,
              const float* __restrict__ fcb, const float* __restrict__ bng,
              const float* __restrict__ bnb, const float* __restrict__ bnm,
              const float* __restrict__ bnv, const float* __restrict__ biasp)
{
    extern __shared__ float fsm[];
    float*    As = fsm;                                // [2][128*GST]
    float*    Bs = fsm + 2 * 128 * GST;                // [2][128*GST]
    unsigned* hp = (unsigned*)(fsm + 4 * 128 * GST);   // [128][HPST]
    __shared__ int rowbase[128];

    const int tid  = threadIdx.x;
    const int lane = tid & 31, warp = tid >> 5;
    const int g = lane >> 2, t = lane & 3;
    const int wm = warp & 3, wn = warp >> 2;
    const int m0 = blockIdx.x * 128;

    if (tid < 128) {
        int m = m0 + tid; int b = m / T_STEPS;
        rowbase[tid] = b * (F_IN * T_STEPS) + (m - b * T_STEPS);
    }
    __syncthreads();

    const int r  = tid >> 1;
    const int hf = tid & 1;
    const int nc = (F_IN + 15) >> 4;   // 12

    float av[8], wv[8];
    auto LOAD = [&](int kc) {
#pragma unroll
        for (int i = 0; i < 8; i++) {
            int k = kc + hf * 8 + i;
            av[i] = (k < F_IN) ? __ldg(x + rowbase[r] + k * T_STEPS) : 0.f;
            wv[i] = (k < F_IN) ? __ldg(W + r * F_IN + k) : 0.f;
        }
    };
    auto STORE = [&](int s) {
#pragma unroll
        for (int i = 0; i < 8; i++) As[s * 128 * GST + r * GST + hf * 8 + i] = __uint_as_float(cvt_tf32(av[i]));
#pragma unroll
        for (int i = 0; i < 8; i++) Bs[s * 128 * GST + r * GST + hf * 8 + i] = __uint_as_float(cvt_tf32(wv[i]));
    };

    float acc[2][8][4];
#pragma unroll
    for (int mi = 0; mi < 2; mi++)
#pragma unroll
        for (int j = 0; j < 8; j++)
#pragma unroll
            for (int q = 0; q < 4; q++) acc[mi][j][q] = 0.f;

    LOAD(0); STORE(0); __syncthreads();

    for (int c = 0; c < nc; c++) {
        if (c + 1 < nc) LOAD((c + 1) * 16);
        const float* as = As + (c & 1) * 128 * GST;
        const float* bs = Bs + (c & 1) * 128 * GST;
#pragma unroll
        for (int kh = 0; kh < 2; kh++) {
            unsigned a[2][4];
#pragma unroll
            for (int mi = 0; mi < 2; mi++) {
                int row = wm * 32 + mi * 16;
                a[mi][0] = __float_as_uint(as[(row + g    ) * GST + kh * 8 + t]);
                a[mi][1] = __float_as_uint(as[(row + g + 8) * GST + kh * 8 + t]);
                a[mi][2] = __float_as_uint(as[(row + g    ) * GST + kh * 8 + t + 4]);
                a[mi][3] = __float_as_uint(as[(row + g + 8) * GST + kh * 8 + t + 4]);
            }
#pragma unroll
            for (int j = 0; j < 8; j++) {
                int col = wn * 64 + j * 8 + g;
                unsigned b0 = __float_as_uint(bs[col * GST + kh * 8 + t]);
                unsigned b1 = __float_as_uint(bs[col * GST + kh * 8 + t + 4]);
#pragma unroll
                for (int mi = 0; mi < 2; mi++)
                    mma8(acc[mi][j], a[mi][0], a[mi][1], a[mi][2], a[mi][3], b0, b1);
            }
        }
        if (c + 1 < nc) STORE((c + 1) & 1);
        __syncthreads();
    }

    // phase-1 epilogue: BN + LeakyReLU -> tf32 bits into hp
#pragma unroll
    for (int j = 0; j < 8; j++) {
        int col = wn * 64 + j * 8 + 2 * t;
        float s0 = bng[col]     * rsqrtf(bnv[col]     + 1e-5f);
        float s1 = bng[col + 1] * rsqrtf(bnv[col + 1] + 1e-5f);
        float be0 = (fcb[col]     - bnm[col]    ) * s0 + bnb[col];
        float be1 = (fcb[col + 1] - bnm[col + 1]) * s1 + bnb[col + 1];
#pragma unroll
        for (int mi = 0; mi < 2; mi++) {
            int row = wm * 32 + mi * 16 + g;
            float v0 = acc[mi][j][0] * s0 + be0;
            float v1 = acc[mi][j][1] * s1 + be1;
            float v2 = acc[mi][j][2] * s0 + be0;
            float v3 = acc[mi][j][3] * s1 + be1;
            v0 = (v0 >= 0.f) ? v0 : 0.01f * v0;
            v1 = (v1 >= 0.f) ? v1 : 0.01f * v1;
            v2 = (v2 >= 0.f) ? v2 : 0.01f * v2;
            v3 = (v3 >= 0.f) ? v3 : 0.01f * v3;
            *(uint2*)&hp[(row    ) * HPST + col] = make_uint2(cvt_tf32(v0), cvt_tf32(v1));
            *(uint2*)&hp[(row + 8) * HPST + col] = make_uint2(cvt_tf32(v2), cvt_tf32(v3));
        }
    }
    __syncthreads();

    // phase 2: 4 n-chunks of 128 cols, K=128 from smem hp
    const uint2* wfrag = (const uint2*)Wf;
#pragma unroll 1
    for (int nch = 0; nch < 4; nch++) {
        float a2[2][8][4];
#pragma unroll
        for (int mi = 0; mi < 2; mi++)
#pragma unroll
            for (int j = 0; j < 8; j++)
#pragma unroll
                for (int q = 0; q < 4; q++) a2[mi][j][q] = 0.f;

        const int ntb = nch * 16 + wn * 8;
#pragma unroll 4
        for (int kh = 0; kh < 16; kh++) {
            unsigned a[2][4];
#pragma unroll
            for (int mi = 0; mi < 2; mi++) {
                int row = wm * 32 + mi * 16;
                a[mi][0] = hp[(row + g    ) * HPST + kh * 8 + t];
                a[mi][1] = hp[(row + g + 8) * HPST + kh * 8 + t];
                a[mi][2] = hp[(row + g    ) * HPST + kh * 8 + t + 4];
                a[mi][3] = hp[(row + g + 8) * HPST + kh * 8 + t + 4];
            }
#pragma unroll
            for (int j = 0; j < 8; j++) {
                uint2 b = __ldg(wfrag + ((size_t)(ntb + j) * 16 + kh) * 32 + lane);
#pragma unroll
                for (int mi = 0; mi < 2; mi++)
                    mma8(a2[mi][j], a[mi][0], a[mi][1], a[mi][2], a[mi][3], b.x, b.y);
            }
        }
        // epilogue: + biasp -> fp16 xproj
#pragma unroll
        for (int j = 0; j < 8; j++) {
            int col = nch * 128 + wn * 64 + j * 8 + 2 * t;
            float be0 = __ldg(biasp + col);
            float be1 = __ldg(biasp + col + 1);
#pragma unroll
            for (int mi = 0; mi < 2; mi++) {
                int row = m0 + wm * 32 + mi * 16 + g;
                *(__half2*)(C + (size_t)row * G4 + col) =
                    __floats2half2_rn(a2[mi][j][0] + be0, a2[mi][j][1] + be1);
                *(__half2*)(C + (size_t)(row + 8) * G4 + col) =
                    __floats2half2_rn(a2[mi][j][2] + be0, a2[mi][j][3] + be1);
            }
        }
    }
}

// ---------------- tf32 GEMM for layer-1 projection ----------------
__global__ void __launch_bounds__(256)
gemm_tc1(const float* __restrict__ A, const float* __restrict__ Wf, __half* __restrict__ C,
         int M, const float* __restrict__ q0)
{
    __shared__ float As[2][128 * GST];

    const int tid  = threadIdx.x;
    const int lane = tid & 31, warp = tid >> 5;
    const int g = lane >> 2, t = lane & 3;
    const int wm = warp & 3, wn = warp >> 2;
    const int m0 = blockIdx.x * 128, n0 = blockIdx.y * 128;
    const int r  = tid >> 1;
    const int hf = tid & 1;

    float av[8];
    auto LOAD = [&](int kc) {
        const float4* pa = (const float4*)(A + (size_t)(m0 + r) * H + kc + hf * 8);
        float4 a0v = pa[0], a1v = pa[1];
        av[0]=a0v.x; av[1]=a0v.y; av[2]=a0v.z; av[3]=a0v.w;
        av[4]=a1v.x; av[5]=a1v.y; av[6]=a1v.z; av[7]=a1v.w;
    };
    auto STORE = [&](int s) {
#pragma unroll
        for (int i = 0; i < 8; i++) As[s][r * GST + hf * 8 + i] = __uint_as_float(cvt_tf32(av[i]));
    };

    float acc[2][8][4];
#pragma unroll
    for (int mi = 0; mi < 2; mi++)
#pragma unroll
        for (int j = 0; j < 8; j++)
#pragma unroll
            for (int q = 0; q < 4; q++) acc[mi][j][q] = 0.f;

    const uint2* wfrag = (const uint2*)Wf;
    const int nt_base = (n0 >> 3) + wn * 8;

    LOAD(0); STORE(0); __syncthreads();

    for (int c = 0; c < 8; c++) {
        if (c + 1 < 8) LOAD((c + 1) * 16);
        const float* as = As[c & 1];
#pragma unroll
        for (int kh = 0; kh < 2; kh++) {
            unsigned a[2][4];
#pragma unroll
            for (int mi = 0; mi < 2; mi++) {
                int row = wm * 32 + mi * 16;
                a[mi][0] = __float_as_uint(as[(row + g    ) * GST + kh * 8 + t]);
                a[mi][1] = __float_as_uint(as[(row + g + 8) * GST + kh * 8 + t]);
                a[mi][2] = __float_as_uint(as[(row + g    ) * GST + kh * 8 + t + 4]);
                a[mi][3] = __float_as_uint(as[(row + g + 8) * GST + kh * 8 + t + 4]);
            }
#pragma unroll
            for (int j = 0; j < 8; j++) {
                uint2 b = __ldg(wfrag + ((size_t)(nt_base + j) * 16 + c * 2 + kh) * 32 + lane);
#pragma unroll
                for (int mi = 0; mi < 2; mi++)
                    mma8(acc[mi][j], a[mi][0], a[mi][1], a[mi][2], a[mi][3], b.x, b.y);
            }
        }
        if (c + 1 < 8) STORE((c + 1) & 1);
        __syncthreads();
    }

    const int cm = m0 + wm * 32;
    const int cn = n0 + wn * 64;
#pragma unroll
    for (int j = 0; j < 8; j++) {
        int col = cn + j * 8 + 2 * t;
        float be0 = __ldg(q0 + col);
        float be1 = __ldg(q0 + col + 1);
#pragma unroll
        for (int mi = 0; mi < 2; mi++) {
            int row = cm + mi * 16 + g;
            *(__half2*)(C + (size_t)row * G4 + col) =
                __floats2half2_rn(acc[mi][j][0] + be0, acc[mi][j][1] + be1);
            *(__half2*)(C + (size_t)(row + 8) * G4 + col) =
                __floats2half2_rn(acc[mi][j][2] + be0, acc[mi][j][3] + be1);
        }
    }
}

// ---------------- persistent tf32 tensor-core LSTM ----------------
// 512 threads = 16 warps; warp owns 32 permuted gate-cols (8 hidden x 4 gates, j=0..3).
// A via ldmatrix.x4; Whh B-frags: ks0..5 regs, ks6..15 smem packed as ks-PAIRS (uint4).
// h double-buffered -> 1 barrier/step. xproj is fp16.
#define SH     132
#define HS_BUF (16 * SH)

__global__ void __launch_bounds__(512)
lstm_tc(const __half* __restrict__ xproj, const float* __restrict__ wf,
        float* __restrict__ hsout, float* __restrict__ hlast)
{
    extern __shared__ unsigned smx[];
    unsigned* h_buf = smx;                           // [2][16*SH]
    uint4*    swf   = (uint4*)(smx + 2 * HS_BUF);    // 16 warps x (4j x 5pairs x 32) uint4

    const int tid  = threadIdx.x, lane = tid & 31, w = tid >> 5;
    const int g = lane >> 2, t = lane & 3;
    const int odd = t & 1;
    const int b0 = blockIdx.x * 16;
    const uint2* wfw = (const uint2*)wf + (size_t)w * 2048;
    uint4* swfw = swf + (size_t)w * 640;

    // stage ks 6..15 into smem as pairs (one-time)
#pragma unroll
    for (int j = 0; j < 4; j++)
#pragma unroll
        for (int p = 0; p < 5; p++) {
            uint2 bA = __ldg(wfw + (j * 16 + 6 + 2 * p) * 32 + lane);
            uint2 bB = __ldg(wfw + (j * 16 + 7 + 2 * p) * 32 + lane);
            swfw[(j * 5 + p) * 32 + lane] = make_uint4(bA.x, bA.y, bB.x, bB.y);
        }

    // ks 0..5 resident in registers
    uint2 rb[4][6];
#pragma unroll
    for (int j = 0; j < 4; j++)
#pragma unroll
        for (int ks = 0; ks < 6; ks++)
            rb[j][ks] = __ldg(wfw + (j * 16 + ks) * 32 + lane);

    for (int i = tid; i < 2 * HS_BUF; i += 512) h_buf[i] = 0u;
    __syncthreads();

    float c_reg[4] = {0.f, 0.f, 0.f, 0.f};
    const int row_pw = g + odd * 8;
    const int hh0    = w * 8 + (t >> 1);
    const __half* xr0 = xproj + (size_t)(b0 + g    ) * T_STEPS * G4;
    const __half* xr1 = xproj + (size_t)(b0 + g + 8) * T_STEPS * G4;
    const int colbase = w * 32 + 2 * t;

    const unsigned hb_smem = (unsigned)__cvta_generic_to_shared(h_buf);
    const unsigned lmoff   = hb_smem + (((lane & 15) * SH + (lane >> 4) * 4) << 2);

    __half2 p0[4], p1[4];
#pragma unroll
    for (int j = 0; j < 4; j++) {
        p0[j] = *(const __half2*)(xr0 + colbase + j * 8);
        p1[j] = *(const __half2*)(xr1 + colbase + j * 8);
    }

    int cur = 0;
    for (int ts = 0; ts < T_STEPS; ts++) {
        unsigned*      hnb = h_buf + (cur ^ 1) * HS_BUF;
        const unsigned abase = lmoff + (unsigned)(cur * HS_BUF * 4);
        float acc[4][4];
#pragma unroll
        for (int j = 0; j < 4; j++) {
            float2 f0 = __half22float2(p0[j]);
            float2 f1 = __half22float2(p1[j]);
            acc[j][0] = f0.x; acc[j][1] = f0.y;
            acc[j][2] = f1.x; acc[j][3] = f1.y;
        }
        {
            int tn = (ts + 1 < T_STEPS) ? ts + 1 : ts;
#pragma unroll
            for (int j = 0; j < 4; j++) {
                p0[j] = __ldg((const __half2*)(xr0 + (size_t)tn * G4 + colbase + j * 8));
                p1[j] = __ldg((const __half2*)(xr1 + (size_t)tn * G4 + colbase + j * 8));
            }
        }

        // register-resident ks 0..5
#pragma unroll
        for (int ks = 0; ks < 6; ks++) {
            unsigned a0, a1, a2, a3;
            ldsm4(a0, a1, a2, a3, abase + ks * 32u);
#pragma unroll
            for (int j = 0; j < 4; j++)
                mma8(acc[j], a0, a1, a2, a3, rb[j][ks].x, rb[j][ks].y);
        }
        // smem-resident ks 6..15, pair-packed
#pragma unroll
        for (int p = 0; p < 5; p++) {
            unsigned a0, a1, a2, a3, a4, a5, a6, a7;
            ldsm4(a0, a1, a2, a3, abase + (6 + 2 * p) * 32u);
            ldsm4(a4, a5, a6, a7, abase + (7 + 2 * p) * 32u);
#pragma unroll
            for (int j = 0; j < 4; j++) {
                uint4 b = swfw[(j * 5 + p) * 32 + lane];
                mma8(acc[j], a0, a1, a2, a3, b.x, b.y);
                mma8(acc[j], a4, a5, a6, a7, b.z, b.w);
            }
        }

#pragma unroll
        for (int j = 0; j < 4; j++) {
            float a0 = odd ? tanhf_(acc[j][0]) : sigmoidf_(acc[j][0]);
            float a1 = sigmoidf_(acc[j][1]);
            float a2 = odd ? tanhf_(acc[j][2]) : sigmoidf_(acc[j][2]);
            float a3 = sigmoidf_(acc[j][3]);
            float sv0 = odd ? a0 : a2;
            float sv1 = odd ? a1 : a3;
            float rv0 = __shfl_xor_sync(0xffffffffu, sv0, 1);
            float rv1 = __shfl_xor_sync(0xffffffffu, sv1, 1);
            float iG = odd ? rv0 : a0;
            float fG = odd ? rv1 : a1;
            float gG = odd ? a2  : rv0;
            float oG = odd ? a3  : rv1;
            float cn = fG * c_reg[j] + iG * gG;
            float hn = oG * tanhf_(cn);
            c_reg[j] = cn;
            int hh = hh0 + 2 * j;
            hnb[row_pw * SH + hh] = cvt_tf32(hn);
            if (hsout) hsout[((size_t)(b0 + row_pw) * T_STEPS + ts) * H + hh] = hn;
            if (hlast && ts == T_STEPS - 1) hlast[(size_t)(b0 + row_pw) * H + hh] = hn;
        }
        __syncthreads();
        cur ^= 1;
    }
}

// ---------------- launcher ----------------
extern "C" void kernel_launch(void* const* d_in, const int* in_sizes, int n_in,
                              void* d_out, int out_size)
{
    const float* x       = (const float*)d_in[0];
    const float* fc_w    = (const float*)d_in[1];
    const float* fc_b    = (const float*)d_in[2];
    const float* bn_g    = (const float*)d_in[3];
    const float* bn_b    = (const float*)d_in[4];
    const float* bn_mean = (const float*)d_in[5];
    const float* bn_var  = (const float*)d_in[6];
    const float* wih0    = (const float*)d_in[7];
    const float* whh0    = (const float*)d_in[8];
    const float* bih0    = (const float*)d_in[9];
    const float* bhh0    = (const float*)d_in[10];
    const float* wih1    = (const float*)d_in[11];
    const float* whh1    = (const float*)d_in[12];
    const float* bih1    = (const float*)d_in[13];
    const float* bhh1    = (const float*)d_in[14];
    float* out = (float*)d_out;

    const int B = in_sizes[0] / (F_IN * T_STEPS);
    const int M = B * T_STEPS;

    __half* p_xproj;
    float *p_hs, *p_biasp0, *p_biasp1, *p_wf0, *p_wf1, *p_wif0, *p_wif1;
    cudaGetSymbolAddress((void**)&p_xproj,  g_xproj);
    cudaGetSymbolAddress((void**)&p_hs,     g_hs);
    cudaGetSymbolAddress((void**)&p_biasp0, g_biasp0);
    cudaGetSymbolAddress((void**)&p_biasp1, g_biasp1);
    cudaGetSymbolAddress((void**)&p_wf0,    g_wf0);
    cudaGetSymbolAddress((void**)&p_wf1,    g_wf1);
    cudaGetSymbolAddress((void**)&p_wif0,   g_wif0);
    cudaGetSymbolAddress((void**)&p_wif1,   g_wif1);

    const size_t lstm_smem = (size_t)2 * HS_BUF * 4 + (size_t)16 * 640 * 16;   // ~177KB
    const size_t fuse_smem = (size_t)(4 * 128 * GST + 128 * HPST) * 4;         // ~108KB
    cudaFuncSetAttribute(lstm_tc, cudaFuncAttributeMaxDynamicSharedMemorySize, (int)lstm_smem);
    cudaFuncSetAttribute(fc_proj_fused, cudaFuncAttributeMaxDynamicSharedMemorySize, (int)fuse_smem);

    prep_kernel<<<256, 256>>>(wih0, bih0, bhh0, whh0, p_biasp0, p_wf0, p_wif0);
    prep_kernel<<<256, 256>>>(wih1, bih1, bhh1, whh1, p_biasp1, p_wf1, p_wif1);

    // fused FC+BN+LeakyReLU -> layer-0 projection (fp16 out)
    fc_proj_fused<<<M / 128, 256, fuse_smem>>>(x, fc_w, p_wif0, p_xproj,
                                               fc_b, bn_g, bn_b, bn_mean, bn_var, p_biasp0);
    // layer-0 LSTM
    lstm_tc<<<B / 16, 512, lstm_smem>>>(p_xproj, p_wf0, p_hs, nullptr);
    // layer-1 projection (fp16 out)
    gemm_tc1<<<dim3(M / 128, 4), 256>>>(p_hs, p_wif1, p_xproj, M, p_biasp1);
    // layer-1 LSTM -> final hidden state
    lstm_tc<<<B / 16, 512, lstm_smem>>>(p_xproj, p_wf1, nullptr, out);
}

// round 9
// speedup vs baseline: 3.8711x; 1.0294x over previous
#include <cuda_runtime.h>
#include <cuda_fp16.h>
#include <math.h>

#define T_STEPS 120
#define F_IN    180
#define H       128
#define G4      512
#define MAX_B   2048

// ---------------- static scratch ----------------
__device__ __half g_xproj[(size_t)MAX_B * T_STEPS * G4];   // fp16 projections (reused)
__device__ __half g_hs   [(size_t)MAX_B * T_STEPS * H];    // layer-0 hidden states (fp16)
__device__ float  g_biasp0[G4],  g_biasp1[G4];
__device__ float  g_wf0[G4 * H], g_wf1[G4 * H];
__device__ float  g_wif0[G4 * H], g_wif1[G4 * H];

// ---------------- helpers ----------------
__device__ __forceinline__ unsigned cvt_tf32(float f) {
    unsigned u; asm("cvt.rna.tf32.f32 %0, %1;" : "=r"(u) : "f"(f)); return u;
}
__device__ __forceinline__ void mma8(float* c, unsigned a0, unsigned a1, unsigned a2, unsigned a3,
                                     unsigned b0, unsigned b1) {
    asm volatile("mma.sync.aligned.m16n8k8.row.col.f32.tf32.tf32.f32 "
                 "{%0,%1,%2,%3}, {%4,%5,%6,%7}, {%8,%9}, {%0,%1,%2,%3};"
                 : "+f"(c[0]), "+f"(c[1]), "+f"(c[2]), "+f"(c[3])
                 : "r"(a0), "r"(a1), "r"(a2), "r"(a3), "r"(b0), "r"(b1));
}
__device__ __forceinline__ void ldsm4(unsigned& a0, unsigned& a1, unsigned& a2, unsigned& a3,
                                      unsigned addr) {
    asm volatile("ldmatrix.sync.aligned.m8n8.x4.shared.b16 {%0,%1,%2,%3}, [%4];"
                 : "=r"(a0), "=r"(a1), "=r"(a2), "=r"(a3) : "r"(addr));
}
__device__ __forceinline__ float sigmoidf_(float x) {
    return __fdividef(1.f, 1.f + __expf(-x));
}
__device__ __forceinline__ float tanhf_(float x) {
    return __fdividef(2.f, 1.f + __expf(-2.f * x)) - 1.f;
}

// ---------------- prep: combine bias, pack Whh and wih as B-fragments ----------------
__global__ void prep_kernel(const float* __restrict__ wih, const float* __restrict__ bih,
                            const float* __restrict__ bhh, const float* __restrict__ whh,
                            float* __restrict__ biasp, float* __restrict__ wf,
                            float* __restrict__ wif)
{
    int i = blockIdx.x * 256 + threadIdx.x;
    if (i < G4 * H) {
        int n = i >> 7, k = i & 127;
        if (k == 0) {
            int np = ((n & 127) << 2) | (n >> 7);
            biasp[np] = bih[n] + bhh[n];
        }
        int v = i & 1, lane = (i >> 1) & 31, ks = (i >> 6) & 15, nt = i >> 10;
        int npf = nt * 8 + (lane >> 2);
        int kk  = ks * 8 + (lane & 3) + 4 * v;
        int orig = ((npf & 3) << 7) | (npf >> 2);
        wf [i] = __uint_as_float(cvt_tf32(whh[orig * H + kk]));
        wif[i] = __uint_as_float(cvt_tf32(wih[orig * H + kk]));
    }
}

#define GST  20
#define HPST 132

// ---------------- fused FC+BN+LeakyReLU -> layer-0 projection ----------------
__global__ void __launch_bounds__(256)
fc_proj_fused(const float* __restrict__ x, const float* __restrict__ W,
              const float* __restrict__ Wf, __half* __restrict__ C,
              const float* __restrict__ fcb, const float* __restrict__ bng,
              const float* __restrict__ bnb, const float* __restrict__ bnm,
              const float* __restrict__ bnv, const float* __restrict__ biasp)
{
    extern __shared__ float fsm[];
    float*    As = fsm;                                // [2][128*GST]
    float*    Bs = fsm + 2 * 128 * GST;                // [2][128*GST]
    unsigned* hp = (unsigned*)(fsm + 4 * 128 * GST);   // [128][HPST]
    __shared__ int rowbase[128];

    const int tid  = threadIdx.x;
    const int lane = tid & 31, warp = tid >> 5;
    const int g = lane >> 2, t = lane & 3;
    const int wm = warp & 3, wn = warp >> 2;
    const int m0 = blockIdx.x * 128;

    if (tid < 128) {
        int m = m0 + tid; int b = m / T_STEPS;
        rowbase[tid] = b * (F_IN * T_STEPS) + (m - b * T_STEPS);
    }
    __syncthreads();

    const int r  = tid >> 1;
    const int hf = tid & 1;
    const int nc = (F_IN + 15) >> 4;   // 12

    float av[8], wv[8];
    auto LOAD = [&](int kc) {
#pragma unroll
        for (int i = 0; i < 8; i++) {
            int k = kc + hf * 8 + i;
            av[i] = (k < F_IN) ? __ldg(x + rowbase[r] + k * T_STEPS) : 0.f;
            wv[i] = (k < F_IN) ? __ldg(W + r * F_IN + k) : 0.f;
        }
    };
    auto STORE = [&](int s) {
#pragma unroll
        for (int i = 0; i < 8; i++) As[s * 128 * GST + r * GST + hf * 8 + i] = __uint_as_float(cvt_tf32(av[i]));
#pragma unroll
        for (int i = 0; i < 8; i++) Bs[s * 128 * GST + r * GST + hf * 8 + i] = __uint_as_float(cvt_tf32(wv[i]));
    };

    float acc[2][8][4];
#pragma unroll
    for (int mi = 0; mi < 2; mi++)
#pragma unroll
        for (int j = 0; j < 8; j++)
#pragma unroll
            for (int q = 0; q < 4; q++) acc[mi][j][q] = 0.f;

    LOAD(0); STORE(0); __syncthreads();

    for (int c = 0; c < nc; c++) {
        if (c + 1 < nc) LOAD((c + 1) * 16);
        const float* as = As + (c & 1) * 128 * GST;
        const float* bs = Bs + (c & 1) * 128 * GST;
#pragma unroll
        for (int kh = 0; kh < 2; kh++) {
            unsigned a[2][4];
#pragma unroll
            for (int mi = 0; mi < 2; mi++) {
                int row = wm * 32 + mi * 16;
                a[mi][0] = __float_as_uint(as[(row + g    ) * GST + kh * 8 + t]);
                a[mi][1] = __float_as_uint(as[(row + g + 8) * GST + kh * 8 + t]);
                a[mi][2] = __float_as_uint(as[(row + g    ) * GST + kh * 8 + t + 4]);
                a[mi][3] = __float_as_uint(as[(row + g + 8) * GST + kh * 8 + t + 4]);
            }
#pragma unroll
            for (int j = 0; j < 8; j++) {
                int col = wn * 64 + j * 8 + g;
                unsigned b0 = __float_as_uint(bs[col * GST + kh * 8 + t]);
                unsigned b1 = __float_as_uint(bs[col * GST + kh * 8 + t + 4]);
#pragma unroll
                for (int mi = 0; mi < 2; mi++)
                    mma8(acc[mi][j], a[mi][0], a[mi][1], a[mi][2], a[mi][3], b0, b1);
            }
        }
        if (c + 1 < nc) STORE((c + 1) & 1);
        __syncthreads();
    }

    // phase-1 epilogue: BN + LeakyReLU -> tf32 bits into hp
#pragma unroll
    for (int j = 0; j < 8; j++) {
        int col = wn * 64 + j * 8 + 2 * t;
        float s0 = bng[col]     * rsqrtf(bnv[col]     + 1e-5f);
        float s1 = bng[col + 1] * rsqrtf(bnv[col + 1] + 1e-5f);
        float be0 = (fcb[col]     - bnm[col]    ) * s0 + bnb[col];
        float be1 = (fcb[col + 1] - bnm[col + 1]) * s1 + bnb[col + 1];
#pragma unroll
        for (int mi = 0; mi < 2; mi++) {
            int row = wm * 32 + mi * 16 + g;
            float v0 = acc[mi][j][0] * s0 + be0;
            float v1 = acc[mi][j][1] * s1 + be1;
            float v2 = acc[mi][j][2] * s0 + be0;
            float v3 = acc[mi][j][3] * s1 + be1;
            v0 = (v0 >= 0.f) ? v0 : 0.01f * v0;
            v1 = (v1 >= 0.f) ? v1 : 0.01f * v1;
            v2 = (v2 >= 0.f) ? v2 : 0.01f * v2;
            v3 = (v3 >= 0.f) ? v3 : 0.01f * v3;
            *(uint2*)&hp[(row    ) * HPST + col] = make_uint2(cvt_tf32(v0), cvt_tf32(v1));
            *(uint2*)&hp[(row + 8) * HPST + col] = make_uint2(cvt_tf32(v2), cvt_tf32(v3));
        }
    }
    __syncthreads();

    // phase 2: 4 n-chunks of 128 cols, K=128 from smem hp
    const uint2* wfrag = (const uint2*)Wf;
#pragma unroll 1
    for (int nch = 0; nch < 4; nch++) {
        float a2[2][8][4];
#pragma unroll
        for (int mi = 0; mi < 2; mi++)
#pragma unroll
            for (int j = 0; j < 8; j++)
#pragma unroll
                for (int q = 0; q < 4; q++) a2[mi][j][q] = 0.f;

        const int ntb = nch * 16 + wn * 8;
#pragma unroll 4
        for (int kh = 0; kh < 16; kh++) {
            unsigned a[2][4];
#pragma unroll
            for (int mi = 0; mi < 2; mi++) {
                int row = wm * 32 + mi * 16;
                a[mi][0] = hp[(row + g    ) * HPST + kh * 8 + t];
                a[mi][1] = hp[(row + g + 8) * HPST + kh * 8 + t];
                a[mi][2] = hp[(row + g    ) * HPST + kh * 8 + t + 4];
                a[mi][3] = hp[(row + g + 8) * HPST + kh * 8 + t + 4];
            }
#pragma unroll
            for (int j = 0; j < 8; j++) {
                uint2 b = __ldg(wfrag + ((size_t)(ntb + j) * 16 + kh) * 32 + lane);
#pragma unroll
                for (int mi = 0; mi < 2; mi++)
                    mma8(a2[mi][j], a[mi][0], a[mi][1], a[mi][2], a[mi][3], b.x, b.y);
            }
        }
#pragma unroll
        for (int j = 0; j < 8; j++) {
            int col = nch * 128 + wn * 64 + j * 8 + 2 * t;
            float be0 = __ldg(biasp + col);
            float be1 = __ldg(biasp + col + 1);
#pragma unroll
            for (int mi = 0; mi < 2; mi++) {
                int row = m0 + wm * 32 + mi * 16 + g;
                *(__half2*)(C + (size_t)row * G4 + col) =
                    __floats2half2_rn(a2[mi][j][0] + be0, a2[mi][j][1] + be1);
                *(__half2*)(C + (size_t)(row + 8) * G4 + col) =
                    __floats2half2_rn(a2[mi][j][2] + be0, a2[mi][j][3] + be1);
            }
        }
    }
}

// ---------------- tf32 GEMM for layer-1 projection (A = fp16 hs) ----------------
__global__ void __launch_bounds__(256)
gemm_tc1(const __half* __restrict__ A, const float* __restrict__ Wf, __half* __restrict__ C,
         int M, const float* __restrict__ q0)
{
    __shared__ float As[2][128 * GST];

    const int tid  = threadIdx.x;
    const int lane = tid & 31, warp = tid >> 5;
    const int g = lane >> 2, t = lane & 3;
    const int wm = warp & 3, wn = warp >> 2;
    const int m0 = blockIdx.x * 128, n0 = blockIdx.y * 128;
    const int r  = tid >> 1;
    const int hf = tid & 1;

    float av[8];
    auto LOAD = [&](int kc) {
        uint4 v = *(const uint4*)(A + (size_t)(m0 + r) * H + kc + hf * 8);
        const __half2* h2 = (const __half2*)&v;
#pragma unroll
        for (int i = 0; i < 4; i++) {
            float2 f = __half22float2(h2[i]);
            av[2 * i] = f.x; av[2 * i + 1] = f.y;
        }
    };
    auto STORE = [&](int s) {
        // fp16-sourced values already fit in tf32 mantissa; store directly
#pragma unroll
        for (int i = 0; i < 8; i++) As[s][r * GST + hf * 8 + i] = av[i];
    };

    float acc[2][8][4];
#pragma unroll
    for (int mi = 0; mi < 2; mi++)
#pragma unroll
        for (int j = 0; j < 8; j++)
#pragma unroll
            for (int q = 0; q < 4; q++) acc[mi][j][q] = 0.f;

    const uint2* wfrag = (const uint2*)Wf;
    const int nt_base = (n0 >> 3) + wn * 8;

    LOAD(0); STORE(0); __syncthreads();

    for (int c = 0; c < 8; c++) {
        if (c + 1 < 8) LOAD((c + 1) * 16);
        const float* as = As[c & 1];
#pragma unroll
        for (int kh = 0; kh < 2; kh++) {
            unsigned a[2][4];
#pragma unroll
            for (int mi = 0; mi < 2; mi++) {
                int row = wm * 32 + mi * 16;
                a[mi][0] = __float_as_uint(as[(row + g    ) * GST + kh * 8 + t]);
                a[mi][1] = __float_as_uint(as[(row + g + 8) * GST + kh * 8 + t]);
                a[mi][2] = __float_as_uint(as[(row + g    ) * GST + kh * 8 + t + 4]);
                a[mi][3] = __float_as_uint(as[(row + g + 8) * GST + kh * 8 + t + 4]);
            }
#pragma unroll
            for (int j = 0; j < 8; j++) {
                uint2 b = __ldg(wfrag + ((size_t)(nt_base + j) * 16 + c * 2 + kh) * 32 + lane);
#pragma unroll
                for (int mi = 0; mi < 2; mi++)
                    mma8(acc[mi][j], a[mi][0], a[mi][1], a[mi][2], a[mi][3], b.x, b.y);
            }
        }
        if (c + 1 < 8) STORE((c + 1) & 1);
        __syncthreads();
    }

    const int cm = m0 + wm * 32;
    const int cn = n0 + wn * 64;
#pragma unroll
    for (int j = 0; j < 8; j++) {
        int col = cn + j * 8 + 2 * t;
        float be0 = __ldg(q0 + col);
        float be1 = __ldg(q0 + col + 1);
#pragma unroll
        for (int mi = 0; mi < 2; mi++) {
            int row = cm + mi * 16 + g;
            *(__half2*)(C + (size_t)row * G4 + col) =
                __floats2half2_rn(acc[mi][j][0] + be0, acc[mi][j][1] + be1);
            *(__half2*)(C + (size_t)(row + 8) * G4 + col) =
                __floats2half2_rn(acc[mi][j][2] + be0, acc[mi][j][3] + be1);
        }
    }
}

// ---------------- persistent tf32 tensor-core LSTM ----------------
// 512 threads = 16 warps. h double-buffered in smem (1 barrier/step); hs written
// cooperatively/coalesced as fp16 AFTER the barrier (tf32 bits -> fp16 is exact).
#define SH     132
#define HS_BUF (16 * SH)

__global__ void __launch_bounds__(512)
lstm_tc(const __half* __restrict__ xproj, const float* __restrict__ wf,
        __half* __restrict__ hsout, float* __restrict__ hlast)
{
    extern __shared__ unsigned smx[];
    unsigned* h_buf = smx;                           // [2][16*SH]
    uint4*    swf   = (uint4*)(smx + 2 * HS_BUF);    // 16 warps x (4j x 5pairs x 32) uint4

    const int tid  = threadIdx.x, lane = tid & 31, w = tid >> 5;
    const int g = lane >> 2, t = lane & 3;
    const int odd = t & 1;
    const int b0 = blockIdx.x * 16;
    const uint2* wfw = (const uint2*)wf + (size_t)w * 2048;
    uint4* swfw = swf + (size_t)w * 640;

#pragma unroll
    for (int j = 0; j < 4; j++)
#pragma unroll
        for (int p = 0; p < 5; p++) {
            uint2 bA = __ldg(wfw + (j * 16 + 6 + 2 * p) * 32 + lane);
            uint2 bB = __ldg(wfw + (j * 16 + 7 + 2 * p) * 32 + lane);
            swfw[(j * 5 + p) * 32 + lane] = make_uint4(bA.x, bA.y, bB.x, bB.y);
        }

    uint2 rb[4][6];
#pragma unroll
    for (int j = 0; j < 4; j++)
#pragma unroll
        for (int ks = 0; ks < 6; ks++)
            rb[j][ks] = __ldg(wfw + (j * 16 + ks) * 32 + lane);

    for (int i = tid; i < 2 * HS_BUF; i += 512) h_buf[i] = 0u;
    __syncthreads();

    float c_reg[4] = {0.f, 0.f, 0.f, 0.f};
    const int row_pw = g + odd * 8;
    const int hh0    = w * 8 + (t >> 1);
    const __half* xr0 = xproj + (size_t)(b0 + g    ) * T_STEPS * G4;
    const __half* xr1 = xproj + (size_t)(b0 + g + 8) * T_STEPS * G4;
    const int colbase = w * 32 + 2 * t;

    const unsigned hb_smem = (unsigned)__cvta_generic_to_shared(h_buf);
    const unsigned lmoff   = hb_smem + (((lane & 15) * SH + (lane >> 4) * 4) << 2);

    // cooperative hs-writer indexing (coalesced __half2 stores)
    const int wr_r0 = tid >> 6;               // row for elem tid
    const int wr_c0 = (tid & 63) << 1;        // hcol for elem tid

    __half2 p0[4], p1[4];
#pragma unroll
    for (int j = 0; j < 4; j++) {
        p0[j] = *(const __half2*)(xr0 + colbase + j * 8);
        p1[j] = *(const __half2*)(xr1 + colbase + j * 8);
    }

    int cur = 0;
    for (int ts = 0; ts < T_STEPS; ts++) {
        unsigned*      hnb = h_buf + (cur ^ 1) * HS_BUF;
        const unsigned abase = lmoff + (unsigned)(cur * HS_BUF * 4);
        float acc[4][4];
#pragma unroll
        for (int j = 0; j < 4; j++) {
            float2 f0 = __half22float2(p0[j]);
            float2 f1 = __half22float2(p1[j]);
            acc[j][0] = f0.x; acc[j][1] = f0.y;
            acc[j][2] = f1.x; acc[j][3] = f1.y;
        }
        {
            int tn = (ts + 1 < T_STEPS) ? ts + 1 : ts;
#pragma unroll
            for (int j = 0; j < 4; j++) {
                p0[j] = __ldg((const __half2*)(xr0 + (size_t)tn * G4 + colbase + j * 8));
                p1[j] = __ldg((const __half2*)(xr1 + (size_t)tn * G4 + colbase + j * 8));
            }
        }

#pragma unroll
        for (int ks = 0; ks < 6; ks++) {
            unsigned a0, a1, a2, a3;
            ldsm4(a0, a1, a2, a3, abase + ks * 32u);
#pragma unroll
            for (int j = 0; j < 4; j++)
                mma8(acc[j], a0, a1, a2, a3, rb[j][ks].x, rb[j][ks].y);
        }
#pragma unroll
        for (int p = 0; p < 5; p++) {
            unsigned a0, a1, a2, a3, a4, a5, a6, a7;
            ldsm4(a0, a1, a2, a3, abase + (6 + 2 * p) * 32u);
            ldsm4(a4, a5, a6, a7, abase + (7 + 2 * p) * 32u);
#pragma unroll
            for (int j = 0; j < 4; j++) {
                uint4 b = swfw[(j * 5 + p) * 32 + lane];
                mma8(acc[j], a0, a1, a2, a3, b.x, b.y);
                mma8(acc[j], a4, a5, a6, a7, b.z, b.w);
            }
        }

#pragma unroll
        for (int j = 0; j < 4; j++) {
            float a0 = odd ? tanhf_(acc[j][0]) : sigmoidf_(acc[j][0]);
            float a1 = sigmoidf_(acc[j][1]);
            float a2 = odd ? tanhf_(acc[j][2]) : sigmoidf_(acc[j][2]);
            float a3 = sigmoidf_(acc[j][3]);
            float sv0 = odd ? a0 : a2;
            float sv1 = odd ? a1 : a3;
            float rv0 = __shfl_xor_sync(0xffffffffu, sv0, 1);
            float rv1 = __shfl_xor_sync(0xffffffffu, sv1, 1);
            float iG = odd ? rv0 : a0;
            float fG = odd ? rv1 : a1;
            float gG = odd ? a2  : rv0;
            float oG = odd ? a3  : rv1;
            float cn = fG * c_reg[j] + iG * gG;
            float hn = oG * tanhf_(cn);
            c_reg[j] = cn;
            int hh = hh0 + 2 * j;
            hnb[row_pw * SH + hh] = cvt_tf32(hn);
            if (hlast && ts == T_STEPS - 1) hlast[(size_t)(b0 + row_pw) * H + hh] = hn;
        }
        __syncthreads();   // h tile complete

        // coalesced fp16 hs write (tf32 bits -> fp16 is exact for |h|<1)
        if (hsout) {
#pragma unroll
            for (int q = 0; q < 2; q++) {
                int r = wr_r0 + q * 8;
                uint2 bits = *(const uint2*)&hnb[r * SH + wr_c0];
                *(__half2*)(hsout + ((size_t)(b0 + r) * T_STEPS + ts) * H + wr_c0) =
                    __floats2half2_rn(__uint_as_float(bits.x), __uint_as_float(bits.y));
            }
        }
        cur ^= 1;
    }
}

// ---------------- launcher ----------------
extern "C" void kernel_launch(void* const* d_in, const int* in_sizes, int n_in,
                              void* d_out, int out_size)
{
    const float* x       = (const float*)d_in[0];
    const float* fc_w    = (const float*)d_in[1];
    const float* fc_b    = (const float*)d_in[2];
    const float* bn_g    = (const float*)d_in[3];
    const float* bn_b    = (const float*)d_in[4];
    const float* bn_mean = (const float*)d_in[5];
    const float* bn_var  = (const float*)d_in[6];
    const float* wih0    = (const float*)d_in[7];
    const float* whh0    = (const float*)d_in[8];
    const float* bih0    = (const float*)d_in[9];
    const float* bhh0    = (const float*)d_in[10];
    const float* wih1    = (const float*)d_in[11];
    const float* whh1    = (const float*)d_in[12];
    const float* bih1    = (const float*)d_in[13];
    const float* bhh1    = (const float*)d_in[14];
    float* out = (float*)d_out;

    const int B = in_sizes[0] / (F_IN * T_STEPS);
    const int M = B * T_STEPS;

    __half *p_xproj, *p_hs;
    float *p_biasp0, *p_biasp1, *p_wf0, *p_wf1, *p_wif0, *p_wif1;
    cudaGetSymbolAddress((void**)&p_xproj,  g_xproj);
    cudaGetSymbolAddress((void**)&p_hs,     g_hs);
    cudaGetSymbolAddress((void**)&p_biasp0, g_biasp0);
    cudaGetSymbolAddress((void**)&p_biasp1, g_biasp1);
    cudaGetSymbolAddress((void**)&p_wf0,    g_wf0);
    cudaGetSymbolAddress((void**)&p_wf1,    g_wf1);
    cudaGetSymbolAddress((void**)&p_wif0,   g_wif0);
    cudaGetSymbolAddress((void**)&p_wif1,   g_wif1);

    const size_t lstm_smem = (size_t)2 * HS_BUF * 4 + (size_t)16 * 640 * 16;   // ~177KB
    const size_t fuse_smem = (size_t)(4 * 128 * GST + 128 * HPST) * 4;         // ~108KB
    cudaFuncSetAttribute(lstm_tc, cudaFuncAttributeMaxDynamicSharedMemorySize, (int)lstm_smem);
    cudaFuncSetAttribute(fc_proj_fused, cudaFuncAttributeMaxDynamicSharedMemorySize, (int)fuse_smem);

    prep_kernel<<<256, 256>>>(wih0, bih0, bhh0, whh0, p_biasp0, p_wf0, p_wif0);
    prep_kernel<<<256, 256>>>(wih1, bih1, bhh1, whh1, p_biasp1, p_wf1, p_wif1);

    // fused FC+BN+LeakyReLU -> layer-0 projection (fp16 out)
    fc_proj_fused<<<M / 128, 256, fuse_smem>>>(x, fc_w, p_wif0, p_xproj,
                                               fc_b, bn_g, bn_b, bn_mean, bn_var, p_biasp0);
    // layer-0 LSTM (fp16 hs out, coalesced)
    lstm_tc<<<B / 16, 512, lstm_smem>>>(p_xproj, p_wf0, p_hs, nullptr);
    // layer-1 projection (fp16 in/out)
    gemm_tc1<<<dim3(M / 128, 4), 256>>>(p_hs, p_wif1, p_xproj, M, p_biasp1);
    // layer-1 LSTM -> final hidden state (fp32 out)
    lstm_tc<<<B / 16, 512, lstm_smem>>>(p_xproj, p_wf1, nullptr, out);
}

// round 10
// speedup vs baseline: 4.0721x; 1.0519x over previous
#include <cuda_runtime.h>
#include <cuda_fp16.h>
#include <math.h>

#define T_STEPS 120
#define F_IN    180
#define H       128
#define G4      512
#define MAX_B   2048

// ---------------- static scratch ----------------
__device__ __half g_xproj[(size_t)MAX_B * T_STEPS * G4];   // fp16 projections (reused)
__device__ __half g_hs   [(size_t)MAX_B * T_STEPS * H];    // layer-0 hidden states (fp16)
__device__ float  g_biasp0[G4],  g_biasp1[G4];
__device__ __half g_wfh0[G4 * H], g_wfh1[G4 * H];          // Whh as fp16 m16n8k16 B-frags
__device__ float  g_wif0[G4 * H], g_wif1[G4 * H];          // wih as tf32 m16n8k8 B-frags

// ---------------- helpers ----------------
__device__ __forceinline__ unsigned cvt_tf32(float f) {
    unsigned u; asm("cvt.rna.tf32.f32 %0, %1;" : "=r"(u) : "f"(f)); return u;
}
__device__ __forceinline__ void mma8(float* c, unsigned a0, unsigned a1, unsigned a2, unsigned a3,
                                     unsigned b0, unsigned b1) {
    asm volatile("mma.sync.aligned.m16n8k8.row.col.f32.tf32.tf32.f32 "
                 "{%0,%1,%2,%3}, {%4,%5,%6,%7}, {%8,%9}, {%0,%1,%2,%3};"
                 : "+f"(c[0]), "+f"(c[1]), "+f"(c[2]), "+f"(c[3])
                 : "r"(a0), "r"(a1), "r"(a2), "r"(a3), "r"(b0), "r"(b1));
}
__device__ __forceinline__ void mma16h(float* c, unsigned a0, unsigned a1, unsigned a2, unsigned a3,
                                       unsigned b0, unsigned b1) {
    asm volatile("mma.sync.aligned.m16n8k16.row.col.f32.f16.f16.f32 "
                 "{%0,%1,%2,%3}, {%4,%5,%6,%7}, {%8,%9}, {%0,%1,%2,%3};"
                 : "+f"(c[0]), "+f"(c[1]), "+f"(c[2]), "+f"(c[3])
                 : "r"(a0), "r"(a1), "r"(a2), "r"(a3), "r"(b0), "r"(b1));
}
__device__ __forceinline__ void ldsm4(unsigned& a0, unsigned& a1, unsigned& a2, unsigned& a3,
                                      unsigned addr) {
    asm volatile("ldmatrix.sync.aligned.m8n8.x4.shared.b16 {%0,%1,%2,%3}, [%4];"
                 : "=r"(a0), "=r"(a1), "=r"(a2), "=r"(a3) : "r"(addr));
}
__device__ __forceinline__ float sigmoidf_(float x) {
    return __fdividef(1.f, 1.f + __expf(-x));
}
__device__ __forceinline__ float tanhf_(float x) {
    return __fdividef(2.f, 1.f + __expf(-2.f * x)) - 1.f;
}

// ---------------- prep: combine bias, pack wih (tf32 frags) + Whh (fp16 frags) ----------------
// Gate interleave: orig row n (gate=n>>7, hh=n&127) -> row' = hh*4 + gate.
// wif (tf32 m16n8k8): [nt][ks16][lane][v]: n' = nt*8+(lane>>2), k = ks*8+(lane&3)+4v
// wfh (fp16 m16n8k16): [w][j][p][lane][v2]: n' = w*32+j*8+(lane>>2),
//   ks = 2p+(v2>>2), k = ks*16 + (lane&3)*2 + (v2&1) + ((v2>>1)&1)*8
__global__ void prep_kernel(const float* __restrict__ wih, const float* __restrict__ bih,
                            const float* __restrict__ bhh, const float* __restrict__ whh,
                            float* __restrict__ biasp, __half* __restrict__ wfh,
                            float* __restrict__ wif)
{
    int i = blockIdx.x * 256 + threadIdx.x;
    if (i < G4 * H) {
        int n = i >> 7, k = i & 127;
        if (k == 0) {
            int np = ((n & 127) << 2) | (n >> 7);
            biasp[np] = bih[n] + bhh[n];
        }
        // wih tf32 frags
        {
            int v = i & 1, lane = (i >> 1) & 31, ks = (i >> 6) & 15, nt = i >> 10;
            int npf = nt * 8 + (lane >> 2);
            int kk  = ks * 8 + (lane & 3) + 4 * v;
            int orig = ((npf & 3) << 7) | (npf >> 2);
            wif[i] = __uint_as_float(cvt_tf32(wih[orig * H + kk]));
        }
        // Whh fp16 frags
        {
            int v2 = i & 7, lane = (i >> 3) & 31, p = (i >> 8) & 3, j = (i >> 10) & 3, w = i >> 12;
            int ks = 2 * p + (v2 >> 2);
            int kk = ks * 16 + (lane & 3) * 2 + (v2 & 1) + ((v2 >> 1) & 1) * 8;
            int np = w * 32 + j * 8 + (lane >> 2);
            int orig = ((np & 3) << 7) | (np >> 2);
            wfh[i] = __float2half_rn(whh[orig * H + kk]);
        }
    }
}

#define GST  20
#define HPST 132

// ---------------- fused FC+BN+LeakyReLU -> layer-0 projection ----------------
__global__ void __launch_bounds__(256)
fc_proj_fused(const float* __restrict__ x, const float* __restrict__ W,
              const float* __restrict__ Wf, __half* __restrict__ C,
              const float* __restrict__ fcb, const float* __restrict__ bng,
              const float* __restrict__ bnb, const float* __restrict__ bnm,
              const float* __restrict__ bnv, const float* __restrict__ biasp)
{
    extern __shared__ float fsm[];
    float*    As = fsm;                                // [2][128*GST]
    float*    Bs = fsm + 2 * 128 * GST;                // [2][128*GST]
    unsigned* hp = (unsigned*)(fsm + 4 * 128 * GST);   // [128][HPST]
    __shared__ int rowbase[128];

    const int tid  = threadIdx.x;
    const int lane = tid & 31, warp = tid >> 5;
    const int g = lane >> 2, t = lane & 3;
    const int wm = warp & 3, wn = warp >> 2;
    const int m0 = blockIdx.x * 128;

    if (tid < 128) {
        int m = m0 + tid; int b = m / T_STEPS;
        rowbase[tid] = b * (F_IN * T_STEPS) + (m - b * T_STEPS);
    }
    __syncthreads();

    const int r  = tid >> 1;
    const int hf = tid & 1;
    const int nc = (F_IN + 15) >> 4;   // 12

    float av[8], wv[8];
    auto LOAD = [&](int kc) {
#pragma unroll
        for (int i = 0; i < 8; i++) {
            int k = kc + hf * 8 + i;
            av[i] = (k < F_IN) ? __ldg(x + rowbase[r] + k * T_STEPS) : 0.f;
            wv[i] = (k < F_IN) ? __ldg(W + r * F_IN + k) : 0.f;
        }
    };
    auto STORE = [&](int s) {
#pragma unroll
        for (int i = 0; i < 8; i++) As[s * 128 * GST + r * GST + hf * 8 + i] = __uint_as_float(cvt_tf32(av[i]));
#pragma unroll
        for (int i = 0; i < 8; i++) Bs[s * 128 * GST + r * GST + hf * 8 + i] = __uint_as_float(cvt_tf32(wv[i]));
    };

    float acc[2][8][4];
#pragma unroll
    for (int mi = 0; mi < 2; mi++)
#pragma unroll
        for (int j = 0; j < 8; j++)
#pragma unroll
            for (int q = 0; q < 4; q++) acc[mi][j][q] = 0.f;

    LOAD(0); STORE(0); __syncthreads();

    for (int c = 0; c < nc; c++) {
        if (c + 1 < nc) LOAD((c + 1) * 16);
        const float* as = As + (c & 1) * 128 * GST;
        const float* bs = Bs + (c & 1) * 128 * GST;
#pragma unroll
        for (int kh = 0; kh < 2; kh++) {
            unsigned a[2][4];
#pragma unroll
            for (int mi = 0; mi < 2; mi++) {
                int row = wm * 32 + mi * 16;
                a[mi][0] = __float_as_uint(as[(row + g    ) * GST + kh * 8 + t]);
                a[mi][1] = __float_as_uint(as[(row + g + 8) * GST + kh * 8 + t]);
                a[mi][2] = __float_as_uint(as[(row + g    ) * GST + kh * 8 + t + 4]);
                a[mi][3] = __float_as_uint(as[(row + g + 8) * GST + kh * 8 + t + 4]);
            }
#pragma unroll
            for (int j = 0; j < 8; j++) {
                int col = wn * 64 + j * 8 + g;
                unsigned b0 = __float_as_uint(bs[col * GST + kh * 8 + t]);
                unsigned b1 = __float_as_uint(bs[col * GST + kh * 8 + t + 4]);
#pragma unroll
                for (int mi = 0; mi < 2; mi++)
                    mma8(acc[mi][j], a[mi][0], a[mi][1], a[mi][2], a[mi][3], b0, b1);
            }
        }
        if (c + 1 < nc) STORE((c + 1) & 1);
        __syncthreads();
    }

    // phase-1 epilogue: BN + LeakyReLU -> tf32 bits into hp
#pragma unroll
    for (int j = 0; j < 8; j++) {
        int col = wn * 64 + j * 8 + 2 * t;
        float s0 = bng[col]     * rsqrtf(bnv[col]     + 1e-5f);
        float s1 = bng[col + 1] * rsqrtf(bnv[col + 1] + 1e-5f);
        float be0 = (fcb[col]     - bnm[col]    ) * s0 + bnb[col];
        float be1 = (fcb[col + 1] - bnm[col + 1]) * s1 + bnb[col + 1];
#pragma unroll
        for (int mi = 0; mi < 2; mi++) {
            int row = wm * 32 + mi * 16 + g;
            float v0 = acc[mi][j][0] * s0 + be0;
            float v1 = acc[mi][j][1] * s1 + be1;
            float v2 = acc[mi][j][2] * s0 + be0;
            float v3 = acc[mi][j][3] * s1 + be1;
            v0 = (v0 >= 0.f) ? v0 : 0.01f * v0;
            v1 = (v1 >= 0.f) ? v1 : 0.01f * v1;
            v2 = (v2 >= 0.f) ? v2 : 0.01f * v2;
            v3 = (v3 >= 0.f) ? v3 : 0.01f * v3;
            *(uint2*)&hp[(row    ) * HPST + col] = make_uint2(cvt_tf32(v0), cvt_tf32(v1));
            *(uint2*)&hp[(row + 8) * HPST + col] = make_uint2(cvt_tf32(v2), cvt_tf32(v3));
        }
    }
    __syncthreads();

    // phase 2: 4 n-chunks of 128 cols, K=128 from smem hp
    const uint2* wfrag = (const uint2*)Wf;
#pragma unroll 1
    for (int nch = 0; nch < 4; nch++) {
        float a2[2][8][4];
#pragma unroll
        for (int mi = 0; mi < 2; mi++)
#pragma unroll
            for (int j = 0; j < 8; j++)
#pragma unroll
                for (int q = 0; q < 4; q++) a2[mi][j][q] = 0.f;

        const int ntb = nch * 16 + wn * 8;
#pragma unroll 4
        for (int kh = 0; kh < 16; kh++) {
            unsigned a[2][4];
#pragma unroll
            for (int mi = 0; mi < 2; mi++) {
                int row = wm * 32 + mi * 16;
                a[mi][0] = hp[(row + g    ) * HPST + kh * 8 + t];
                a[mi][1] = hp[(row + g + 8) * HPST + kh * 8 + t];
                a[mi][2] = hp[(row + g    ) * HPST + kh * 8 + t + 4];
                a[mi][3] = hp[(row + g + 8) * HPST + kh * 8 + t + 4];
            }
#pragma unroll
            for (int j = 0; j < 8; j++) {
                uint2 b = __ldg(wfrag + ((size_t)(ntb + j) * 16 + kh) * 32 + lane);
#pragma unroll
                for (int mi = 0; mi < 2; mi++)
                    mma8(a2[mi][j], a[mi][0], a[mi][1], a[mi][2], a[mi][3], b.x, b.y);
            }
        }
#pragma unroll
        for (int j = 0; j < 8; j++) {
            int col = nch * 128 + wn * 64 + j * 8 + 2 * t;
            float be0 = __ldg(biasp + col);
            float be1 = __ldg(biasp + col + 1);
#pragma unroll
            for (int mi = 0; mi < 2; mi++) {
                int row = m0 + wm * 32 + mi * 16 + g;
                *(__half2*)(C + (size_t)row * G4 + col) =
                    __floats2half2_rn(a2[mi][j][0] + be0, a2[mi][j][1] + be1);
                *(__half2*)(C + (size_t)(row + 8) * G4 + col) =
                    __floats2half2_rn(a2[mi][j][2] + be0, a2[mi][j][3] + be1);
            }
        }
    }
}

// ---------------- tf32 GEMM for layer-1 projection (A = fp16 hs) ----------------
__global__ void __launch_bounds__(256)
gemm_tc1(const __half* __restrict__ A, const float* __restrict__ Wf, __half* __restrict__ C,
         int M, const float* __restrict__ q0)
{
    __shared__ float As[2][128 * GST];

    const int tid  = threadIdx.x;
    const int lane = tid & 31, warp = tid >> 5;
    const int g = lane >> 2, t = lane & 3;
    const int wm = warp & 3, wn = warp >> 2;
    const int m0 = blockIdx.x * 128, n0 = blockIdx.y * 128;
    const int r  = tid >> 1;
    const int hf = tid & 1;

    float av[8];
    auto LOAD = [&](int kc) {
        uint4 v = *(const uint4*)(A + (size_t)(m0 + r) * H + kc + hf * 8);
        const __half2* h2 = (const __half2*)&v;
#pragma unroll
        for (int i = 0; i < 4; i++) {
            float2 f = __half22float2(h2[i]);
            av[2 * i] = f.x; av[2 * i + 1] = f.y;
        }
    };
    auto STORE = [&](int s) {
#pragma unroll
        for (int i = 0; i < 8; i++) As[s][r * GST + hf * 8 + i] = av[i];
    };

    float acc[2][8][4];
#pragma unroll
    for (int mi = 0; mi < 2; mi++)
#pragma unroll
        for (int j = 0; j < 8; j++)
#pragma unroll
            for (int q = 0; q < 4; q++) acc[mi][j][q] = 0.f;

    const uint2* wfrag = (const uint2*)Wf;
    const int nt_base = (n0 >> 3) + wn * 8;

    LOAD(0); STORE(0); __syncthreads();

    for (int c = 0; c < 8; c++) {
        if (c + 1 < 8) LOAD((c + 1) * 16);
        const float* as = As[c & 1];
#pragma unroll
        for (int kh = 0; kh < 2; kh++) {
            unsigned a[2][4];
#pragma unroll
            for (int mi = 0; mi < 2; mi++) {
                int row = wm * 32 + mi * 16;
                a[mi][0] = __float_as_uint(as[(row + g    ) * GST + kh * 8 + t]);
                a[mi][1] = __float_as_uint(as[(row + g + 8) * GST + kh * 8 + t]);
                a[mi][2] = __float_as_uint(as[(row + g    ) * GST + kh * 8 + t + 4]);
                a[mi][3] = __float_as_uint(as[(row + g + 8) * GST + kh * 8 + t + 4]);
            }
#pragma unroll
            for (int j = 0; j < 8; j++) {
                uint2 b = __ldg(wfrag + ((size_t)(nt_base + j) * 16 + c * 2 + kh) * 32 + lane);
#pragma unroll
                for (int mi = 0; mi < 2; mi++)
                    mma8(acc[mi][j], a[mi][0], a[mi][1], a[mi][2], a[mi][3], b.x, b.y);
            }
        }
        if (c + 1 < 8) STORE((c + 1) & 1);
        __syncthreads();
    }

    const int cm = m0 + wm * 32;
    const int cn = n0 + wn * 64;
#pragma unroll
    for (int j = 0; j < 8; j++) {
        int col = cn + j * 8 + 2 * t;
        float be0 = __ldg(q0 + col);
        float be1 = __ldg(q0 + col + 1);
#pragma unroll
        for (int mi = 0; mi < 2; mi++) {
            int row = cm + mi * 16 + g;
            *(__half2*)(C + (size_t)row * G4 + col) =
                __floats2half2_rn(acc[mi][j][0] + be0, acc[mi][j][1] + be1);
            *(__half2*)(C + (size_t)(row + 8) * G4 + col) =
                __floats2half2_rn(acc[mi][j][2] + be0, acc[mi][j][3] + be1);
        }
    }
}

// ---------------- persistent fp16 tensor-core LSTM ----------------
// 512 threads = 16 warps; recurrence via mma.m16n8k16.f16 (fp32 accum).
// h stored fp16 in smem (double-buffered, ldmatrix-native); Whh fp16 frags all in smem.
// C-fragment layout identical to tf32 path -> gate epilogue unchanged.
#define SHh    136                 // h row stride in halfs (272B: conflict-free ldsm)
#define HBUF_B (16 * SHh * 2)      // one h buffer, bytes (4352)

__global__ void __launch_bounds__(512)
lstm_tc(const __half* __restrict__ xproj, const __half* __restrict__ wfh,
        __half* __restrict__ hsout, float* __restrict__ hlast)
{
    extern __shared__ unsigned smx[];
    __half* h_buf = (__half*)smx;                        // [2][16*SHh] halfs (8704B)
    uint4*  swf   = (uint4*)((char*)smx + 2 * HBUF_B);   // 16 warps x 512 uint4 (128KB)

    const int tid  = threadIdx.x, lane = tid & 31, w = tid >> 5;
    const int g = lane >> 2, t = lane & 3;
    const int odd = t & 1;
    const int b0 = blockIdx.x * 16;
    uint4* swfw = swf + (size_t)w * 512;

    // stage all Whh fp16 frags into smem (one-time, coalesced)
    {
        const uint4* src = (const uint4*)wfh + (size_t)w * 512;
        for (int idx = lane; idx < 512; idx += 32)
            swfw[idx] = __ldg(src + idx);
    }

    for (int i = tid; i < (2 * HBUF_B) / 4; i += 512) smx[i] = 0u;
    __syncthreads();

    float c_reg[4] = {0.f, 0.f, 0.f, 0.f};
    const int row_pw = g + odd * 8;
    const int hh0    = w * 8 + (t >> 1);
    const __half* xr0 = xproj + (size_t)(b0 + g    ) * T_STEPS * G4;
    const __half* xr1 = xproj + (size_t)(b0 + g + 8) * T_STEPS * G4;
    const int colbase = w * 32 + 2 * t;

    const unsigned hb_smem = (unsigned)__cvta_generic_to_shared(h_buf);
    // ldmatrix b16 x4: row = lane&15, col-half (+8 halfs = 16B) = lane>>4
    const unsigned lmoff = hb_smem + (unsigned)((lane & 15) * SHh * 2 + (lane >> 4) * 16);

    // cooperative hs-writer indexing (coalesced 4B stores of half2)
    const int wr_r0 = tid >> 6;               // 0..7
    const int wr_c0 = (tid & 63) << 1;        // half col (even)

    __half2 p0[4], p1[4];
#pragma unroll
    for (int j = 0; j < 4; j++) {
        p0[j] = *(const __half2*)(xr0 + colbase + j * 8);
        p1[j] = *(const __half2*)(xr1 + colbase + j * 8);
    }

    int cur = 0;
    for (int ts = 0; ts < T_STEPS; ts++) {
        __half*        hnb   = h_buf + (cur ^ 1) * (16 * SHh);
        const unsigned abase = lmoff + (unsigned)(cur * HBUF_B);
        float acc[4][4];
#pragma unroll
        for (int j = 0; j < 4; j++) {
            float2 f0 = __half22float2(p0[j]);
            float2 f1 = __half22float2(p1[j]);
            acc[j][0] = f0.x; acc[j][1] = f0.y;
            acc[j][2] = f1.x; acc[j][3] = f1.y;
        }
        {
            int tn = (ts + 1 < T_STEPS) ? ts + 1 : ts;
#pragma unroll
            for (int j = 0; j < 4; j++) {
                p0[j] = __ldg((const __half2*)(xr0 + (size_t)tn * G4 + colbase + j * 8));
                p1[j] = __ldg((const __half2*)(xr1 + (size_t)tn * G4 + colbase + j * 8));
            }
        }

        // recurrent matmul: 4 ks-pairs x 4 n-tiles of m16n8k16 fp16
#pragma unroll
        for (int p = 0; p < 4; p++) {
            unsigned e0, e1, e2, e3, o0, o1, o2, o3;
            ldsm4(e0, e1, e2, e3, abase + (2 * p    ) * 32u);   // ks = 2p   (16 halfs = 32B)
            ldsm4(o0, o1, o2, o3, abase + (2 * p + 1) * 32u);   // ks = 2p+1
#pragma unroll
            for (int j = 0; j < 4; j++) {
                uint4 b = swfw[(j * 4 + p) * 32 + lane];
                mma16h(acc[j], e0, e1, e2, e3, b.x, b.y);
                mma16h(acc[j], o0, o1, o2, o3, b.z, b.w);
            }
        }

        // activations + pair-exchange + state update
#pragma unroll
        for (int j = 0; j < 4; j++) {
            float a0 = odd ? tanhf_(acc[j][0]) : sigmoidf_(acc[j][0]);
            float a1 = sigmoidf_(acc[j][1]);
            float a2 = odd ? tanhf_(acc[j][2]) : sigmoidf_(acc[j][2]);
            float a3 = sigmoidf_(acc[j][3]);
            float sv0 = odd ? a0 : a2;
            float sv1 = odd ? a1 : a3;
            float rv0 = __shfl_xor_sync(0xffffffffu, sv0, 1);
            float rv1 = __shfl_xor_sync(0xffffffffu, sv1, 1);
            float iG = odd ? rv0 : a0;
            float fG = odd ? rv1 : a1;
            float gG = odd ? a2  : rv0;
            float oG = odd ? a3  : rv1;
            float cn = fG * c_reg[j] + iG * gG;
            float hn = oG * tanhf_(cn);
            c_reg[j] = cn;
            int hh = hh0 + 2 * j;
            hnb[row_pw * SHh + hh] = __float2half_rn(hn);
            if (hlast && ts == T_STEPS - 1) hlast[(size_t)(b0 + row_pw) * H + hh] = hn;
        }
        __syncthreads();   // h tile complete

        // coalesced fp16 hs write (direct bit copy)
        if (hsout) {
#pragma unroll
            for (int q = 0; q < 2; q++) {
                int r = wr_r0 + q * 8;
                unsigned bits = *(const unsigned*)&hnb[r * SHh + wr_c0];
                *(unsigned*)(hsout + ((size_t)(b0 + r) * T_STEPS + ts) * H + wr_c0) = bits;
            }
        }
        cur ^= 1;
    }
}

// ---------------- launcher ----------------
extern "C" void kernel_launch(void* const* d_in, const int* in_sizes, int n_in,
                              void* d_out, int out_size)
{
    const float* x       = (const float*)d_in[0];
    const float* fc_w    = (const float*)d_in[1];
    const float* fc_b    = (const float*)d_in[2];
    const float* bn_g    = (const float*)d_in[3];
    const float* bn_b    = (const float*)d_in[4];
    const float* bn_mean = (const float*)d_in[5];
    const float* bn_var  = (const float*)d_in[6];
    const float* wih0    = (const float*)d_in[7];
    const float* whh0    = (const float*)d_in[8];
    const float* bih0    = (const float*)d_in[9];
    const float* bhh0    = (const float*)d_in[10];
    const float* wih1    = (const float*)d_in[11];
    const float* whh1    = (const float*)d_in[12];
    const float* bih1    = (const float*)d_in[13];
    const float* bhh1    = (const float*)d_in[14];
    float* out = (float*)d_out;

    const int B = in_sizes[0] / (F_IN * T_STEPS);
    const int M = B * T_STEPS;

    __half *p_xproj, *p_hs, *p_wfh0, *p_wfh1;
    float *p_biasp0, *p_biasp1, *p_wif0, *p_wif1;
    cudaGetSymbolAddress((void**)&p_xproj,  g_xproj);
    cudaGetSymbolAddress((void**)&p_hs,     g_hs);
    cudaGetSymbolAddress((void**)&p_biasp0, g_biasp0);
    cudaGetSymbolAddress((void**)&p_biasp1, g_biasp1);
    cudaGetSymbolAddress((void**)&p_wfh0,   g_wfh0);
    cudaGetSymbolAddress((void**)&p_wfh1,   g_wfh1);
    cudaGetSymbolAddress((void**)&p_wif0,   g_wif0);
    cudaGetSymbolAddress((void**)&p_wif1,   g_wif1);

    const size_t lstm_smem = (size_t)2 * (16 * SHh * 2) + (size_t)16 * 512 * 16;  // 8704 + 128KB
    const size_t fuse_smem = (size_t)(4 * 128 * GST + 128 * HPST) * 4;            // ~108KB
    cudaFuncSetAttribute(lstm_tc, cudaFuncAttributeMaxDynamicSharedMemorySize, (int)lstm_smem);
    cudaFuncSetAttribute(fc_proj_fused, cudaFuncAttributeMaxDynamicSharedMemorySize, (int)fuse_smem);

    prep_kernel<<<256, 256>>>(wih0, bih0, bhh0, whh0, p_biasp0, p_wfh0, p_wif0);
    prep_kernel<<<256, 256>>>(wih1, bih1, bhh1, whh1, p_biasp1, p_wfh1, p_wif1);

    // fused FC+BN+LeakyReLU -> layer-0 projection (fp16 out)
    fc_proj_fused<<<M / 128, 256, fuse_smem>>>(x, fc_w, p_wif0, p_xproj,
                                               fc_b, bn_g, bn_b, bn_mean, bn_var, p_biasp0);
    // layer-0 LSTM (fp16 recurrence, fp16 hs out)
    lstm_tc<<<B / 16, 512, lstm_smem>>>(p_xproj, p_wfh0, p_hs, nullptr);
    // layer-1 projection (fp16 in/out)
    gemm_tc1<<<dim3(M / 128, 4), 256>>>(p_hs, p_wif1, p_xproj, M, p_biasp1);
    // layer-1 LSTM -> final hidden state (fp32 out)
    lstm_tc<<<B / 16, 512, lstm_smem>>>(p_xproj, p_wfh1, nullptr, out);
}

// round 11
// speedup vs baseline: 4.8005x; 1.1789x over previous
#include <cuda_runtime.h>
#include <cuda_fp16.h>
#include <math.h>

#define T_STEPS 120
#define F_IN    180
#define H       128
#define G4      512
#define MAX_B   2048

// ---------------- static scratch ----------------
__device__ __half g_xproj[(size_t)MAX_B * T_STEPS * G4];   // fp16 projections (reused)
__device__ __half g_hs   [(size_t)MAX_B * T_STEPS * H];    // layer-0 hidden states (fp16)
__device__ float  g_biasp0[G4],  g_biasp1[G4];
__device__ __align__(16) __half g_wfh0[G4 * H], g_wfh1[G4 * H];   // Whh fp16 m16n8k16 B-frags
__device__ __align__(16) __half g_wifh0[G4 * H], g_wifh1[G4 * H]; // wih fp16 m16n8k16 B-frags

// ---------------- helpers ----------------
__device__ __forceinline__ void mma16h(float* c, unsigned a0, unsigned a1, unsigned a2, unsigned a3,
                                       unsigned b0, unsigned b1) {
    asm volatile("mma.sync.aligned.m16n8k16.row.col.f32.f16.f16.f32 "
                 "{%0,%1,%2,%3}, {%4,%5,%6,%7}, {%8,%9}, {%0,%1,%2,%3};"
                 : "+f"(c[0]), "+f"(c[1]), "+f"(c[2]), "+f"(c[3])
                 : "r"(a0), "r"(a1), "r"(a2), "r"(a3), "r"(b0), "r"(b1));
}
__device__ __forceinline__ void ldsm4(unsigned& a0, unsigned& a1, unsigned& a2, unsigned& a3,
                                      unsigned addr) {
    asm volatile("ldmatrix.sync.aligned.m8n8.x4.shared.b16 {%0,%1,%2,%3}, [%4];"
                 : "=r"(a0), "=r"(a1), "=r"(a2), "=r"(a3) : "r"(addr));
}
__device__ __forceinline__ float sigmoidf_(float x) {
    return __fdividef(1.f, 1.f + __expf(-x));
}
__device__ __forceinline__ float tanhf_(float x) {
    return __fdividef(2.f, 1.f + __expf(-2.f * x)) - 1.f;
}

// ---------------- prep: combine bias; pack Whh AND wih as fp16 m16n8k16 B-frags ----------------
// Gate interleave: orig row n (gate=n>>7, hh=n&127) -> row' = hh*4 + gate.
// frag layout (uint4-pair form): idx i: v2=i&7, lane=(i>>3)&31, p=(i>>8)&3, j=(i>>10)&3, w=i>>12
//   nt = w*4+j; n' = nt*8+(lane>>2); ks = 2p+(v2>>2); k = ks*16+(lane&3)*2+(v2&1)+((v2>>1)&1)*8
__global__ void prep_kernel(const float* __restrict__ wih, const float* __restrict__ bih,
                            const float* __restrict__ bhh, const float* __restrict__ whh,
                            float* __restrict__ biasp, __half* __restrict__ wfh,
                            __half* __restrict__ wifh)
{
    int i = blockIdx.x * 256 + threadIdx.x;
    if (i < G4 * H) {
        int n = i >> 7, k = i & 127;
        if (k == 0) {
            int np = ((n & 127) << 2) | (n >> 7);
            biasp[np] = bih[n] + bhh[n];
        }
        int v2 = i & 7, lane = (i >> 3) & 31, p = (i >> 8) & 3, j = (i >> 10) & 3, w = i >> 12;
        int ks = 2 * p + (v2 >> 2);
        int kk = ks * 16 + (lane & 3) * 2 + (v2 & 1) + ((v2 >> 1) & 1) * 8;
        int np = w * 32 + j * 8 + (lane >> 2);
        int orig = ((np & 3) << 7) | (np >> 2);
        wfh [i] = __float2half_rn(whh[orig * H + kk]);
        wifh[i] = __float2half_rn(wih[orig * H + kk]);
    }
}

#define SA  40    // phase-1 tile row stride (halfs), k32 chunks, conflict-free
#define S2  136   // 128-half row stride (halfs), conflict-free for ldsm

// ---------------- fused FC+BN+LeakyReLU -> layer-0 projection (all fp16 mma) ----------------
__global__ void __launch_bounds__(256)
fc_proj_fused(const float* __restrict__ x, const float* __restrict__ W,
              const __half* __restrict__ Wf, __half* __restrict__ C,
              const float* __restrict__ fcb, const float* __restrict__ bng,
              const float* __restrict__ bnb, const float* __restrict__ bnm,
              const float* __restrict__ bnv, const float* __restrict__ biasp)
{
    extern __shared__ __align__(16) char fsm[];
    __half* Ah = (__half*)fsm;              // [2][128*SA]
    __half* Bh = Ah + 2 * 128 * SA;         // [2][128*SA]
    __half* hp = Bh + 2 * 128 * SA;         // [128][S2]
    __shared__ int rowbase[128];

    const int tid  = threadIdx.x;
    const int lane = tid & 31, warp = tid >> 5;
    const int g = lane >> 2, t = lane & 3;
    const int wm = warp & 3, wn = warp >> 2;
    const int m0 = blockIdx.x * 128;

    if (tid < 128) {
        int m = m0 + tid; int b = m / T_STEPS;
        rowbase[tid] = b * (F_IN * T_STEPS) + (m - b * T_STEPS);
    }
    __syncthreads();

    const int r  = tid >> 1;
    const int hf = tid & 1;
    const int nc = 6;    // ceil(180/32)

    __half2 av2[8], wv2[8];
    auto LOAD = [&](int kc) {
#pragma unroll
        for (int i = 0; i < 8; i++) {
            int k = kc + hf * 16 + 2 * i;
            float x0 = (k     < F_IN) ? __ldg(x + rowbase[r] + k * T_STEPS)       : 0.f;
            float x1 = (k + 1 < F_IN) ? __ldg(x + rowbase[r] + (k + 1) * T_STEPS) : 0.f;
            av2[i] = __floats2half2_rn(x0, x1);
            float w0 = (k     < F_IN) ? __ldg(W + r * F_IN + k)     : 0.f;
            float w1 = (k + 1 < F_IN) ? __ldg(W + r * F_IN + k + 1) : 0.f;
            wv2[i] = __floats2half2_rn(w0, w1);
        }
    };
    auto STORE = [&](int s) {
#pragma unroll
        for (int i = 0; i < 8; i++) {
            *(__half2*)&Ah[s * 128 * SA + r * SA + hf * 16 + 2 * i] = av2[i];
            *(__half2*)&Bh[s * 128 * SA + r * SA + hf * 16 + 2 * i] = wv2[i];
        }
    };

    float acc[2][8][4];
#pragma unroll
    for (int mi = 0; mi < 2; mi++)
#pragma unroll
        for (int j = 0; j < 8; j++)
#pragma unroll
            for (int q = 0; q < 4; q++) acc[mi][j][q] = 0.f;

    const unsigned ah_smem = (unsigned)__cvta_generic_to_shared(Ah);
    const unsigned lm_a    = ah_smem + (unsigned)((lane & 15) * SA * 2 + (lane >> 4) * 16);

    LOAD(0); STORE(0); __syncthreads();

    for (int c = 0; c < nc; c++) {
        if (c + 1 < nc) LOAD((c + 1) * 32);
        const unsigned abuf = lm_a + (unsigned)((c & 1) * 128 * SA * 2);
        const __half* bs = Bh + (c & 1) * 128 * SA;
#pragma unroll
        for (int kq = 0; kq < 2; kq++) {
            unsigned a[2][4];
#pragma unroll
            for (int mi = 0; mi < 2; mi++)
                ldsm4(a[mi][0], a[mi][1], a[mi][2], a[mi][3],
                      abuf + (unsigned)((wm * 32 + mi * 16) * SA * 2 + kq * 32));
#pragma unroll
            for (int j = 0; j < 8; j++) {
                int row = wn * 64 + j * 8 + g;
                unsigned b0 = *(const unsigned*)&bs[row * SA + kq * 16 + 2 * t];
                unsigned b1 = *(const unsigned*)&bs[row * SA + kq * 16 + 2 * t + 8];
#pragma unroll
                for (int mi = 0; mi < 2; mi++)
                    mma16h(acc[mi][j], a[mi][0], a[mi][1], a[mi][2], a[mi][3], b0, b1);
            }
        }
        if (c + 1 < nc) STORE((c + 1) & 1);
        __syncthreads();
    }

    // phase-1 epilogue: BN + LeakyReLU -> fp16 into hp
#pragma unroll
    for (int j = 0; j < 8; j++) {
        int col = wn * 64 + j * 8 + 2 * t;
        float s0 = bng[col]     * rsqrtf(bnv[col]     + 1e-5f);
        float s1 = bng[col + 1] * rsqrtf(bnv[col + 1] + 1e-5f);
        float be0 = (fcb[col]     - bnm[col]    ) * s0 + bnb[col];
        float be1 = (fcb[col + 1] - bnm[col + 1]) * s1 + bnb[col + 1];
#pragma unroll
        for (int mi = 0; mi < 2; mi++) {
            int row = wm * 32 + mi * 16 + g;
            float v0 = acc[mi][j][0] * s0 + be0;
            float v1 = acc[mi][j][1] * s1 + be1;
            float v2 = acc[mi][j][2] * s0 + be0;
            float v3 = acc[mi][j][3] * s1 + be1;
            v0 = (v0 >= 0.f) ? v0 : 0.01f * v0;
            v1 = (v1 >= 0.f) ? v1 : 0.01f * v1;
            v2 = (v2 >= 0.f) ? v2 : 0.01f * v2;
            v3 = (v3 >= 0.f) ? v3 : 0.01f * v3;
            *(__half2*)&hp[(row    ) * S2 + col] = __floats2half2_rn(v0, v1);
            *(__half2*)&hp[(row + 8) * S2 + col] = __floats2half2_rn(v2, v3);
        }
    }
    __syncthreads();

    // phase 2: xproj = hp @ wih^T + biasp, fp16 mma, K=128
    const uint4* wf4 = (const uint4*)Wf;
    const unsigned hp_smem = (unsigned)__cvta_generic_to_shared(hp);
    const unsigned lm_h    = hp_smem + (unsigned)((lane & 15) * S2 * 2 + (lane >> 4) * 16);
#pragma unroll 1
    for (int nch = 0; nch < 4; nch++) {
        float a2[2][8][4];
#pragma unroll
        for (int mi = 0; mi < 2; mi++)
#pragma unroll
            for (int j = 0; j < 8; j++)
#pragma unroll
                for (int q = 0; q < 4; q++) a2[mi][j][q] = 0.f;

#pragma unroll
        for (int p = 0; p < 4; p++) {
            unsigned e[2][4], o[2][4];
#pragma unroll
            for (int mi = 0; mi < 2; mi++) {
                unsigned rbase = lm_h + (unsigned)((wm * 32 + mi * 16) * S2 * 2);
                ldsm4(e[mi][0], e[mi][1], e[mi][2], e[mi][3], rbase + (2 * p    ) * 32u);
                ldsm4(o[mi][0], o[mi][1], o[mi][2], o[mi][3], rbase + (2 * p + 1) * 32u);
            }
#pragma unroll
            for (int j = 0; j < 8; j++) {
                int nt = nch * 16 + wn * 8 + j;
                uint4 b = __ldg(wf4 + ((size_t)nt * 4 + p) * 32 + lane);
#pragma unroll
                for (int mi = 0; mi < 2; mi++) {
                    mma16h(a2[mi][j], e[mi][0], e[mi][1], e[mi][2], e[mi][3], b.x, b.y);
                    mma16h(a2[mi][j], o[mi][0], o[mi][1], o[mi][2], o[mi][3], b.z, b.w);
                }
            }
        }
#pragma unroll
        for (int j = 0; j < 8; j++) {
            int col = nch * 128 + wn * 64 + j * 8 + 2 * t;
            float be0 = __ldg(biasp + col);
            float be1 = __ldg(biasp + col + 1);
#pragma unroll
            for (int mi = 0; mi < 2; mi++) {
                int row = m0 + wm * 32 + mi * 16 + g;
                *(__half2*)(C + (size_t)row * G4 + col) =
                    __floats2half2_rn(a2[mi][j][0] + be0, a2[mi][j][1] + be1);
                *(__half2*)(C + (size_t)(row + 8) * G4 + col) =
                    __floats2half2_rn(a2[mi][j][2] + be0, a2[mi][j][3] + be1);
            }
        }
    }
}

// ---------------- fp16 GEMM for layer-1 projection (A = fp16 hs, single-staged tile) ----------
__global__ void __launch_bounds__(256)
gemm_tc1(const __half* __restrict__ A, const __half* __restrict__ Wf, __half* __restrict__ C,
         int M, const float* __restrict__ q0)
{
    __shared__ __align__(16) __half Ah[128 * S2];

    const int tid  = threadIdx.x;
    const int lane = tid & 31, warp = tid >> 5;
    const int g = lane >> 2, t = lane & 3;
    const int wm = warp & 3, wn = warp >> 2;
    const int m0 = blockIdx.x * 128, n0 = blockIdx.y * 128;

    // stage A tile (bit copy, coalesced uint4)
#pragma unroll
    for (int it = 0; it < 8; it++) {
        int linear = tid + it * 256;
        int row = linear >> 4, seg = linear & 15;
        *(uint4*)&Ah[row * S2 + seg * 8] =
            *(const uint4*)(A + (size_t)(m0 + row) * H + seg * 8);
    }
    __syncthreads();

    float acc[2][8][4];
#pragma unroll
    for (int mi = 0; mi < 2; mi++)
#pragma unroll
        for (int j = 0; j < 8; j++)
#pragma unroll
            for (int q = 0; q < 4; q++) acc[mi][j][q] = 0.f;

    const uint4* wf4 = (const uint4*)Wf;
    const unsigned ah_smem = (unsigned)__cvta_generic_to_shared(Ah);
    const unsigned lm_a    = ah_smem + (unsigned)((lane & 15) * S2 * 2 + (lane >> 4) * 16);
    const int nt_base = (n0 >> 3) + wn * 8;

#pragma unroll
    for (int p = 0; p < 4; p++) {
        unsigned e[2][4], o[2][4];
#pragma unroll
        for (int mi = 0; mi < 2; mi++) {
            unsigned rbase = lm_a + (unsigned)((wm * 32 + mi * 16) * S2 * 2);
            ldsm4(e[mi][0], e[mi][1], e[mi][2], e[mi][3], rbase + (2 * p    ) * 32u);
            ldsm4(o[mi][0], o[mi][1], o[mi][2], o[mi][3], rbase + (2 * p + 1) * 32u);
        }
#pragma unroll
        for (int j = 0; j < 8; j++) {
            uint4 b = __ldg(wf4 + ((size_t)(nt_base + j) * 4 + p) * 32 + lane);
#pragma unroll
            for (int mi = 0; mi < 2; mi++) {
                mma16h(acc[mi][j], e[mi][0], e[mi][1], e[mi][2], e[mi][3], b.x, b.y);
                mma16h(acc[mi][j], o[mi][0], o[mi][1], o[mi][2], o[mi][3], b.z, b.w);
            }
        }
    }

    const int cm = m0 + wm * 32;
    const int cn = n0 + wn * 64;
#pragma unroll
    for (int j = 0; j < 8; j++) {
        int col = cn + j * 8 + 2 * t;
        float be0 = __ldg(q0 + col);
        float be1 = __ldg(q0 + col + 1);
#pragma unroll
        for (int mi = 0; mi < 2; mi++) {
            int row = cm + mi * 16 + g;
            *(__half2*)(C + (size_t)row * G4 + col) =
                __floats2half2_rn(acc[mi][j][0] + be0, acc[mi][j][1] + be1);
            *(__half2*)(C + (size_t)(row + 8) * G4 + col) =
                __floats2half2_rn(acc[mi][j][2] + be0, acc[mi][j][3] + be1);
        }
    }
}

// ---------------- persistent fp16 tensor-core LSTM (unchanged from round 10) ----------------
#define SHh    136
#define HBUF_B (16 * SHh * 2)

__global__ void __launch_bounds__(512)
lstm_tc(const __half* __restrict__ xproj, const __half* __restrict__ wfh,
        __half* __restrict__ hsout, float* __restrict__ hlast)
{
    extern __shared__ unsigned smx[];
    __half* h_buf = (__half*)smx;
    uint4*  swf   = (uint4*)((char*)smx + 2 * HBUF_B);

    const int tid  = threadIdx.x, lane = tid & 31, w = tid >> 5;
    const int g = lane >> 2, t = lane & 3;
    const int odd = t & 1;
    const int b0 = blockIdx.x * 16;
    uint4* swfw = swf + (size_t)w * 512;

    {
        const uint4* src = (const uint4*)wfh + (size_t)w * 512;
        for (int idx = lane; idx < 512; idx += 32)
            swfw[idx] = __ldg(src + idx);
    }

    for (int i = tid; i < (2 * HBUF_B) / 4; i += 512) smx[i] = 0u;
    __syncthreads();

    float c_reg[4] = {0.f, 0.f, 0.f, 0.f};
    const int row_pw = g + odd * 8;
    const int hh0    = w * 8 + (t >> 1);
    const __half* xr0 = xproj + (size_t)(b0 + g    ) * T_STEPS * G4;
    const __half* xr1 = xproj + (size_t)(b0 + g + 8) * T_STEPS * G4;
    const int colbase = w * 32 + 2 * t;

    const unsigned hb_smem = (unsigned)__cvta_generic_to_shared(h_buf);
    const unsigned lmoff = hb_smem + (unsigned)((lane & 15) * SHh * 2 + (lane >> 4) * 16);

    const int wr_r0 = tid >> 6;
    const int wr_c0 = (tid & 63) << 1;

    __half2 p0[4], p1[4];
#pragma unroll
    for (int j = 0; j < 4; j++) {
        p0[j] = *(const __half2*)(xr0 + colbase + j * 8);
        p1[j] = *(const __half2*)(xr1 + colbase + j * 8);
    }

    int cur = 0;
    for (int ts = 0; ts < T_STEPS; ts++) {
        __half*        hnb   = h_buf + (cur ^ 1) * (16 * SHh);
        const unsigned abase = lmoff + (unsigned)(cur * HBUF_B);
        float acc[4][4];
#pragma unroll
        for (int j = 0; j < 4; j++) {
            float2 f0 = __half22float2(p0[j]);
            float2 f1 = __half22float2(p1[j]);
            acc[j][0] = f0.x; acc[j][1] = f0.y;
            acc[j][2] = f1.x; acc[j][3] = f1.y;
        }
        {
            int tn = (ts + 1 < T_STEPS) ? ts + 1 : ts;
#pragma unroll
            for (int j = 0; j < 4; j++) {
                p0[j] = __ldg((const __half2*)(xr0 + (size_t)tn * G4 + colbase + j * 8));
                p1[j] = __ldg((const __half2*)(xr1 + (size_t)tn * G4 + colbase + j * 8));
            }
        }

#pragma unroll
        for (int p = 0; p < 4; p++) {
            unsigned e0, e1, e2, e3, o0, o1, o2, o3;
            ldsm4(e0, e1, e2, e3, abase + (2 * p    ) * 32u);
            ldsm4(o0, o1, o2, o3, abase + (2 * p + 1) * 32u);
#pragma unroll
            for (int j = 0; j < 4; j++) {
                uint4 b = swfw[(j * 4 + p) * 32 + lane];
                mma16h(acc[j], e0, e1, e2, e3, b.x, b.y);
                mma16h(acc[j], o0, o1, o2, o3, b.z, b.w);
            }
        }

#pragma unroll
        for (int j = 0; j < 4; j++) {
            float a0 = odd ? tanhf_(acc[j][0]) : sigmoidf_(acc[j][0]);
            float a1 = sigmoidf_(acc[j][1]);
            float a2 = odd ? tanhf_(acc[j][2]) : sigmoidf_(acc[j][2]);
            float a3 = sigmoidf_(acc[j][3]);
            float sv0 = odd ? a0 : a2;
            float sv1 = odd ? a1 : a3;
            float rv0 = __shfl_xor_sync(0xffffffffu, sv0, 1);
            float rv1 = __shfl_xor_sync(0xffffffffu, sv1, 1);
            float iG = odd ? rv0 : a0;
            float fG = odd ? rv1 : a1;
            float gG = odd ? a2  : rv0;
            float oG = odd ? a3  : rv1;
            float cn = fG * c_reg[j] + iG * gG;
            float hn = oG * tanhf_(cn);
            c_reg[j] = cn;
            int hh = hh0 + 2 * j;
            hnb[row_pw * SHh + hh] = __float2half_rn(hn);
            if (hlast && ts == T_STEPS - 1) hlast[(size_t)(b0 + row_pw) * H + hh] = hn;
        }
        __syncthreads();

        if (hsout) {
#pragma unroll
            for (int q = 0; q < 2; q++) {
                int r = wr_r0 + q * 8;
                unsigned bits = *(const unsigned*)&hnb[r * SHh + wr_c0];
                *(unsigned*)(hsout + ((size_t)(b0 + r) * T_STEPS + ts) * H + wr_c0) = bits;
            }
        }
        cur ^= 1;
    }
}

// ---------------- launcher ----------------
extern "C" void kernel_launch(void* const* d_in, const int* in_sizes, int n_in,
                              void* d_out, int out_size)
{
    const float* x       = (const float*)d_in[0];
    const float* fc_w    = (const float*)d_in[1];
    const float* fc_b    = (const float*)d_in[2];
    const float* bn_g    = (const float*)d_in[3];
    const float* bn_b    = (const float*)d_in[4];
    const float* bn_mean = (const float*)d_in[5];
    const float* bn_var  = (const float*)d_in[6];
    const float* wih0    = (const float*)d_in[7];
    const float* whh0    = (const float*)d_in[8];
    const float* bih0    = (const float*)d_in[9];
    const float* bhh0    = (const float*)d_in[10];
    const float* wih1    = (const float*)d_in[11];
    const float* whh1    = (const float*)d_in[12];
    const float* bih1    = (const float*)d_in[13];
    const float* bhh1    = (const float*)d_in[14];
    float* out = (float*)d_out;

    const int B = in_sizes[0] / (F_IN * T_STEPS);
    const int M = B * T_STEPS;

    __half *p_xproj, *p_hs, *p_wfh0, *p_wfh1, *p_wifh0, *p_wifh1;
    float *p_biasp0, *p_biasp1;
    cudaGetSymbolAddress((void**)&p_xproj,  g_xproj);
    cudaGetSymbolAddress((void**)&p_hs,     g_hs);
    cudaGetSymbolAddress((void**)&p_biasp0, g_biasp0);
    cudaGetSymbolAddress((void**)&p_biasp1, g_biasp1);
    cudaGetSymbolAddress((void**)&p_wfh0,   g_wfh0);
    cudaGetSymbolAddress((void**)&p_wfh1,   g_wfh1);
    cudaGetSymbolAddress((void**)&p_wifh0,  g_wifh0);
    cudaGetSymbolAddress((void**)&p_wifh1,  g_wifh1);

    const size_t lstm_smem = (size_t)2 * HBUF_B + (size_t)16 * 512 * 16;     // 8704 + 128KB
    const size_t fuse_smem = (size_t)(4 * 128 * SA + 128 * S2) * 2;          // ~75KB
    cudaFuncSetAttribute(lstm_tc, cudaFuncAttributeMaxDynamicSharedMemorySize, (int)lstm_smem);
    cudaFuncSetAttribute(fc_proj_fused, cudaFuncAttributeMaxDynamicSharedMemorySize, (int)fuse_smem);

    prep_kernel<<<256, 256>>>(wih0, bih0, bhh0, whh0, p_biasp0, p_wfh0, p_wifh0);
    prep_kernel<<<256, 256>>>(wih1, bih1, bhh1, whh1, p_biasp1, p_wfh1, p_wifh1);

    // fused FC+BN+LeakyReLU -> layer-0 projection (fp16 mma throughout)
    fc_proj_fused<<<M / 128, 256, fuse_smem>>>(x, fc_w, p_wifh0, p_xproj,
                                               fc_b, bn_g, bn_b, bn_mean, bn_var, p_biasp0);
    // layer-0 LSTM
    lstm_tc<<<B / 16, 512, lstm_smem>>>(p_xproj, p_wfh0, p_hs, nullptr);
    // layer-1 projection (fp16 mma)
    gemm_tc1<<<dim3(M / 128, 4), 256>>>(p_hs, p_wifh1, p_xproj, M, p_biasp1);
    // layer-1 LSTM -> final hidden state (fp32 out)
    lstm_tc<<<B / 16, 512, lstm_smem>>>(p_xproj, p_wfh1, nullptr, out);
}

// round 12
// speedup vs baseline: 5.6147x; 1.1696x over previous
#include <cuda_runtime.h>
#include <cuda_fp16.h>
#include <math.h>

#define T_STEPS 120
#define F_IN    180
#define H       128
#define G4      512
#define MAX_B   2048

// ---------------- static scratch ----------------
__device__ __half g_xproj[(size_t)MAX_B * T_STEPS * G4];   // fp16 projections (reused)
__device__ __half g_hs   [(size_t)MAX_B * T_STEPS * H];    // layer-0 hidden states (fp16)
__device__ float  g_biasp0[G4],  g_biasp1[G4];
__device__ __align__(16) __half g_wfh0[G4 * H], g_wfh1[G4 * H];   // Whh fp16 m16n8k16 B-frags
__device__ __align__(16) __half g_wifh0[G4 * H], g_wifh1[G4 * H]; // wih fp16 m16n8k16 B-frags

// ---------------- helpers ----------------
__device__ __forceinline__ void mma16h(float* c, unsigned a0, unsigned a1, unsigned a2, unsigned a3,
                                       unsigned b0, unsigned b1) {
    asm volatile("mma.sync.aligned.m16n8k16.row.col.f32.f16.f16.f32 "
                 "{%0,%1,%2,%3}, {%4,%5,%6,%7}, {%8,%9}, {%0,%1,%2,%3};"
                 : "+f"(c[0]), "+f"(c[1]), "+f"(c[2]), "+f"(c[3])
                 : "r"(a0), "r"(a1), "r"(a2), "r"(a3), "r"(b0), "r"(b1));
}
__device__ __forceinline__ void ldsm4(unsigned& a0, unsigned& a1, unsigned& a2, unsigned& a3,
                                      unsigned addr) {
    asm volatile("ldmatrix.sync.aligned.m8n8.x4.shared.b16 {%0,%1,%2,%3}, [%4];"
                 : "=r"(a0), "=r"(a1), "=r"(a2), "=r"(a3) : "r"(addr));
}
__device__ __forceinline__ float tanh_ap(float x) {
    float y; asm("tanh.approx.f32 %0, %1;" : "=f"(y) : "f"(x)); return y;
}
__device__ __forceinline__ float sig_ap(float x) {
    return fmaf(0.5f, tanh_ap(0.5f * x), 0.5f);
}

// ---------------- prep: combine bias; pack Whh AND wih as fp16 m16n8k16 B-frags ----------------
// Gate interleave: orig row n (gate=n>>7, hh=n&127) -> row' = hh*4 + gate.
// frag layout (uint4-pair form): idx i: v2=i&7, lane=(i>>3)&31, p=(i>>8)&3, j=(i>>10)&3, w=i>>12
//   nt = w*4+j; n' = nt*8+(lane>>2); ks = 2p+(v2>>2); k = ks*16+(lane&3)*2+(v2&1)+((v2>>1)&1)*8
__global__ void prep_kernel(const float* __restrict__ wih, const float* __restrict__ bih,
                            const float* __restrict__ bhh, const float* __restrict__ whh,
                            float* __restrict__ biasp, __half* __restrict__ wfh,
                            __half* __restrict__ wifh)
{
    int i = blockIdx.x * 256 + threadIdx.x;
    if (i < G4 * H) {
        int n = i >> 7, k = i & 127;
        if (k == 0) {
            int np = ((n & 127) << 2) | (n >> 7);
            biasp[np] = bih[n] + bhh[n];
        }
        int v2 = i & 7, lane = (i >> 3) & 31, p = (i >> 8) & 3, j = (i >> 10) & 3, w = i >> 12;
        int ks = 2 * p + (v2 >> 2);
        int kk = ks * 16 + (lane & 3) * 2 + (v2 & 1) + ((v2 >> 1) & 1) * 8;
        int np = w * 32 + j * 8 + (lane >> 2);
        int orig = ((np & 3) << 7) | (np >> 2);
        wfh [i] = __float2half_rn(whh[orig * H + kk]);
        wifh[i] = __float2half_rn(wih[orig * H + kk]);
    }
}

#define SA  40    // phase-1 tile row stride (halfs), k32 chunks, conflict-free
#define S2  136   // 128-half row stride (halfs), conflict-free for ldsm

// ---------------- fused FC+BN+LeakyReLU -> layer-0 projection (all fp16 mma) ----------------
__global__ void __launch_bounds__(256)
fc_proj_fused(const float* __restrict__ x, const float* __restrict__ W,
              const __half* __restrict__ Wf, __half* __restrict__ C,
              const float* __restrict__ fcb, const float* __restrict__ bng,
              const float* __restrict__ bnb, const float* __restrict__ bnm,
              const float* __restrict__ bnv, const float* __restrict__ biasp)
{
    extern __shared__ __align__(16) char fsm[];
    __half* Ah = (__half*)fsm;              // [2][128*SA]
    __half* Bh = Ah + 2 * 128 * SA;         // [2][128*SA]
    __half* hp = Bh + 2 * 128 * SA;         // [128][S2]
    __shared__ int rowbase[128];

    const int tid  = threadIdx.x;
    const int lane = tid & 31, warp = tid >> 5;
    const int g = lane >> 2, t = lane & 3;
    const int wm = warp & 3, wn = warp >> 2;
    const int m0 = blockIdx.x * 128;

    if (tid < 128) {
        int m = m0 + tid; int b = m / T_STEPS;
        rowbase[tid] = b * (F_IN * T_STEPS) + (m - b * T_STEPS);
    }
    __syncthreads();

    const int r  = tid >> 1;
    const int hf = tid & 1;
    const int nc = 6;    // ceil(180/32)

    __half2 av2[8], wv2[8];
    auto LOAD = [&](int kc) {
#pragma unroll
        for (int i = 0; i < 8; i++) {
            int k = kc + hf * 16 + 2 * i;
            float x0 = (k     < F_IN) ? __ldg(x + rowbase[r] + k * T_STEPS)       : 0.f;
            float x1 = (k + 1 < F_IN) ? __ldg(x + rowbase[r] + (k + 1) * T_STEPS) : 0.f;
            av2[i] = __floats2half2_rn(x0, x1);
            float w0 = (k     < F_IN) ? __ldg(W + r * F_IN + k)     : 0.f;
            float w1 = (k + 1 < F_IN) ? __ldg(W + r * F_IN + k + 1) : 0.f;
            wv2[i] = __floats2half2_rn(w0, w1);
        }
    };
    auto STORE = [&](int s) {
#pragma unroll
        for (int i = 0; i < 8; i++) {
            *(__half2*)&Ah[s * 128 * SA + r * SA + hf * 16 + 2 * i] = av2[i];
            *(__half2*)&Bh[s * 128 * SA + r * SA + hf * 16 + 2 * i] = wv2[i];
        }
    };

    float acc[2][8][4];
#pragma unroll
    for (int mi = 0; mi < 2; mi++)
#pragma unroll
        for (int j = 0; j < 8; j++)
#pragma unroll
            for (int q = 0; q < 4; q++) acc[mi][j][q] = 0.f;

    const unsigned ah_smem = (unsigned)__cvta_generic_to_shared(Ah);
    const unsigned lm_a    = ah_smem + (unsigned)((lane & 15) * SA * 2 + (lane >> 4) * 16);

    LOAD(0); STORE(0); __syncthreads();

    for (int c = 0; c < nc; c++) {
        if (c + 1 < nc) LOAD((c + 1) * 32);
        const unsigned abuf = lm_a + (unsigned)((c & 1) * 128 * SA * 2);
        const __half* bs = Bh + (c & 1) * 128 * SA;
#pragma unroll
        for (int kq = 0; kq < 2; kq++) {
            unsigned a[2][4];
#pragma unroll
            for (int mi = 0; mi < 2; mi++)
                ldsm4(a[mi][0], a[mi][1], a[mi][2], a[mi][3],
                      abuf + (unsigned)((wm * 32 + mi * 16) * SA * 2 + kq * 32));
#pragma unroll
            for (int j = 0; j < 8; j++) {
                int row = wn * 64 + j * 8 + g;
                unsigned b0 = *(const unsigned*)&bs[row * SA + kq * 16 + 2 * t];
                unsigned b1 = *(const unsigned*)&bs[row * SA + kq * 16 + 2 * t + 8];
#pragma unroll
                for (int mi = 0; mi < 2; mi++)
                    mma16h(acc[mi][j], a[mi][0], a[mi][1], a[mi][2], a[mi][3], b0, b1);
            }
        }
        if (c + 1 < nc) STORE((c + 1) & 1);
        __syncthreads();
    }

    // phase-1 epilogue: BN + LeakyReLU -> fp16 into hp
#pragma unroll
    for (int j = 0; j < 8; j++) {
        int col = wn * 64 + j * 8 + 2 * t;
        float s0 = bng[col]     * rsqrtf(bnv[col]     + 1e-5f);
        float s1 = bng[col + 1] * rsqrtf(bnv[col + 1] + 1e-5f);
        float be0 = (fcb[col]     - bnm[col]    ) * s0 + bnb[col];
        float be1 = (fcb[col + 1] - bnm[col + 1]) * s1 + bnb[col + 1];
#pragma unroll
        for (int mi = 0; mi < 2; mi++) {
            int row = wm * 32 + mi * 16 + g;
            float v0 = acc[mi][j][0] * s0 + be0;
            float v1 = acc[mi][j][1] * s1 + be1;
            float v2 = acc[mi][j][2] * s0 + be0;
            float v3 = acc[mi][j][3] * s1 + be1;
            v0 = (v0 >= 0.f) ? v0 : 0.01f * v0;
            v1 = (v1 >= 0.f) ? v1 : 0.01f * v1;
            v2 = (v2 >= 0.f) ? v2 : 0.01f * v2;
            v3 = (v3 >= 0.f) ? v3 : 0.01f * v3;
            *(__half2*)&hp[(row    ) * S2 + col] = __floats2half2_rn(v0, v1);
            *(__half2*)&hp[(row + 8) * S2 + col] = __floats2half2_rn(v2, v3);
        }
    }
    __syncthreads();

    // phase 2: xproj = hp @ wih^T + biasp, fp16 mma, K=128
    const uint4* wf4 = (const uint4*)Wf;
    const unsigned hp_smem = (unsigned)__cvta_generic_to_shared(hp);
    const unsigned lm_h    = hp_smem + (unsigned)((lane & 15) * S2 * 2 + (lane >> 4) * 16);
#pragma unroll 1
    for (int nch = 0; nch < 4; nch++) {
        float a2[2][8][4];
#pragma unroll
        for (int mi = 0; mi < 2; mi++)
#pragma unroll
            for (int j = 0; j < 8; j++)
#pragma unroll
                for (int q = 0; q < 4; q++) a2[mi][j][q] = 0.f;

#pragma unroll
        for (int p = 0; p < 4; p++) {
            unsigned e[2][4], o[2][4];
#pragma unroll
            for (int mi = 0; mi < 2; mi++) {
                unsigned rbase = lm_h + (unsigned)((wm * 32 + mi * 16) * S2 * 2);
                ldsm4(e[mi][0], e[mi][1], e[mi][2], e[mi][3], rbase + (2 * p    ) * 32u);
                ldsm4(o[mi][0], o[mi][1], o[mi][2], o[mi][3], rbase + (2 * p + 1) * 32u);
            }
#pragma unroll
            for (int j = 0; j < 8; j++) {
                int nt = nch * 16 + wn * 8 + j;
                uint4 b = __ldg(wf4 + ((size_t)nt * 4 + p) * 32 + lane);
#pragma unroll
                for (int mi = 0; mi < 2; mi++) {
                    mma16h(a2[mi][j], e[mi][0], e[mi][1], e[mi][2], e[mi][3], b.x, b.y);
                    mma16h(a2[mi][j], o[mi][0], o[mi][1], o[mi][2], o[mi][3], b.z, b.w);
                }
            }
        }
#pragma unroll
        for (int j = 0; j < 8; j++) {
            int col = nch * 128 + wn * 64 + j * 8 + 2 * t;
            float be0 = __ldg(biasp + col);
            float be1 = __ldg(biasp + col + 1);
#pragma unroll
            for (int mi = 0; mi < 2; mi++) {
                int row = m0 + wm * 32 + mi * 16 + g;
                *(__half2*)(C + (size_t)row * G4 + col) =
                    __floats2half2_rn(a2[mi][j][0] + be0, a2[mi][j][1] + be1);
                *(__half2*)(C + (size_t)(row + 8) * G4 + col) =
                    __floats2half2_rn(a2[mi][j][2] + be0, a2[mi][j][3] + be1);
            }
        }
    }
}

// ---------------- fp16 GEMM for layer-1 projection (A = fp16 hs, single-staged tile) ----------
__global__ void __launch_bounds__(256)
gemm_tc1(const __half* __restrict__ A, const __half* __restrict__ Wf, __half* __restrict__ C,
         int M, const float* __restrict__ q0)
{
    __shared__ __align__(16) __half Ah[128 * S2];

    const int tid  = threadIdx.x;
    const int lane = tid & 31, warp = tid >> 5;
    const int g = lane >> 2, t = lane & 3;
    const int wm = warp & 3, wn = warp >> 2;
    const int m0 = blockIdx.x * 128, n0 = blockIdx.y * 128;

    // stage A tile (bit copy, coalesced uint4)
#pragma unroll
    for (int it = 0; it < 8; it++) {
        int linear = tid + it * 256;
        int row = linear >> 4, seg = linear & 15;
        *(uint4*)&Ah[row * S2 + seg * 8] =
            *(const uint4*)(A + (size_t)(m0 + row) * H + seg * 8);
    }
    __syncthreads();

    float acc[2][8][4];
#pragma unroll
    for (int mi = 0; mi < 2; mi++)
#pragma unroll
        for (int j = 0; j < 8; j++)
#pragma unroll
            for (int q = 0; q < 4; q++) acc[mi][j][q] = 0.f;

    const uint4* wf4 = (const uint4*)Wf;
    const unsigned ah_smem = (unsigned)__cvta_generic_to_shared(Ah);
    const unsigned lm_a    = ah_smem + (unsigned)((lane & 15) * S2 * 2 + (lane >> 4) * 16);
    const int nt_base = (n0 >> 3) + wn * 8;

#pragma unroll
    for (int p = 0; p < 4; p++) {
        unsigned e[2][4], o[2][4];
#pragma unroll
        for (int mi = 0; mi < 2; mi++) {
            unsigned rbase = lm_a + (unsigned)((wm * 32 + mi * 16) * S2 * 2);
            ldsm4(e[mi][0], e[mi][1], e[mi][2], e[mi][3], rbase + (2 * p    ) * 32u);
            ldsm4(o[mi][0], o[mi][1], o[mi][2], o[mi][3], rbase + (2 * p + 1) * 32u);
        }
#pragma unroll
        for (int j = 0; j < 8; j++) {
            uint4 b = __ldg(wf4 + ((size_t)(nt_base + j) * 4 + p) * 32 + lane);
#pragma unroll
            for (int mi = 0; mi < 2; mi++) {
                mma16h(acc[mi][j], e[mi][0], e[mi][1], e[mi][2], e[mi][3], b.x, b.y);
                mma16h(acc[mi][j], o[mi][0], o[mi][1], o[mi][2], o[mi][3], b.z, b.w);
            }
        }
    }

    const int cm = m0 + wm * 32;
    const int cn = n0 + wn * 64;
#pragma unroll
    for (int j = 0; j < 8; j++) {
        int col = cn + j * 8 + 2 * t;
        float be0 = __ldg(q0 + col);
        float be1 = __ldg(q0 + col + 1);
#pragma unroll
        for (int mi = 0; mi < 2; mi++) {
            int row = cm + mi * 16 + g;
            *(__half2*)(C + (size_t)row * G4 + col) =
                __floats2half2_rn(acc[mi][j][0] + be0, acc[mi][j][1] + be1);
            *(__half2*)(C + (size_t)(row + 8) * G4 + col) =
                __floats2half2_rn(acc[mi][j][2] + be0, acc[mi][j][3] + be1);
        }
    }
}

// ---------------- persistent fp16 tensor-core LSTM (hw-tanh epilogue) ----------------
#define SHh    136
#define HBUF_B (16 * SHh * 2)

__global__ void __launch_bounds__(512)
lstm_tc(const __half* __restrict__ xproj, const __half* __restrict__ wfh,
        __half* __restrict__ hsout, float* __restrict__ hlast)
{
    extern __shared__ unsigned smx[];
    __half* h_buf = (__half*)smx;
    uint4*  swf   = (uint4*)((char*)smx + 2 * HBUF_B);

    const int tid  = threadIdx.x, lane = tid & 31, w = tid >> 5;
    const int g = lane >> 2, t = lane & 3;
    const int odd = t & 1;
    const int b0 = blockIdx.x * 16;
    uint4* swfw = swf + (size_t)w * 512;

    {
        const uint4* src = (const uint4*)wfh + (size_t)w * 512;
        for (int idx = lane; idx < 512; idx += 32)
            swfw[idx] = __ldg(src + idx);
    }

    for (int i = tid; i < (2 * HBUF_B) / 4; i += 512) smx[i] = 0u;
    __syncthreads();

    float c_reg[4] = {0.f, 0.f, 0.f, 0.f};
    const int row_pw = g + odd * 8;
    const int hh0    = w * 8 + (t >> 1);
    const __half* xr0 = xproj + (size_t)(b0 + g    ) * T_STEPS * G4;
    const __half* xr1 = xproj + (size_t)(b0 + g + 8) * T_STEPS * G4;
    const int colbase = w * 32 + 2 * t;

    const unsigned hb_smem = (unsigned)__cvta_generic_to_shared(h_buf);
    const unsigned lmoff = hb_smem + (unsigned)((lane & 15) * SHh * 2 + (lane >> 4) * 16);

    const int wr_r0 = tid >> 6;
    const int wr_c0 = (tid & 63) << 1;

    __half2 p0[4], p1[4];
#pragma unroll
    for (int j = 0; j < 4; j++) {
        p0[j] = *(const __half2*)(xr0 + colbase + j * 8);
        p1[j] = *(const __half2*)(xr1 + colbase + j * 8);
    }

    int cur = 0;
    for (int ts = 0; ts < T_STEPS; ts++) {
        __half*        hnb   = h_buf + (cur ^ 1) * (16 * SHh);
        const unsigned abase = lmoff + (unsigned)(cur * HBUF_B);
        float acc[4][4];
#pragma unroll
        for (int j = 0; j < 4; j++) {
            float2 f0 = __half22float2(p0[j]);
            float2 f1 = __half22float2(p1[j]);
            acc[j][0] = f0.x; acc[j][1] = f0.y;
            acc[j][2] = f1.x; acc[j][3] = f1.y;
        }
        {
            int tn = (ts + 1 < T_STEPS) ? ts + 1 : ts;
#pragma unroll
            for (int j = 0; j < 4; j++) {
                p0[j] = __ldg((const __half2*)(xr0 + (size_t)tn * G4 + colbase + j * 8));
                p1[j] = __ldg((const __half2*)(xr1 + (size_t)tn * G4 + colbase + j * 8));
            }
        }

#pragma unroll
        for (int p = 0; p < 4; p++) {
            unsigned e0, e1, e2, e3, o0, o1, o2, o3;
            ldsm4(e0, e1, e2, e3, abase + (2 * p    ) * 32u);
            ldsm4(o0, o1, o2, o3, abase + (2 * p + 1) * 32u);
#pragma unroll
            for (int j = 0; j < 4; j++) {
                uint4 b = swfw[(j * 4 + p) * 32 + lane];
                mma16h(acc[j], e0, e1, e2, e3, b.x, b.y);
                mma16h(acc[j], o0, o1, o2, o3, b.z, b.w);
            }
        }

        // activations (hw tanh) + pair-exchange + state update
#pragma unroll
        for (int j = 0; j < 4; j++) {
            float a0 = odd ? tanh_ap(acc[j][0]) : sig_ap(acc[j][0]);
            float a1 = sig_ap(acc[j][1]);
            float a2 = odd ? tanh_ap(acc[j][2]) : sig_ap(acc[j][2]);
            float a3 = sig_ap(acc[j][3]);
            float sv0 = odd ? a0 : a2;
            float sv1 = odd ? a1 : a3;
            float rv0 = __shfl_xor_sync(0xffffffffu, sv0, 1);
            float rv1 = __shfl_xor_sync(0xffffffffu, sv1, 1);
            float iG = odd ? rv0 : a0;
            float fG = odd ? rv1 : a1;
            float gG = odd ? a2  : rv0;
            float oG = odd ? a3  : rv1;
            float cn = fG * c_reg[j] + iG * gG;
            float hn = oG * tanh_ap(cn);
            c_reg[j] = cn;
            int hh = hh0 + 2 * j;
            hnb[row_pw * SHh + hh] = __float2half_rn(hn);
            if (hlast && ts == T_STEPS - 1) hlast[(size_t)(b0 + row_pw) * H + hh] = hn;
        }
        __syncthreads();

        if (hsout) {
#pragma unroll
            for (int q = 0; q < 2; q++) {
                int r = wr_r0 + q * 8;
                unsigned bits = *(const unsigned*)&hnb[r * SHh + wr_c0];
                *(unsigned*)(hsout + ((size_t)(b0 + r) * T_STEPS + ts) * H + wr_c0) = bits;
            }
        }
        cur ^= 1;
    }
}

// ---------------- launcher ----------------
extern "C" void kernel_launch(void* const* d_in, const int* in_sizes, int n_in,
                              void* d_out, int out_size)
{
    const float* x       = (const float*)d_in[0];
    const float* fc_w    = (const float*)d_in[1];
    const float* fc_b    = (const float*)d_in[2];
    const float* bn_g    = (const float*)d_in[3];
    const float* bn_b    = (const float*)d_in[4];
    const float* bn_mean = (const float*)d_in[5];
    const float* bn_var  = (const float*)d_in[6];
    const float* wih0    = (const float*)d_in[7];
    const float* whh0    = (const float*)d_in[8];
    const float* bih0    = (const float*)d_in[9];
    const float* bhh0    = (const float*)d_in[10];
    const float* wih1    = (const float*)d_in[11];
    const float* whh1    = (const float*)d_in[12];
    const float* bih1    = (const float*)d_in[13];
    const float* bhh1    = (const float*)d_in[14];
    float* out = (float*)d_out;

    const int B = in_sizes[0] / (F_IN * T_STEPS);
    const int M = B * T_STEPS;

    __half *p_xproj, *p_hs, *p_wfh0, *p_wfh1, *p_wifh0, *p_wifh1;
    float *p_biasp0, *p_biasp1;
    cudaGetSymbolAddress((void**)&p_xproj,  g_xproj);
    cudaGetSymbolAddress((void**)&p_hs,     g_hs);
    cudaGetSymbolAddress((void**)&p_biasp0, g_biasp0);
    cudaGetSymbolAddress((void**)&p_biasp1, g_biasp1);
    cudaGetSymbolAddress((void**)&p_wfh0,   g_wfh0);
    cudaGetSymbolAddress((void**)&p_wfh1,   g_wfh1);
    cudaGetSymbolAddress((void**)&p_wifh0,  g_wifh0);
    cudaGetSymbolAddress((void**)&p_wifh1,  g_wifh1);

    const size_t lstm_smem = (size_t)2 * HBUF_B + (size_t)16 * 512 * 16;     // 8704 + 128KB
    const size_t fuse_smem = (size_t)(4 * 128 * SA + 128 * S2) * 2;          // ~75KB
    cudaFuncSetAttribute(lstm_tc, cudaFuncAttributeMaxDynamicSharedMemorySize, (int)lstm_smem);
    cudaFuncSetAttribute(fc_proj_fused, cudaFuncAttributeMaxDynamicSharedMemorySize, (int)fuse_smem);

    prep_kernel<<<256, 256>>>(wih0, bih0, bhh0, whh0, p_biasp0, p_wfh0, p_wifh0);
    prep_kernel<<<256, 256>>>(wih1, bih1, bhh1, whh1, p_biasp1, p_wfh1, p_wifh1);

    // fused FC+BN+LeakyReLU -> layer-0 projection (fp16 mma throughout)
    fc_proj_fused<<<M / 128, 256, fuse_smem>>>(x, fc_w, p_wifh0, p_xproj,
                                               fc_b, bn_g, bn_b, bn_mean, bn_var, p_biasp0);
    // layer-0 LSTM
    lstm_tc<<<B / 16, 512, lstm_smem>>>(p_xproj, p_wfh0, p_hs, nullptr);
    // layer-1 projection (fp16 mma)
    gemm_tc1<<<dim3(M / 128, 4), 256>>>(p_hs, p_wifh1, p_xproj, M, p_biasp1);
    // layer-1 LSTM -> final hidden state (fp32 out)
    lstm_tc<<<B / 16, 512, lstm_smem>>>(p_xproj, p_wfh1, nullptr, out);
}

// round 13
// speedup vs baseline: 5.7847x; 1.0303x over previous
#include <cuda_runtime.h>
#include <cuda_fp16.h>
#include <math.h>

#define T_STEPS 120
#define F_IN    180
#define H       128
#define G4      512
#define MAX_B   2048

// ---------------- static scratch ----------------
__device__ __half g_xproj[(size_t)MAX_B * T_STEPS * G4];   // fp16 projections (in-place reuse)
__device__ float  g_biasp0[G4],  g_biasp1[G4];
__device__ __align__(16) __half g_wfh0[G4 * H], g_wfh1[G4 * H];   // Whh fp16 m16n8k16 B-frags
__device__ __align__(16) __half g_wifh0[G4 * H], g_wifh1[G4 * H]; // wih fp16 m16n8k16 B-frags

// ---------------- helpers ----------------
__device__ __forceinline__ void mma16h(float* c, unsigned a0, unsigned a1, unsigned a2, unsigned a3,
                                       unsigned b0, unsigned b1) {
    asm volatile("mma.sync.aligned.m16n8k16.row.col.f32.f16.f16.f32 "
                 "{%0,%1,%2,%3}, {%4,%5,%6,%7}, {%8,%9}, {%0,%1,%2,%3};"
                 : "+f"(c[0]), "+f"(c[1]), "+f"(c[2]), "+f"(c[3])
                 : "r"(a0), "r"(a1), "r"(a2), "r"(a3), "r"(b0), "r"(b1));
}
__device__ __forceinline__ void ldsm4(unsigned& a0, unsigned& a1, unsigned& a2, unsigned& a3,
                                      unsigned addr) {
    asm volatile("ldmatrix.sync.aligned.m8n8.x4.shared.b16 {%0,%1,%2,%3}, [%4];"
                 : "=r"(a0), "=r"(a1), "=r"(a2), "=r"(a3) : "r"(addr));
}
__device__ __forceinline__ float tanh_ap(float x) {
    float y; asm("tanh.approx.f32 %0, %1;" : "=f"(y) : "f"(x)); return y;
}
__device__ __forceinline__ float sig_ap(float x) {
    return fmaf(0.5f, tanh_ap(0.5f * x), 0.5f);
}

// ---------------- prep: combine bias; pack Whh AND wih as fp16 m16n8k16 B-frags ----------------
__global__ void prep_kernel(const float* __restrict__ wih, const float* __restrict__ bih,
                            const float* __restrict__ bhh, const float* __restrict__ whh,
                            float* __restrict__ biasp, __half* __restrict__ wfh,
                            __half* __restrict__ wifh)
{
    int i = blockIdx.x * 256 + threadIdx.x;
    if (i < G4 * H) {
        int n = i >> 7, k = i & 127;
        if (k == 0) {
            int np = ((n & 127) << 2) | (n >> 7);
            biasp[np] = bih[n] + bhh[n];
        }
        int v2 = i & 7, lane = (i >> 3) & 31, p = (i >> 8) & 3, j = (i >> 10) & 3, w = i >> 12;
        int ks = 2 * p + (v2 >> 2);
        int kk = ks * 16 + (lane & 3) * 2 + (v2 & 1) + ((v2 >> 1) & 1) * 8;
        int np = w * 32 + j * 8 + (lane >> 2);
        int orig = ((np & 3) << 7) | (np >> 2);
        wfh [i] = __float2half_rn(whh[orig * H + kk]);
        wifh[i] = __float2half_rn(wih[orig * H + kk]);
    }
}

#define SA  40
#define S2  136

// ---------------- fused FC+BN+LeakyReLU -> layer-0 projection (all fp16 mma) ----------------
__global__ void __launch_bounds__(256)
fc_proj_fused(const float* __restrict__ x, const float* __restrict__ W,
              const __half* __restrict__ Wf, __half* __restrict__ C,
              const float* __restrict__ fcb, const float* __restrict__ bng,
              const float* __restrict__ bnb, const float* __restrict__ bnm,
              const float* __restrict__ bnv, const float* __restrict__ biasp)
{
    extern __shared__ __align__(16) char fsm[];
    __half* Ah = (__half*)fsm;              // [2][128*SA]
    __half* Bh = Ah + 2 * 128 * SA;         // [2][128*SA]
    __half* hp = Bh + 2 * 128 * SA;         // [128][S2]
    __shared__ int rowbase[128];

    const int tid  = threadIdx.x;
    const int lane = tid & 31, warp = tid >> 5;
    const int g = lane >> 2, t = lane & 3;
    const int wm = warp & 3, wn = warp >> 2;
    const int m0 = blockIdx.x * 128;

    if (tid < 128) {
        int m = m0 + tid; int b = m / T_STEPS;
        rowbase[tid] = b * (F_IN * T_STEPS) + (m - b * T_STEPS);
    }
    __syncthreads();

    const int r  = tid >> 1;
    const int hf = tid & 1;
    const int nc = 6;

    __half2 av2[8], wv2[8];
    auto LOAD = [&](int kc) {
#pragma unroll
        for (int i = 0; i < 8; i++) {
            int k = kc + hf * 16 + 2 * i;
            float x0 = (k     < F_IN) ? __ldg(x + rowbase[r] + k * T_STEPS)       : 0.f;
            float x1 = (k + 1 < F_IN) ? __ldg(x + rowbase[r] + (k + 1) * T_STEPS) : 0.f;
            av2[i] = __floats2half2_rn(x0, x1);
            float w0 = (k     < F_IN) ? __ldg(W + r * F_IN + k)     : 0.f;
            float w1 = (k + 1 < F_IN) ? __ldg(W + r * F_IN + k + 1) : 0.f;
            wv2[i] = __floats2half2_rn(w0, w1);
        }
    };
    auto STORE = [&](int s) {
#pragma unroll
        for (int i = 0; i < 8; i++) {
            *(__half2*)&Ah[s * 128 * SA + r * SA + hf * 16 + 2 * i] = av2[i];
            *(__half2*)&Bh[s * 128 * SA + r * SA + hf * 16 + 2 * i] = wv2[i];
        }
    };

    float acc[2][8][4];
#pragma unroll
    for (int mi = 0; mi < 2; mi++)
#pragma unroll
        for (int j = 0; j < 8; j++)
#pragma unroll
            for (int q = 0; q < 4; q++) acc[mi][j][q] = 0.f;

    const unsigned ah_smem = (unsigned)__cvta_generic_to_shared(Ah);
    const unsigned lm_a    = ah_smem + (unsigned)((lane & 15) * SA * 2 + (lane >> 4) * 16);

    LOAD(0); STORE(0); __syncthreads();

    for (int c = 0; c < nc; c++) {
        if (c + 1 < nc) LOAD((c + 1) * 32);
        const unsigned abuf = lm_a + (unsigned)((c & 1) * 128 * SA * 2);
        const __half* bs = Bh + (c & 1) * 128 * SA;
#pragma unroll
        for (int kq = 0; kq < 2; kq++) {
            unsigned a[2][4];
#pragma unroll
            for (int mi = 0; mi < 2; mi++)
                ldsm4(a[mi][0], a[mi][1], a[mi][2], a[mi][3],
                      abuf + (unsigned)((wm * 32 + mi * 16) * SA * 2 + kq * 32));
#pragma unroll
            for (int j = 0; j < 8; j++) {
                int row = wn * 64 + j * 8 + g;
                unsigned b0 = *(const unsigned*)&bs[row * SA + kq * 16 + 2 * t];
                unsigned b1 = *(const unsigned*)&bs[row * SA + kq * 16 + 2 * t + 8];
#pragma unroll
                for (int mi = 0; mi < 2; mi++)
                    mma16h(acc[mi][j], a[mi][0], a[mi][1], a[mi][2], a[mi][3], b0, b1);
            }
        }
        if (c + 1 < nc) STORE((c + 1) & 1);
        __syncthreads();
    }

#pragma unroll
    for (int j = 0; j < 8; j++) {
        int col = wn * 64 + j * 8 + 2 * t;
        float s0 = bng[col]     * rsqrtf(bnv[col]     + 1e-5f);
        float s1 = bng[col + 1] * rsqrtf(bnv[col + 1] + 1e-5f);
        float be0 = (fcb[col]     - bnm[col]    ) * s0 + bnb[col];
        float be1 = (fcb[col + 1] - bnm[col + 1]) * s1 + bnb[col + 1];
#pragma unroll
        for (int mi = 0; mi < 2; mi++) {
            int row = wm * 32 + mi * 16 + g;
            float v0 = acc[mi][j][0] * s0 + be0;
            float v1 = acc[mi][j][1] * s1 + be1;
            float v2 = acc[mi][j][2] * s0 + be0;
            float v3 = acc[mi][j][3] * s1 + be1;
            v0 = (v0 >= 0.f) ? v0 : 0.01f * v0;
            v1 = (v1 >= 0.f) ? v1 : 0.01f * v1;
            v2 = (v2 >= 0.f) ? v2 : 0.01f * v2;
            v3 = (v3 >= 0.f) ? v3 : 0.01f * v3;
            *(__half2*)&hp[(row    ) * S2 + col] = __floats2half2_rn(v0, v1);
            *(__half2*)&hp[(row + 8) * S2 + col] = __floats2half2_rn(v2, v3);
        }
    }
    __syncthreads();

    const uint4* wf4 = (const uint4*)Wf;
    const unsigned hp_smem = (unsigned)__cvta_generic_to_shared(hp);
    const unsigned lm_h    = hp_smem + (unsigned)((lane & 15) * S2 * 2 + (lane >> 4) * 16);
#pragma unroll 1
    for (int nch = 0; nch < 4; nch++) {
        float a2[2][8][4];
#pragma unroll
        for (int mi = 0; mi < 2; mi++)
#pragma unroll
            for (int j = 0; j < 8; j++)
#pragma unroll
                for (int q = 0; q < 4; q++) a2[mi][j][q] = 0.f;

#pragma unroll
        for (int p = 0; p < 4; p++) {
            unsigned e[2][4], o[2][4];
#pragma unroll
            for (int mi = 0; mi < 2; mi++) {
                unsigned rbase = lm_h + (unsigned)((wm * 32 + mi * 16) * S2 * 2);
                ldsm4(e[mi][0], e[mi][1], e[mi][2], e[mi][3], rbase + (2 * p    ) * 32u);
                ldsm4(o[mi][0], o[mi][1], o[mi][2], o[mi][3], rbase + (2 * p + 1) * 32u);
            }
#pragma unroll
            for (int j = 0; j < 8; j++) {
                int nt = nch * 16 + wn * 8 + j;
                uint4 b = __ldg(wf4 + ((size_t)nt * 4 + p) * 32 + lane);
#pragma unroll
                for (int mi = 0; mi < 2; mi++) {
                    mma16h(a2[mi][j], e[mi][0], e[mi][1], e[mi][2], e[mi][3], b.x, b.y);
                    mma16h(a2[mi][j], o[mi][0], o[mi][1], o[mi][2], o[mi][3], b.z, b.w);
                }
            }
        }
#pragma unroll
        for (int j = 0; j < 8; j++) {
            int col = nch * 128 + wn * 64 + j * 8 + 2 * t;
            float be0 = __ldg(biasp + col);
            float be1 = __ldg(biasp + col + 1);
#pragma unroll
            for (int mi = 0; mi < 2; mi++) {
                int row = m0 + wm * 32 + mi * 16 + g;
                *(__half2*)(C + (size_t)row * G4 + col) =
                    __floats2half2_rn(a2[mi][j][0] + be0, a2[mi][j][1] + be1);
                *(__half2*)(C + (size_t)(row + 8) * G4 + col) =
                    __floats2half2_rn(a2[mi][j][2] + be0, a2[mi][j][3] + be1);
            }
        }
    }
}

// ---------------- persistent fp16 LSTM; PROJ fuses the next layer's input projection --------
// A-frags of h0[ts-1] (already ldsm'd for the recurrence) feed an independent second mma
// chain computing xproj1[ts-1] = h0[ts-1] @ wih1^T + bias, written in-place to xproj.
#define SHh    136
#define HBUF_B (16 * SHh * 2)

template<bool PROJ>
__global__ void __launch_bounds__(512)
lstm_tc(const __half* __restrict__ xproj, const __half* __restrict__ wfh,
        const __half* __restrict__ wpf, __half* __restrict__ xpout,
        const float* __restrict__ biasp, float* __restrict__ hlast)
{
    extern __shared__ unsigned smx[];
    __half* h_buf = (__half*)smx;                          // [2][16*SHh]
    uint4*  swf   = (uint4*)((char*)smx + 2 * HBUF_B);     // whh: 16 warps x 512 uint4
    uint4*  swf1  = swf + 16 * 512;                        // wih1 p=2,3: 16 warps x 256 uint4

    const int tid  = threadIdx.x, lane = tid & 31, w = tid >> 5;
    const int g = lane >> 2, t = lane & 3;
    const int odd = t & 1;
    const int b0 = blockIdx.x * 16;
    uint4* swfw  = swf  + (size_t)w * 512;
    uint4* swf1w = swf1 + (size_t)w * 256;
    const int colbase = w * 32 + 2 * t;

    {
        const uint4* src = (const uint4*)wfh + (size_t)w * 512;
        for (int idx = lane; idx < 512; idx += 32)
            swfw[idx] = __ldg(src + idx);
    }

    uint4 rb1[4][2];
    float bs0[4], bs1[4];
    if (PROJ) {
        const uint4* src1 = (const uint4*)wpf + (size_t)w * 512;
#pragma unroll
        for (int j = 0; j < 4; j++) {
#pragma unroll
            for (int p = 0; p < 2; p++)
                rb1[j][p] = __ldg(src1 + (j * 4 + p) * 32 + lane);
#pragma unroll
            for (int p = 2; p < 4; p++)
                swf1w[(j * 2 + p - 2) * 32 + lane] = __ldg(src1 + (j * 4 + p) * 32 + lane);
            bs0[j] = __ldg(biasp + colbase + j * 8);
            bs1[j] = __ldg(biasp + colbase + j * 8 + 1);
        }
    }

    for (int i = tid; i < (2 * HBUF_B) / 4; i += 512) smx[i] = 0u;
    __syncthreads();

    float c_reg[4] = {0.f, 0.f, 0.f, 0.f};
    const int row_pw = g + odd * 8;
    const int hh0    = w * 8 + (t >> 1);
    const __half* xr0 = xproj + (size_t)(b0 + g    ) * T_STEPS * G4;
    const __half* xr1 = xproj + (size_t)(b0 + g + 8) * T_STEPS * G4;
    __half* xw0 = PROJ ? (xpout + (size_t)(b0 + g    ) * T_STEPS * G4) : nullptr;
    __half* xw1 = PROJ ? (xpout + (size_t)(b0 + g + 8) * T_STEPS * G4) : nullptr;

    const unsigned hb_smem = (unsigned)__cvta_generic_to_shared(h_buf);
    const unsigned lmoff = hb_smem + (unsigned)((lane & 15) * SHh * 2 + (lane >> 4) * 16);

    __half2 p0[4], p1[4];
#pragma unroll
    for (int j = 0; j < 4; j++) {
        p0[j] = *(const __half2*)(xr0 + colbase + j * 8);
        p1[j] = *(const __half2*)(xr1 + colbase + j * 8);
    }

    int cur = 0;
    for (int ts = 0; ts < T_STEPS; ts++) {
        __half*        hnb   = h_buf + (cur ^ 1) * (16 * SHh);
        const unsigned abase = lmoff + (unsigned)(cur * HBUF_B);
        float acc[4][4];
#pragma unroll
        for (int j = 0; j < 4; j++) {
            float2 f0 = __half22float2(p0[j]);
            float2 f1 = __half22float2(p1[j]);
            acc[j][0] = f0.x; acc[j][1] = f0.y;
            acc[j][2] = f1.x; acc[j][3] = f1.y;
        }
        {
            int tn = (ts + 1 < T_STEPS) ? ts + 1 : ts;
#pragma unroll
            for (int j = 0; j < 4; j++) {
                p0[j] = __ldg((const __half2*)(xr0 + (size_t)tn * G4 + colbase + j * 8));
                p1[j] = __ldg((const __half2*)(xr1 + (size_t)tn * G4 + colbase + j * 8));
            }
        }

        float pacc[4][4];
        if (PROJ) {
#pragma unroll
            for (int j = 0; j < 4; j++)
#pragma unroll
                for (int q = 0; q < 4; q++) pacc[j][q] = 0.f;
        }

#pragma unroll
        for (int p = 0; p < 4; p++) {
            unsigned e0, e1, e2, e3, o0, o1, o2, o3;
            ldsm4(e0, e1, e2, e3, abase + (2 * p    ) * 32u);
            ldsm4(o0, o1, o2, o3, abase + (2 * p + 1) * 32u);
#pragma unroll
            for (int j = 0; j < 4; j++) {
                uint4 b = swfw[(j * 4 + p) * 32 + lane];
                mma16h(acc[j], e0, e1, e2, e3, b.x, b.y);
                mma16h(acc[j], o0, o1, o2, o3, b.z, b.w);
            }
            if (PROJ) {
#pragma unroll
                for (int j = 0; j < 4; j++) {
                    uint4 b1 = (p < 2) ? rb1[j][p] : swf1w[(j * 2 + p - 2) * 32 + lane];
                    mma16h(pacc[j], e0, e1, e2, e3, b1.x, b1.y);
                    mma16h(pacc[j], o0, o1, o2, o3, b1.z, b1.w);
                }
            }
        }

        // emit xproj1[ts-1] (A-frags were h0[ts-1]); identical math to the old gemm_tc1
        if (PROJ && ts > 0) {
            size_t tb = (size_t)(ts - 1) * G4;
#pragma unroll
            for (int j = 0; j < 4; j++) {
                *(__half2*)(xw0 + tb + colbase + j * 8) =
                    __floats2half2_rn(pacc[j][0] + bs0[j], pacc[j][1] + bs1[j]);
                *(__half2*)(xw1 + tb + colbase + j * 8) =
                    __floats2half2_rn(pacc[j][2] + bs0[j], pacc[j][3] + bs1[j]);
            }
        }

        // activations (hw tanh) + pair-exchange + state update
#pragma unroll
        for (int j = 0; j < 4; j++) {
            float a0 = odd ? tanh_ap(acc[j][0]) : sig_ap(acc[j][0]);
            float a1 = sig_ap(acc[j][1]);
            float a2 = odd ? tanh_ap(acc[j][2]) : sig_ap(acc[j][2]);
            float a3 = sig_ap(acc[j][3]);
            float sv0 = odd ? a0 : a2;
            float sv1 = odd ? a1 : a3;
            float rv0 = __shfl_xor_sync(0xffffffffu, sv0, 1);
            float rv1 = __shfl_xor_sync(0xffffffffu, sv1, 1);
            float iG = odd ? rv0 : a0;
            float fG = odd ? rv1 : a1;
            float gG = odd ? a2  : rv0;
            float oG = odd ? a3  : rv1;
            float cn = fG * c_reg[j] + iG * gG;
            float hn = oG * tanh_ap(cn);
            c_reg[j] = cn;
            int hh = hh0 + 2 * j;
            hnb[row_pw * SHh + hh] = __float2half_rn(hn);
            if (hlast && ts == T_STEPS - 1) hlast[(size_t)(b0 + row_pw) * H + hh] = hn;
        }
        __syncthreads();
        cur ^= 1;
    }

    // tail: xproj1[T-1] from h0[T-1] (now in h_buf[cur])
    if (PROJ) {
        const unsigned abase = lmoff + (unsigned)(cur * HBUF_B);
        float pacc[4][4];
#pragma unroll
        for (int j = 0; j < 4; j++)
#pragma unroll
            for (int q = 0; q < 4; q++) pacc[j][q] = 0.f;
#pragma unroll
        for (int p = 0; p < 4; p++) {
            unsigned e0, e1, e2, e3, o0, o1, o2, o3;
            ldsm4(e0, e1, e2, e3, abase + (2 * p    ) * 32u);
            ldsm4(o0, o1, o2, o3, abase + (2 * p + 1) * 32u);
#pragma unroll
            for (int j = 0; j < 4; j++) {
                uint4 b1 = (p < 2) ? rb1[j][p] : swf1w[(j * 2 + p - 2) * 32 + lane];
                mma16h(pacc[j], e0, e1, e2, e3, b1.x, b1.y);
                mma16h(pacc[j], o0, o1, o2, o3, b1.z, b1.w);
            }
        }
        size_t tb = (size_t)(T_STEPS - 1) * G4;
#pragma unroll
        for (int j = 0; j < 4; j++) {
            *(__half2*)(xw0 + tb + colbase + j * 8) =
                __floats2half2_rn(pacc[j][0] + bs0[j], pacc[j][1] + bs1[j]);
            *(__half2*)(xw1 + tb + colbase + j * 8) =
                __floats2half2_rn(pacc[j][2] + bs0[j], pacc[j][3] + bs1[j]);
        }
    }
}

// ---------------- launcher ----------------
extern "C" void kernel_launch(void* const* d_in, const int* in_sizes, int n_in,
                              void* d_out, int out_size)
{
    const float* x       = (const float*)d_in[0];
    const float* fc_w    = (const float*)d_in[1];
    const float* fc_b    = (const float*)d_in[2];
    const float* bn_g    = (const float*)d_in[3];
    const float* bn_b    = (const float*)d_in[4];
    const float* bn_mean = (const float*)d_in[5];
    const float* bn_var  = (const float*)d_in[6];
    const float* wih0    = (const float*)d_in[7];
    const float* whh0    = (const float*)d_in[8];
    const float* bih0    = (const float*)d_in[9];
    const float* bhh0    = (const float*)d_in[10];
    const float* wih1    = (const float*)d_in[11];
    const float* whh1    = (const float*)d_in[12];
    const float* bih1    = (const float*)d_in[13];
    const float* bhh1    = (const float*)d_in[14];
    float* out = (float*)d_out;

    const int B = in_sizes[0] / (F_IN * T_STEPS);
    const int M = B * T_STEPS;

    __half *p_xproj, *p_wfh0, *p_wfh1, *p_wifh0, *p_wifh1;
    float *p_biasp0, *p_biasp1;
    cudaGetSymbolAddress((void**)&p_xproj,  g_xproj);
    cudaGetSymbolAddress((void**)&p_biasp0, g_biasp0);
    cudaGetSymbolAddress((void**)&p_biasp1, g_biasp1);
    cudaGetSymbolAddress((void**)&p_wfh0,   g_wfh0);
    cudaGetSymbolAddress((void**)&p_wfh1,   g_wfh1);
    cudaGetSymbolAddress((void**)&p_wifh0,  g_wifh0);
    cudaGetSymbolAddress((void**)&p_wifh1,  g_wifh1);

    const size_t smem_proj = (size_t)2 * HBUF_B + 16 * 512 * 16 + 16 * 256 * 16;  // ~200.5KB
    const size_t smem_base = (size_t)2 * HBUF_B + 16 * 512 * 16;                  // ~136.5KB
    const size_t fuse_smem = (size_t)(4 * 128 * SA + 128 * S2) * 2;               // ~75KB
    cudaFuncSetAttribute(lstm_tc<true>,  cudaFuncAttributeMaxDynamicSharedMemorySize, (int)smem_proj);
    cudaFuncSetAttribute(lstm_tc<false>, cudaFuncAttributeMaxDynamicSharedMemorySize, (int)smem_base);
    cudaFuncSetAttribute(fc_proj_fused,  cudaFuncAttributeMaxDynamicSharedMemorySize, (int)fuse_smem);

    prep_kernel<<<256, 256>>>(wih0, bih0, bhh0, whh0, p_biasp0, p_wfh0, p_wifh0);
    prep_kernel<<<256, 256>>>(wih1, bih1, bhh1, whh1, p_biasp1, p_wfh1, p_wifh1);

    // fused FC+BN+LeakyReLU -> layer-0 projection (fp16 mma throughout)
    fc_proj_fused<<<M / 128, 256, fuse_smem>>>(x, fc_w, p_wifh0, p_xproj,
                                               fc_b, bn_g, bn_b, bn_mean, bn_var, p_biasp0);
    // layer-0 LSTM with fused layer-1 projection (in-place xproj rewrite)
    lstm_tc<true><<<B / 16, 512, smem_proj>>>(p_xproj, p_wfh0, p_wifh1, p_xproj,
                                              p_biasp1, nullptr);
    // layer-1 LSTM -> final hidden state (fp32 out)
    lstm_tc<false><<<B / 16, 512, smem_base>>>(p_xproj, p_wfh1, nullptr, nullptr,
                                               nullptr, out);
}

// round 14
// speedup vs baseline: 6.0362x; 1.0435x over previous
#include <cuda_runtime.h>
#include <cuda_fp16.h>
#include <math.h>

#define T_STEPS 120
#define F_IN    180
#define H       128
#define G4      512
#define MAX_B   2048

// ---------------- static scratch ----------------
__device__ __half g_xproj[(size_t)MAX_B * T_STEPS * G4];   // fp16 projections (in-place reuse)
__device__ float  g_biasp0[G4],  g_biasp1[G4];
__device__ __align__(16) __half g_wfh0[G4 * H], g_wfh1[G4 * H];   // Whh fp16 m16n8k16 B-frags
__device__ __align__(16) __half g_wifh0[G4 * H], g_wifh1[G4 * H]; // wih fp16 m16n8k16 B-frags

// ---------------- helpers ----------------
__device__ __forceinline__ void mma16h(float* c, unsigned a0, unsigned a1, unsigned a2, unsigned a3,
                                       unsigned b0, unsigned b1) {
    asm volatile("mma.sync.aligned.m16n8k16.row.col.f32.f16.f16.f32 "
                 "{%0,%1,%2,%3}, {%4,%5,%6,%7}, {%8,%9}, {%0,%1,%2,%3};"
                 : "+f"(c[0]), "+f"(c[1]), "+f"(c[2]), "+f"(c[3])
                 : "r"(a0), "r"(a1), "r"(a2), "r"(a3), "r"(b0), "r"(b1));
}
__device__ __forceinline__ void ldsm4(unsigned& a0, unsigned& a1, unsigned& a2, unsigned& a3,
                                      unsigned addr) {
    asm volatile("ldmatrix.sync.aligned.m8n8.x4.shared.b16 {%0,%1,%2,%3}, [%4];"
                 : "=r"(a0), "=r"(a1), "=r"(a2), "=r"(a3) : "r"(addr));
}
__device__ __forceinline__ float tanh_ap(float x) {
    float y; asm("tanh.approx.f32 %0, %1;" : "=f"(y) : "f"(x)); return y;
}
__device__ __forceinline__ float sig_ap(float x) {
    return fmaf(0.5f, tanh_ap(0.5f * x), 0.5f);
}

// ---------------- prep: combine bias; pack Whh AND wih as fp16 m16n8k16 B-frags ----------------
__global__ void prep_kernel(const float* __restrict__ wih, const float* __restrict__ bih,
                            const float* __restrict__ bhh, const float* __restrict__ whh,
                            float* __restrict__ biasp, __half* __restrict__ wfh,
                            __half* __restrict__ wifh)
{
    int i = blockIdx.x * 256 + threadIdx.x;
    if (i < G4 * H) {
        int n = i >> 7, k = i & 127;
        if (k == 0) {
            int np = ((n & 127) << 2) | (n >> 7);
            biasp[np] = bih[n] + bhh[n];
        }
        int v2 = i & 7, lane = (i >> 3) & 31, p = (i >> 8) & 3, j = (i >> 10) & 3, w = i >> 12;
        int ks = 2 * p + (v2 >> 2);
        int kk = ks * 16 + (lane & 3) * 2 + (v2 & 1) + ((v2 >> 1) & 1) * 8;
        int np = w * 32 + j * 8 + (lane >> 2);
        int orig = ((np & 3) << 7) | (np >> 2);
        wfh [i] = __float2half_rn(whh[orig * H + kk]);
        wifh[i] = __float2half_rn(wih[orig * H + kk]);
    }
}

#define SA  40
#define S2  136

// ---------------- fused FC+BN+LeakyReLU -> layer-0 projection (all fp16 mma) ----------------
__global__ void __launch_bounds__(256)
fc_proj_fused(const float* __restrict__ x, const float* __restrict__ W,
              const __half* __restrict__ Wf, __half* __restrict__ C,
              const float* __restrict__ fcb, const float* __restrict__ bng,
              const float* __restrict__ bnb, const float* __restrict__ bnm,
              const float* __restrict__ bnv, const float* __restrict__ biasp)
{
    extern __shared__ __align__(16) char fsm[];
    __half* Ah = (__half*)fsm;              // [2][128*SA]
    __half* Bh = Ah + 2 * 128 * SA;         // [2][128*SA]
    __half* hp = Bh + 2 * 128 * SA;         // [128][S2]
    __shared__ int rowbase[128];

    const int tid  = threadIdx.x;
    const int lane = tid & 31, warp = tid >> 5;
    const int g = lane >> 2, t = lane & 3;
    const int wm = warp & 3, wn = warp >> 2;
    const int m0 = blockIdx.x * 128;

    if (tid < 128) {
        int m = m0 + tid; int b = m / T_STEPS;
        rowbase[tid] = b * (F_IN * T_STEPS) + (m - b * T_STEPS);
    }
    __syncthreads();

    const int r  = tid >> 1;
    const int hf = tid & 1;
    const int nc = 6;

    __half2 av2[8], wv2[8];
    auto LOAD = [&](int kc) {
#pragma unroll
        for (int i = 0; i < 8; i++) {
            int k = kc + hf * 16 + 2 * i;
            float x0 = (k     < F_IN) ? __ldg(x + rowbase[r] + k * T_STEPS)       : 0.f;
            float x1 = (k + 1 < F_IN) ? __ldg(x + rowbase[r] + (k + 1) * T_STEPS) : 0.f;
            av2[i] = __floats2half2_rn(x0, x1);
            float w0 = (k     < F_IN) ? __ldg(W + r * F_IN + k)     : 0.f;
            float w1 = (k + 1 < F_IN) ? __ldg(W + r * F_IN + k + 1) : 0.f;
            wv2[i] = __floats2half2_rn(w0, w1);
        }
    };
    auto STORE = [&](int s) {
#pragma unroll
        for (int i = 0; i < 8; i++) {
            *(__half2*)&Ah[s * 128 * SA + r * SA + hf * 16 + 2 * i] = av2[i];
            *(__half2*)&Bh[s * 128 * SA + r * SA + hf * 16 + 2 * i] = wv2[i];
        }
    };

    float acc[2][8][4];
#pragma unroll
    for (int mi = 0; mi < 2; mi++)
#pragma unroll
        for (int j = 0; j < 8; j++)
#pragma unroll
            for (int q = 0; q < 4; q++) acc[mi][j][q] = 0.f;

    const unsigned ah_smem = (unsigned)__cvta_generic_to_shared(Ah);
    const unsigned lm_a    = ah_smem + (unsigned)((lane & 15) * SA * 2 + (lane >> 4) * 16);

    LOAD(0); STORE(0); __syncthreads();

    for (int c = 0; c < nc; c++) {
        if (c + 1 < nc) LOAD((c + 1) * 32);
        const unsigned abuf = lm_a + (unsigned)((c & 1) * 128 * SA * 2);
        const __half* bs = Bh + (c & 1) * 128 * SA;
#pragma unroll
        for (int kq = 0; kq < 2; kq++) {
            unsigned a[2][4];
#pragma unroll
            for (int mi = 0; mi < 2; mi++)
                ldsm4(a[mi][0], a[mi][1], a[mi][2], a[mi][3],
                      abuf + (unsigned)((wm * 32 + mi * 16) * SA * 2 + kq * 32));
#pragma unroll
            for (int j = 0; j < 8; j++) {
                int row = wn * 64 + j * 8 + g;
                unsigned b0 = *(const unsigned*)&bs[row * SA + kq * 16 + 2 * t];
                unsigned b1 = *(const unsigned*)&bs[row * SA + kq * 16 + 2 * t + 8];
#pragma unroll
                for (int mi = 0; mi < 2; mi++)
                    mma16h(acc[mi][j], a[mi][0], a[mi][1], a[mi][2], a[mi][3], b0, b1);
            }
        }
        if (c + 1 < nc) STORE((c + 1) & 1);
        __syncthreads();
    }

#pragma unroll
    for (int j = 0; j < 8; j++) {
        int col = wn * 64 + j * 8 + 2 * t;
        float s0 = bng[col]     * rsqrtf(bnv[col]     + 1e-5f);
        float s1 = bng[col + 1] * rsqrtf(bnv[col + 1] + 1e-5f);
        float be0 = (fcb[col]     - bnm[col]    ) * s0 + bnb[col];
        float be1 = (fcb[col + 1] - bnm[col + 1]) * s1 + bnb[col + 1];
#pragma unroll
        for (int mi = 0; mi < 2; mi++) {
            int row = wm * 32 + mi * 16 + g;
            float v0 = acc[mi][j][0] * s0 + be0;
            float v1 = acc[mi][j][1] * s1 + be1;
            float v2 = acc[mi][j][2] * s0 + be0;
            float v3 = acc[mi][j][3] * s1 + be1;
            v0 = (v0 >= 0.f) ? v0 : 0.01f * v0;
            v1 = (v1 >= 0.f) ? v1 : 0.01f * v1;
            v2 = (v2 >= 0.f) ? v2 : 0.01f * v2;
            v3 = (v3 >= 0.f) ? v3 : 0.01f * v3;
            *(__half2*)&hp[(row    ) * S2 + col] = __floats2half2_rn(v0, v1);
            *(__half2*)&hp[(row + 8) * S2 + col] = __floats2half2_rn(v2, v3);
        }
    }
    __syncthreads();

    const uint4* wf4 = (const uint4*)Wf;
    const unsigned hp_smem = (unsigned)__cvta_generic_to_shared(hp);
    const unsigned lm_h    = hp_smem + (unsigned)((lane & 15) * S2 * 2 + (lane >> 4) * 16);
#pragma unroll 1
    for (int nch = 0; nch < 4; nch++) {
        float a2[2][8][4];
#pragma unroll
        for (int mi = 0; mi < 2; mi++)
#pragma unroll
            for (int j = 0; j < 8; j++)
#pragma unroll
                for (int q = 0; q < 4; q++) a2[mi][j][q] = 0.f;

#pragma unroll
        for (int p = 0; p < 4; p++) {
            unsigned e[2][4], o[2][4];
#pragma unroll
            for (int mi = 0; mi < 2; mi++) {
                unsigned rbase = lm_h + (unsigned)((wm * 32 + mi * 16) * S2 * 2);
                ldsm4(e[mi][0], e[mi][1], e[mi][2], e[mi][3], rbase + (2 * p    ) * 32u);
                ldsm4(o[mi][0], o[mi][1], o[mi][2], o[mi][3], rbase + (2 * p + 1) * 32u);
            }
#pragma unroll
            for (int j = 0; j < 8; j++) {
                int nt = nch * 16 + wn * 8 + j;
                uint4 b = __ldg(wf4 + ((size_t)nt * 4 + p) * 32 + lane);
#pragma unroll
                for (int mi = 0; mi < 2; mi++) {
                    mma16h(a2[mi][j], e[mi][0], e[mi][1], e[mi][2], e[mi][3], b.x, b.y);
                    mma16h(a2[mi][j], o[mi][0], o[mi][1], o[mi][2], o[mi][3], b.z, b.w);
                }
            }
        }
#pragma unroll
        for (int j = 0; j < 8; j++) {
            int col = nch * 128 + wn * 64 + j * 8 + 2 * t;
            float be0 = __ldg(biasp + col);
            float be1 = __ldg(biasp + col + 1);
#pragma unroll
            for (int mi = 0; mi < 2; mi++) {
                int row = m0 + wm * 32 + mi * 16 + g;
                *(__half2*)(C + (size_t)row * G4 + col) =
                    __floats2half2_rn(a2[mi][j][0] + be0, a2[mi][j][1] + be1);
                *(__half2*)(C + (size_t)(row + 8) * G4 + col) =
                    __floats2half2_rn(a2[mi][j][2] + be0, a2[mi][j][3] + be1);
            }
        }
    }
}

// ---------------- persistent fp16 LSTM; PROJ fuses the next layer's input projection --------
// wih1 p0,p1 frags stream via __ldg (L1-resident), p2,p3 from smem; bias via __ldg at store.
#define SHh    136
#define HBUF_B (16 * SHh * 2)

template<bool PROJ>
__global__ void __launch_bounds__(512)
lstm_tc(const __half* __restrict__ xproj, const __half* __restrict__ wfh,
        const __half* __restrict__ wpf, __half* __restrict__ xpout,
        const float* __restrict__ biasp, float* __restrict__ hlast)
{
    extern __shared__ unsigned smx[];
    __half* h_buf = (__half*)smx;                          // [2][16*SHh]
    uint4*  swf   = (uint4*)((char*)smx + 2 * HBUF_B);     // whh: 16 warps x 512 uint4
    uint4*  swf1  = swf + 16 * 512;                        // wih1 p=2,3: 16 warps x 256 uint4

    const int tid  = threadIdx.x, lane = tid & 31, w = tid >> 5;
    const int g = lane >> 2, t = lane & 3;
    const int odd = t & 1;
    const int b0 = blockIdx.x * 16;
    uint4* swfw  = swf  + (size_t)w * 512;
    uint4* swf1w = swf1 + (size_t)w * 256;
    const int colbase = w * 32 + 2 * t;
    const uint4* src1 = PROJ ? ((const uint4*)wpf + (size_t)w * 512 + lane) : nullptr;

    {
        const uint4* src = (const uint4*)wfh + (size_t)w * 512;
        for (int idx = lane; idx < 512; idx += 32)
            swfw[idx] = __ldg(src + idx);
    }
    if (PROJ) {
#pragma unroll
        for (int j = 0; j < 4; j++)
#pragma unroll
            for (int p = 2; p < 4; p++)
                swf1w[(j * 2 + p - 2) * 32 + lane] = __ldg(src1 + (j * 4 + p) * 32);
    }

    for (int i = tid; i < (2 * HBUF_B) / 4; i += 512) smx[i] = 0u;
    __syncthreads();

    float c_reg[4] = {0.f, 0.f, 0.f, 0.f};
    const int row_pw = g + odd * 8;
    const int hh0    = w * 8 + (t >> 1);
    const __half* xr0 = xproj + (size_t)(b0 + g    ) * T_STEPS * G4;
    const __half* xr1 = xproj + (size_t)(b0 + g + 8) * T_STEPS * G4;
    __half* xw0 = PROJ ? (xpout + (size_t)(b0 + g    ) * T_STEPS * G4) : nullptr;
    __half* xw1 = PROJ ? (xpout + (size_t)(b0 + g + 8) * T_STEPS * G4) : nullptr;

    const unsigned hb_smem = (unsigned)__cvta_generic_to_shared(h_buf);
    const unsigned lmoff = hb_smem + (unsigned)((lane & 15) * SHh * 2 + (lane >> 4) * 16);

    __half2 p0[4], p1[4];
#pragma unroll
    for (int j = 0; j < 4; j++) {
        p0[j] = *(const __half2*)(xr0 + colbase + j * 8);
        p1[j] = *(const __half2*)(xr1 + colbase + j * 8);
    }

    int cur = 0;
    for (int ts = 0; ts < T_STEPS; ts++) {
        __half*        hnb   = h_buf + (cur ^ 1) * (16 * SHh);
        const unsigned abase = lmoff + (unsigned)(cur * HBUF_B);
        float acc[4][4];
#pragma unroll
        for (int j = 0; j < 4; j++) {
            float2 f0 = __half22float2(p0[j]);
            float2 f1 = __half22float2(p1[j]);
            acc[j][0] = f0.x; acc[j][1] = f0.y;
            acc[j][2] = f1.x; acc[j][3] = f1.y;
        }
        {
            int tn = (ts + 1 < T_STEPS) ? ts + 1 : ts;
#pragma unroll
            for (int j = 0; j < 4; j++) {
                p0[j] = __ldg((const __half2*)(xr0 + (size_t)tn * G4 + colbase + j * 8));
                p1[j] = __ldg((const __half2*)(xr1 + (size_t)tn * G4 + colbase + j * 8));
            }
        }

        float pacc[4][4];
        if (PROJ) {
#pragma unroll
            for (int j = 0; j < 4; j++)
#pragma unroll
                for (int q = 0; q < 4; q++) pacc[j][q] = 0.f;
        }

#pragma unroll
        for (int p = 0; p < 4; p++) {
            unsigned e0, e1, e2, e3, o0, o1, o2, o3;
            ldsm4(e0, e1, e2, e3, abase + (2 * p    ) * 32u);
            ldsm4(o0, o1, o2, o3, abase + (2 * p + 1) * 32u);
#pragma unroll
            for (int j = 0; j < 4; j++) {
                uint4 b = swfw[(j * 4 + p) * 32 + lane];
                mma16h(acc[j], e0, e1, e2, e3, b.x, b.y);
                mma16h(acc[j], o0, o1, o2, o3, b.z, b.w);
            }
            if (PROJ) {
#pragma unroll
                for (int j = 0; j < 4; j++) {
                    uint4 b1 = (p < 2) ? __ldg(src1 + (j * 4 + p) * 32)
                                       : swf1w[(j * 2 + p - 2) * 32 + lane];
                    mma16h(pacc[j], e0, e1, e2, e3, b1.x, b1.y);
                    mma16h(pacc[j], o0, o1, o2, o3, b1.z, b1.w);
                }
            }
        }

        // emit xproj1[ts-1] (A-frags were h0[ts-1]); identical math to the old gemm_tc1
        if (PROJ && ts > 0) {
            size_t tb = (size_t)(ts - 1) * G4;
#pragma unroll
            for (int j = 0; j < 4; j++) {
                float be0 = __ldg(biasp + colbase + j * 8);
                float be1 = __ldg(biasp + colbase + j * 8 + 1);
                *(__half2*)(xw0 + tb + colbase + j * 8) =
                    __floats2half2_rn(pacc[j][0] + be0, pacc[j][1] + be1);
                *(__half2*)(xw1 + tb + colbase + j * 8) =
                    __floats2half2_rn(pacc[j][2] + be0, pacc[j][3] + be1);
            }
        }

        // activations (hw tanh) + pair-exchange + state update
#pragma unroll
        for (int j = 0; j < 4; j++) {
            float a0 = odd ? tanh_ap(acc[j][0]) : sig_ap(acc[j][0]);
            float a1 = sig_ap(acc[j][1]);
            float a2 = odd ? tanh_ap(acc[j][2]) : sig_ap(acc[j][2]);
            float a3 = sig_ap(acc[j][3]);
            float sv0 = odd ? a0 : a2;
            float sv1 = odd ? a1 : a3;
            float rv0 = __shfl_xor_sync(0xffffffffu, sv0, 1);
            float rv1 = __shfl_xor_sync(0xffffffffu, sv1, 1);
            float iG = odd ? rv0 : a0;
            float fG = odd ? rv1 : a1;
            float gG = odd ? a2  : rv0;
            float oG = odd ? a3  : rv1;
            float cn = fG * c_reg[j] + iG * gG;
            float hn = oG * tanh_ap(cn);
            c_reg[j] = cn;
            int hh = hh0 + 2 * j;
            hnb[row_pw * SHh + hh] = __float2half_rn(hn);
            if (hlast && ts == T_STEPS - 1) hlast[(size_t)(b0 + row_pw) * H + hh] = hn;
        }
        __syncthreads();
        cur ^= 1;
    }

    // tail: xproj1[T-1] from h0[T-1] (now in h_buf[cur])
    if (PROJ) {
        const unsigned abase = lmoff + (unsigned)(cur * HBUF_B);
        float pacc[4][4];
#pragma unroll
        for (int j = 0; j < 4; j++)
#pragma unroll
            for (int q = 0; q < 4; q++) pacc[j][q] = 0.f;
#pragma unroll
        for (int p = 0; p < 4; p++) {
            unsigned e0, e1, e2, e3, o0, o1, o2, o3;
            ldsm4(e0, e1, e2, e3, abase + (2 * p    ) * 32u);
            ldsm4(o0, o1, o2, o3, abase + (2 * p + 1) * 32u);
#pragma unroll
            for (int j = 0; j < 4; j++) {
                uint4 b1 = (p < 2) ? __ldg(src1 + (j * 4 + p) * 32)
                                   : swf1w[(j * 2 + p - 2) * 32 + lane];
                mma16h(pacc[j], e0, e1, e2, e3, b1.x, b1.y);
                mma16h(pacc[j], o0, o1, o2, o3, b1.z, b1.w);
            }
        }
        size_t tb = (size_t)(T_STEPS - 1) * G4;
#pragma unroll
        for (int j = 0; j < 4; j++) {
            float be0 = __ldg(biasp + colbase + j * 8);
            float be1 = __ldg(biasp + colbase + j * 8 + 1);
            *(__half2*)(xw0 + tb + colbase + j * 8) =
                __floats2half2_rn(pacc[j][0] + be0, pacc[j][1] + be1);
            *(__half2*)(xw1 + tb + colbase + j * 8) =
                __floats2half2_rn(pacc[j][2] + be0, pacc[j][3] + be1);
        }
    }
}

// ---------------- launcher ----------------
extern "C" void kernel_launch(void* const* d_in, const int* in_sizes, int n_in,
                              void* d_out, int out_size)
{
    const float* x       = (const float*)d_in[0];
    const float* fc_w    = (const float*)d_in[1];
    const float* fc_b    = (const float*)d_in[2];
    const float* bn_g    = (const float*)d_in[3];
    const float* bn_b    = (const float*)d_in[4];
    const float* bn_mean = (const float*)d_in[5];
    const float* bn_var  = (const float*)d_in[6];
    const float* wih0    = (const float*)d_in[7];
    const float* whh0    = (const float*)d_in[8];
    const float* bih0    = (const float*)d_in[9];
    const float* bhh0    = (const float*)d_in[10];
    const float* wih1    = (const float*)d_in[11];
    const float* whh1    = (const float*)d_in[12];
    const float* bih1    = (const float*)d_in[13];
    const float* bhh1    = (const float*)d_in[14];
    float* out = (float*)d_out;

    const int B = in_sizes[0] / (F_IN * T_STEPS);
    const int M = B * T_STEPS;

    __half *p_xproj, *p_wfh0, *p_wfh1, *p_wifh0, *p_wifh1;
    float *p_biasp0, *p_biasp1;
    cudaGetSymbolAddress((void**)&p_xproj,  g_xproj);
    cudaGetSymbolAddress((void**)&p_biasp0, g_biasp0);
    cudaGetSymbolAddress((void**)&p_biasp1, g_biasp1);
    cudaGetSymbolAddress((void**)&p_wfh0,   g_wfh0);
    cudaGetSymbolAddress((void**)&p_wfh1,   g_wfh1);
    cudaGetSymbolAddress((void**)&p_wifh0,  g_wifh0);
    cudaGetSymbolAddress((void**)&p_wifh1,  g_wifh1);

    const size_t smem_proj = (size_t)2 * HBUF_B + 16 * 512 * 16 + 16 * 256 * 16;  // ~200.5KB
    const size_t smem_base = (size_t)2 * HBUF_B + 16 * 512 * 16;                  // ~136.5KB
    const size_t fuse_smem = (size_t)(4 * 128 * SA + 128 * S2) * 2;               // ~75KB
    cudaFuncSetAttribute(lstm_tc<true>,  cudaFuncAttributeMaxDynamicSharedMemorySize, (int)smem_proj);
    cudaFuncSetAttribute(lstm_tc<false>, cudaFuncAttributeMaxDynamicSharedMemorySize, (int)smem_base);
    cudaFuncSetAttribute(fc_proj_fused,  cudaFuncAttributeMaxDynamicSharedMemorySize, (int)fuse_smem);

    prep_kernel<<<256, 256>>>(wih0, bih0, bhh0, whh0, p_biasp0, p_wfh0, p_wifh0);
    prep_kernel<<<256, 256>>>(wih1, bih1, bhh1, whh1, p_biasp1, p_wfh1, p_wifh1);

    // fused FC+BN+LeakyReLU -> layer-0 projection (fp16 mma throughout)
    fc_proj_fused<<<M / 128, 256, fuse_smem>>>(x, fc_w, p_wifh0, p_xproj,
                                               fc_b, bn_g, bn_b, bn_mean, bn_var, p_biasp0);
    // layer-0 LSTM with fused layer-1 projection (in-place xproj rewrite)
    lstm_tc<true><<<B / 16, 512, smem_proj>>>(p_xproj, p_wfh0, p_wifh1, p_xproj,
                                              p_biasp1, nullptr);
    // layer-1 LSTM -> final hidden state (fp32 out)
    lstm_tc<false><<<B / 16, 512, smem_base>>>(p_xproj, p_wfh1, nullptr, nullptr,
                                               nullptr, out);
}